// round 1
// baseline (speedup 1.0000x reference)
#include <cuda_runtime.h>
#include <math.h>

#define Bsz 8
#define Lsz 512
#define IDIM 1024
#define Dm 512
#define Hh 8
#define DH 64
#define NBINS 25
#define PWc 10
#define HALFc 256
#define ISZ 513

// ------------------------- scratch (static device mem) -------------------------
__device__ float g_x1[Bsz*Lsz*Dm];
__device__ float g_x2[Bsz*Lsz*Dm];
__device__ float g_t1[Bsz*Lsz*Dm];
__device__ float g_t2[Bsz*Lsz*Dm];
__device__ float g_q [Bsz*Lsz*Dm];
__device__ float g_k [Bsz*Lsz*Dm];
__device__ float g_v [Bsz*Lsz*Dm];
__device__ float g_o [Bsz*Lsz*Dm];
__device__ float g_att[Bsz*Hh*Lsz*Lsz];
__device__ float g_h1[(size_t)Bsz*NBINS*Lsz*HALFc];
__device__ float g_h2[(size_t)Bsz*NBINS*Lsz*HALFc];
__device__ float g_cmraw[(size_t)Bsz*NBINS*Lsz*Lsz];
__device__ float g_cm1[Bsz*Lsz*Lsz];
__device__ float g_cs [Bsz*Lsz*Lsz];
__device__ float g_I  [Bsz*ISZ*ISZ];

// ------------------------- generic tiled GEMM -------------------------
// C = act( alpha * A x op(B) + bias + Cres )
// TB=true : B is (N,K) row-major, ldb = row stride (C = A * B^T)
// TB=false: B is (K,N) row-major, ldb = row stride (C = A * B)
// two-level batching: z = z1*batch2 + z2 ; offsets use (sX1, sX2).
// Cres uses the same ldc/sC strides as C.
template<bool TB>
__global__ void gemm_k(const float* __restrict__ A, const float* __restrict__ B,
                       float* __restrict__ C,
                       int M, int N, int K, int lda, int ldb, int ldc,
                       long long sA1, long long sA2, long long sB1, long long sB2,
                       long long sC1, long long sC2, int batch2,
                       const float* __restrict__ bias,
                       float alpha, int act, const float* __restrict__ Cres)
{
    int z  = blockIdx.z;
    int z1 = z / batch2, z2 = z % batch2;
    A += z1*sA1 + z2*sA2;
    B += z1*sB1 + z2*sB2;
    C += z1*sC1 + z2*sC2;
    if (Cres) Cres += z1*sC1 + z2*sC2;

    __shared__ float As[16][68];
    __shared__ float Bs[16][68];

    const int m0 = blockIdx.y * 64;
    const int n0 = blockIdx.x * 64;
    const int tid = threadIdx.x;          // 0..255
    const int tr = tid >> 4;              // 0..15
    const int tc = tid & 15;              // 0..15

    float acc[4][4] = {};

    for (int k0 = 0; k0 < K; k0 += 16) {
        // A tile: As[k][m]
        #pragma unroll
        for (int i = 0; i < 4; i++) {
            int idx = tid + i*256;
            int m = idx >> 4, kk = idx & 15;
            As[kk][m] = A[(long long)(m0+m)*lda + (k0+kk)];
        }
        if (TB) {
            #pragma unroll
            for (int i = 0; i < 4; i++) {
                int idx = tid + i*256;
                int n = idx >> 4, kk = idx & 15;
                Bs[kk][n] = B[(long long)(n0+n)*ldb + (k0+kk)];
            }
        } else {
            #pragma unroll
            for (int i = 0; i < 4; i++) {
                int idx = tid + i*256;
                int kk = idx >> 6, n = idx & 63;
                Bs[kk][n] = B[(long long)(k0+kk)*ldb + (n0+n)];
            }
        }
        __syncthreads();
        #pragma unroll
        for (int kk = 0; kk < 16; kk++) {
            float4 av = *reinterpret_cast<const float4*>(&As[kk][tr*4]);
            float4 bv = *reinterpret_cast<const float4*>(&Bs[kk][tc*4]);
            float a[4] = {av.x, av.y, av.z, av.w};
            float b[4] = {bv.x, bv.y, bv.z, bv.w};
            #pragma unroll
            for (int i = 0; i < 4; i++)
                #pragma unroll
                for (int j = 0; j < 4; j++)
                    acc[i][j] += a[i]*b[j];
        }
        __syncthreads();
    }

    #pragma unroll
    for (int i = 0; i < 4; i++) {
        int m = m0 + tr*4 + i;
        #pragma unroll
        for (int j = 0; j < 4; j++) {
            int n = n0 + tc*4 + j;
            float v = acc[i][j]*alpha;
            if (bias) v += bias[n];
            if (Cres) v += Cres[(long long)m*ldc + n];
            if (act)  v = tanhf(v);
            C[(long long)m*ldc + n] = v;
        }
    }
}

// ------------------------- softmax over rows of 512 -------------------------
__global__ void softmax_k(float* __restrict__ att)
{
    long long row = blockIdx.x;
    float* p = att + row * Lsz;
    int t = threadIdx.x;                     // 256 threads, 2 elems each
    float v0 = p[t], v1 = p[t + 256];

    __shared__ float red[8];
    unsigned lane = t & 31, w = t >> 5;

    float m = fmaxf(v0, v1);
    #pragma unroll
    for (int o = 16; o > 0; o >>= 1) m = fmaxf(m, __shfl_xor_sync(0xffffffffu, m, o));
    if (lane == 0) red[w] = m;
    __syncthreads();
    if (t == 0) {
        float mm = red[0];
        #pragma unroll
        for (int i = 1; i < 8; i++) mm = fmaxf(mm, red[i]);
        red[0] = mm;
    }
    __syncthreads();
    m = red[0];
    __syncthreads();

    float e0 = expf(v0 - m), e1 = expf(v1 - m);
    float s = e0 + e1;
    #pragma unroll
    for (int o = 16; o > 0; o >>= 1) s += __shfl_xor_sync(0xffffffffu, s, o);
    if (lane == 0) red[w] = s;
    __syncthreads();
    if (t == 0) {
        float ss = 0.f;
        #pragma unroll
        for (int i = 0; i < 8; i++) ss += red[i];
        red[0] = ss;
    }
    __syncthreads();
    float inv = 1.0f / red[0];
    p[t] = e0 * inv;
    p[t + 256] = e1 * inv;
}

// ------------------------- elementwise tanh -------------------------
__global__ void tanh_k(const float* __restrict__ in, float* __restrict__ out, int n)
{
    int i = blockIdx.x * blockDim.x + threadIdx.x;
    if (i < n) out[i] = tanhf(in[i]);
}

// ------------------------- bin smoothing + aggregate -------------------------
__global__ void smooth_k(const float* __restrict__ raw, const float* __restrict__ sm,
                         const float* __restrict__ agg, float* __restrict__ cm_out,
                         float* __restrict__ cm1)
{
    long long idx = (long long)blockIdx.x * blockDim.x + threadIdx.x;
    const long long tot = (long long)Bsz * Lsz * Lsz;
    if (idx >= tot) return;
    int b   = (int)(idx / ((long long)Lsz*Lsz));
    int rem = (int)(idx % ((long long)Lsz*Lsz));

    const float* p = raw + (long long)b * NBINS * Lsz * Lsz + rem;
    float rv[NBINS];
    #pragma unroll
    for (int n = 0; n < NBINS; n++) rv[n] = p[(long long)n * Lsz * Lsz];

    float sw[5];
    #pragma unroll
    for (int k = 0; k < 5; k++) sw[k] = sm[k];

    float* q = cm_out + (long long)b * NBINS * Lsz * Lsz + rem;
    float acc = 0.f;
    #pragma unroll
    for (int n = 0; n < NBINS; n++) {
        float v = 0.f;
        #pragma unroll
        for (int k = 0; k < 5; k++) {
            int m = n + k - 2;
            if (m >= 0 && m < NBINS) v += sw[k] * rv[m];
        }
        q[(long long)n * Lsz * Lsz] = v;
        acc += v * agg[n];
    }
    cm1[idx] = tanhf(acc);
}

// ------------------------- integral image -------------------------
__global__ void zero_k(float* __restrict__ p, int n)
{
    int i = blockIdx.x * blockDim.x + threadIdx.x;
    if (i < n) p[i] = 0.f;
}

__global__ void colsum_k(const float* __restrict__ cm1, float* __restrict__ cs)
{
    int t = blockIdx.x * blockDim.x + threadIdx.x;
    if (t >= Bsz * Lsz) return;
    int b = t / Lsz, j = t % Lsz;
    const float* src = cm1 + (long long)b * Lsz * Lsz + j;
    float* dst       = cs  + (long long)b * Lsz * Lsz + j;
    float acc = 0.f;
    for (int i = 0; i < Lsz; i++) {
        acc += src[(long long)i * Lsz];
        dst[(long long)i * Lsz] = acc;
    }
}

__global__ void rowsum_k(const float* __restrict__ cs, float* __restrict__ I)
{
    int t = blockIdx.x * blockDim.x + threadIdx.x;
    if (t >= Bsz * Lsz) return;
    int b = t / Lsz, i = t % Lsz;
    const float* src = cs + (long long)b * Lsz * Lsz + (long long)i * Lsz;
    float* row = I + (long long)b * ISZ * ISZ + (long long)(i + 1) * ISZ;
    float acc = 0.f;
    row[0] = 0.f;
    for (int j = 0; j < Lsz; j++) { acc += src[j]; row[j + 1] = acc; }
    if (i == 0) {
        float* r0 = I + (long long)b * ISZ * ISZ;
        for (int c = 0; c < ISZ; c++) r0[c] = 0.f;
    }
}

// ------------------------- box sums + sigmoid head -------------------------
__global__ void finalize_k(const float* __restrict__ I, const float* __restrict__ Lmat,
                           const float* __restrict__ biasp, float* __restrict__ pp)
{
    int b = blockIdx.x;
    __shared__ float terms[128];
    int t = threadIdx.x;
    float val = 0.f;
    if (t < PWc * PWc) {
        int p = t / PWc, q = t % PWc;
        const float* Ib = I + (long long)b * ISZ * ISZ;
        const int Hp = Lsz - PWc + 1;   // 503
        float w = Ib[(Hp + p) * ISZ + (Hp + q)] - Ib[(Hp + p) * ISZ + q]
                - Ib[p * ISZ + (Hp + q)]       + Ib[p * ISZ + q];
        val = tanhf(w) * Lmat[t];
    }
    terms[t] = val;
    __syncthreads();
    if (t == 0) {
        float s = 0.f;
        for (int i = 0; i < PWc * PWc; i++) s += terms[i];
        pp[b] = 1.0f / (1.0f + expf(-(s + biasp[0])));
    }
}

// ------------------------- host-side launch helpers -------------------------
static void gemm(bool tb, const float* A, const float* B, float* C,
                 int M, int N, int K, int lda, int ldb, int ldc,
                 long long sA1, long long sA2, long long sB1, long long sB2,
                 long long sC1, long long sC2, int batch1, int batch2,
                 const float* bias, float alpha, int act, const float* Cres)
{
    dim3 grid(N / 64, M / 64, batch1 * batch2);
    if (tb) gemm_k<true ><<<grid, 256>>>(A, B, C, M, N, K, lda, ldb, ldc,
                                         sA1, sA2, sB1, sB2, sC1, sC2, batch2,
                                         bias, alpha, act, Cres);
    else    gemm_k<false><<<grid, 256>>>(A, B, C, M, N, K, lda, ldb, ldc,
                                         sA1, sA2, sB1, sB2, sC1, sC2, batch2,
                                         bias, alpha, act, Cres);
}

static void run_mha(const float* xq, const float* xkv,
                    const float* in_w, const float* in_b,
                    const float* out_w, const float* out_b,
                    float* target, float* q, float* k, float* v,
                    float* att, float* o)
{
    const int M = Bsz * Lsz;
    // q / k / v projections
    gemm(true, xq,  in_w,               q, M, Dm, Dm, Dm, Dm, Dm, 0,0,0,0,0,0, 1,1, in_b,        1.f, 0, nullptr);
    gemm(true, xkv, in_w + Dm*Dm,       k, M, Dm, Dm, Dm, Dm, Dm, 0,0,0,0,0,0, 1,1, in_b + Dm,   1.f, 0, nullptr);
    gemm(true, xkv, in_w + 2*Dm*Dm,     v, M, Dm, Dm, Dm, Dm, Dm, 0,0,0,0,0,0, 1,1, in_b + 2*Dm, 1.f, 0, nullptr);
    // scores: (b,h) batched, S = Q K^T / 8
    gemm(true, q, k, att, Lsz, Lsz, DH, Dm, Dm, Lsz,
         (long long)Lsz*Dm, DH, (long long)Lsz*Dm, DH,
         (long long)Hh*Lsz*Lsz, (long long)Lsz*Lsz, Bsz, Hh,
         nullptr, 0.125f, 0, nullptr);
    softmax_k<<<Bsz*Hh*Lsz, 256>>>(att);
    // O = att @ V   (NN form)
    gemm(false, att, v, o, Lsz, DH, Lsz, Lsz, Dm, Dm,
         (long long)Hh*Lsz*Lsz, (long long)Lsz*Lsz,
         (long long)Lsz*Dm, DH, (long long)Lsz*Dm, DH, Bsz, Hh,
         nullptr, 1.f, 0, nullptr);
    // output projection + residual into target
    gemm(true, o, out_w, target, M, Dm, Dm, Dm, Dm, Dm, 0,0,0,0,0,0, 1,1,
         out_b, 1.f, 0, target);
}

extern "C" void kernel_launch(void* const* d_in, const int* in_sizes, int n_in,
                              void* d_out, int out_size)
{
    const float* x1i     = (const float*)d_in[0];
    const float* x2i     = (const float*)d_in[1];
    const float* proj_w  = (const float*)d_in[2];
    const float* proj_b  = (const float*)d_in[3];
    const float* mha_in_w  = (const float*)d_in[4];
    const float* mha_in_b  = (const float*)d_in[5];
    const float* mha_out_w = (const float*)d_in[6];
    const float* mha_out_b = (const float*)d_in[7];
    const float* ca_in_w   = (const float*)d_in[8];
    const float* ca_in_b   = (const float*)d_in[9];
    const float* ca_out_w  = (const float*)d_in[10];
    const float* ca_out_b  = (const float*)d_in[11];
    const float* Wbins   = (const float*)d_in[12];
    const float* agg     = (const float*)d_in[13];
    const float* Lmat    = (const float*)d_in[14];
    const float* biasp   = (const float*)d_in[15];
    const float* smooth  = (const float*)d_in[16];

    float *x1b, *x2b, *t1b, *t2b, *qb, *kb, *vb, *ob, *attb, *h1b, *h2b, *cmraw, *cm1b, *csb, *Ib;
    cudaGetSymbolAddress((void**)&x1b, g_x1);
    cudaGetSymbolAddress((void**)&x2b, g_x2);
    cudaGetSymbolAddress((void**)&t1b, g_t1);
    cudaGetSymbolAddress((void**)&t2b, g_t2);
    cudaGetSymbolAddress((void**)&qb,  g_q);
    cudaGetSymbolAddress((void**)&kb,  g_k);
    cudaGetSymbolAddress((void**)&vb,  g_v);
    cudaGetSymbolAddress((void**)&ob,  g_o);
    cudaGetSymbolAddress((void**)&attb, g_att);
    cudaGetSymbolAddress((void**)&h1b, g_h1);
    cudaGetSymbolAddress((void**)&h2b, g_h2);
    cudaGetSymbolAddress((void**)&cmraw, g_cmraw);
    cudaGetSymbolAddress((void**)&cm1b, g_cm1);
    cudaGetSymbolAddress((void**)&csb,  g_cs);
    cudaGetSymbolAddress((void**)&Ib,   g_I);

    float* out = (float*)d_out;
    float* pp_out = out + (out_size - Bsz);   // cm first, pp_prob last 8

    const int M = Bsz * Lsz;  // 4096
    const int NXD = M * Dm;   // elementwise sizes

    // 1. input projections
    gemm(true, x1i, proj_w, x1b, M, Dm, IDIM, IDIM, IDIM, Dm, 0,0,0,0,0,0, 1,1, proj_b, 1.f, 0, nullptr);
    gemm(true, x2i, proj_w, x2b, M, Dm, IDIM, IDIM, IDIM, Dm, 0,0,0,0,0,0, 1,1, proj_b, 1.f, 0, nullptr);

    // 2. self-attention (+residual)
    run_mha(x1b, x1b, mha_in_w, mha_in_b, mha_out_w, mha_out_b, x1b, qb, kb, vb, attb, ob);
    run_mha(x2b, x2b, mha_in_w, mha_in_b, mha_out_w, mha_out_b, x2b, qb, kb, vb, attb, ob);

    // 3. tanh copies for cross-attn inputs
    tanh_k<<<(NXD + 255) / 256, 256>>>(x1b, t1b, NXD);
    tanh_k<<<(NXD + 255) / 256, 256>>>(x2b, t2b, NXD);

    // 4. cross-attention (+residual into x)
    run_mha(t1b, t2b, ca_in_w, ca_in_b, ca_out_w, ca_out_b, x1b, qb, kb, vb, attb, ob);
    run_mha(t2b, t1b, ca_in_w, ca_in_b, ca_out_w, ca_out_b, x2b, qb, kb, vb, attb, ob);

    // 5. tanh in place
    tanh_k<<<(NXD + 255) / 256, 256>>>(x1b, x1b, NXD);
    tanh_k<<<(NXD + 255) / 256, 256>>>(x2b, x2b, NXD);

    // 6. h1/h2 = tanh(einsum('bld,ndk->bnlk'))  — batched over (b, n)
    gemm(false, x1b, Wbins, h1b, Lsz, HALFc, Dm, Dm, HALFc, HALFc,
         (long long)Lsz*Dm, 0, 0, (long long)Dm*HALFc,
         (long long)NBINS*Lsz*HALFc, (long long)Lsz*HALFc, Bsz, NBINS,
         nullptr, 1.f, 1, nullptr);
    gemm(false, x2b, Wbins, h2b, Lsz, HALFc, Dm, Dm, HALFc, HALFc,
         (long long)Lsz*Dm, 0, 0, (long long)Dm*HALFc,
         (long long)NBINS*Lsz*HALFc, (long long)Lsz*HALFc, Bsz, NBINS,
         nullptr, 1.f, 1, nullptr);

    // 7. cm_raw = h1 h2^T — batched over b*n = 200
    gemm(true, h1b, h2b, cmraw, Lsz, Lsz, HALFc, HALFc, HALFc, Lsz,
         (long long)Lsz*HALFc, 0, (long long)Lsz*HALFc, 0,
         (long long)Lsz*Lsz, 0, Bsz*NBINS, 1,
         nullptr, 1.f, 0, nullptr);

    // 8. bin smoothing -> cm (output) + cm1
    {
        long long tot = (long long)Bsz * Lsz * Lsz;
        smooth_k<<<(unsigned)((tot + 255) / 256), 256>>>(cmraw, smooth, agg, out, cm1b);
    }

    // 9. integral image
    zero_k<<<(Bsz*ISZ*ISZ + 255) / 256, 256>>>(Ib, Bsz*ISZ*ISZ);
    colsum_k<<<(Bsz*Lsz + 255) / 256, 256>>>(cm1b, csb);
    rowsum_k<<<(Bsz*Lsz + 255) / 256, 256>>>(csb, Ib);

    // 10. box sums + linear head + sigmoid
    finalize_k<<<Bsz, 128>>>(Ib, Lmat, biasp, pp_out);
}

// round 2
// speedup vs baseline: 1.1958x; 1.1958x over previous
#include <cuda_runtime.h>
#include <math.h>

#define Bsz 8
#define Lsz 512
#define IDIM 1024
#define Dm 512
#define Hh 8
#define DH 64
#define NBINS 25
#define PWc 10
#define HALFc 256
#define ISZ 513

// ------------------------- scratch (static device mem) -------------------------
__device__ float g_x1[Bsz*Lsz*Dm];
__device__ float g_x2[Bsz*Lsz*Dm];
__device__ float g_t1[Bsz*Lsz*Dm];
__device__ float g_t2[Bsz*Lsz*Dm];
__device__ float g_q [Bsz*Lsz*Dm];
__device__ float g_kv[Bsz*Lsz*2*Dm];
__device__ float g_o [Bsz*Lsz*Dm];
__device__ float g_att[Bsz*Hh*Lsz*Lsz];
__device__ float g_h1[(size_t)Bsz*NBINS*Lsz*HALFc];
__device__ float g_h2[(size_t)Bsz*NBINS*Lsz*HALFc];
__device__ float g_cmraw[(size_t)Bsz*NBINS*Lsz*Lsz];
__device__ float g_cm1[Bsz*Lsz*Lsz];
__device__ float g_cs [Bsz*Lsz*Lsz];
__device__ float g_I  [Bsz*ISZ*ISZ];

// packed dual-fp32 FMA (sm_100+): d = a*b + c elementwise on 2 lanes
__device__ __forceinline__ float2 ffma2(float2 a, float2 b, float2 c)
{
    unsigned long long ua = *reinterpret_cast<unsigned long long*>(&a);
    unsigned long long ub = *reinterpret_cast<unsigned long long*>(&b);
    unsigned long long uc = *reinterpret_cast<unsigned long long*>(&c);
    unsigned long long ud;
    asm("fma.rn.f32x2 %0, %1, %2, %3;" : "=l"(ud) : "l"(ua), "l"(ub), "l"(uc));
    return *reinterpret_cast<float2*>(&ud);
}

// ------------------------- tiled GEMM -------------------------
// C = act( alpha * A x op(B) + bias + Cres )
// TB=true : B is (N,K) row-major (C = A * B^T); TB=false: B is (K,N) row-major.
// two-level batching: z = z1*batch2 + z2.
// Requires: M%BM==0, N%BN==0, K%16==0, all row strides %4==0.
template<bool TB, int BM, int BN, int TM, int TN>
__global__ void __launch_bounds__(256)
gemm_k(const float* __restrict__ A, const float* __restrict__ B,
       float* __restrict__ C,
       int M, int N, int K, int lda, int ldb, int ldc,
       long long sA1, long long sA2, long long sB1, long long sB2,
       long long sC1, long long sC2, int batch2,
       const float* __restrict__ bias,
       float alpha, int act, const float* __restrict__ Cres)
{
    constexpr int BK = 16;
    int z  = blockIdx.z;
    int z1 = z / batch2, z2 = z % batch2;
    A += z1*sA1 + z2*sA2;
    B += z1*sB1 + z2*sB2;
    C += z1*sC1 + z2*sC2;
    if (Cres) Cres += z1*sC1 + z2*sC2;

    __shared__ float As[BK][BM+4];
    __shared__ float Bs[BK][BN+4];

    const int m0 = blockIdx.y * BM;
    const int n0 = blockIdx.x * BN;
    const int tid = threadIdx.x;          // 0..255
    const int tr = tid >> 4;              // 0..15
    const int tc = tid & 15;              // 0..15

    float2 acc[TM][TN/2];
    #pragma unroll
    for (int i = 0; i < TM; i++)
        #pragma unroll
        for (int j = 0; j < TN/2; j++) acc[i][j] = make_float2(0.f, 0.f);

    for (int k0 = 0; k0 < K; k0 += BK) {
        // ---- A tile: As[k][m], float4 loads along k ----
        #pragma unroll
        for (int i = 0; i < (BM*BK/4)/256; i++) {
            int idx = tid + i*256;
            int m = idx >> 2, c4 = (idx & 3) * 4;
            float4 t = *reinterpret_cast<const float4*>(
                &A[(long long)(m0+m)*lda + k0 + c4]);
            As[c4+0][m] = t.x; As[c4+1][m] = t.y;
            As[c4+2][m] = t.z; As[c4+3][m] = t.w;
        }
        // ---- B tile: Bs[k][n] ----
        if (TB) {
            #pragma unroll
            for (int i = 0; i < (BN*BK/4)/256; i++) {
                int idx = tid + i*256;
                int n = idx >> 2, c4 = (idx & 3) * 4;
                float4 t = *reinterpret_cast<const float4*>(
                    &B[(long long)(n0+n)*ldb + k0 + c4]);
                Bs[c4+0][n] = t.x; Bs[c4+1][n] = t.y;
                Bs[c4+2][n] = t.z; Bs[c4+3][n] = t.w;
            }
        } else {
            constexpr int NW = BN/4;
            #pragma unroll
            for (int i = 0; i < (BK*BN/4)/256; i++) {
                int idx = tid + i*256;
                int kk = idx / NW, n4 = (idx % NW) * 4;
                float4 t = *reinterpret_cast<const float4*>(
                    &B[(long long)(k0+kk)*ldb + n0 + n4]);
                *reinterpret_cast<float4*>(&Bs[kk][n4]) = t;
            }
        }
        __syncthreads();
        #pragma unroll
        for (int kk = 0; kk < BK; kk++) {
            float av[TM];
            #pragma unroll
            for (int i = 0; i < TM; i += 4) {
                float4 t = *reinterpret_cast<const float4*>(&As[kk][tr*TM + i]);
                av[i+0] = t.x; av[i+1] = t.y; av[i+2] = t.z; av[i+3] = t.w;
            }
            float2 bv[TN/2];
            #pragma unroll
            for (int j = 0; j < TN; j += 4) {
                float4 t = *reinterpret_cast<const float4*>(&Bs[kk][tc*TN + j]);
                bv[j/2+0] = make_float2(t.x, t.y);
                bv[j/2+1] = make_float2(t.z, t.w);
            }
            #pragma unroll
            for (int i = 0; i < TM; i++) {
                float2 a2 = make_float2(av[i], av[i]);
                #pragma unroll
                for (int j = 0; j < TN/2; j++)
                    acc[i][j] = ffma2(a2, bv[j], acc[i][j]);
            }
        }
        __syncthreads();
    }

    // ---- epilogue ----
    #pragma unroll
    for (int i = 0; i < TM; i++) {
        int m = m0 + tr*TM + i;
        long long rowo = (long long)m * ldc;
        #pragma unroll
        for (int j4 = 0; j4 < TN/4; j4++) {
            int n = n0 + tc*TN + j4*4;
            float v[4] = { acc[i][j4*2].x,   acc[i][j4*2].y,
                           acc[i][j4*2+1].x, acc[i][j4*2+1].y };
            #pragma unroll
            for (int u = 0; u < 4; u++) v[u] *= alpha;
            if (bias) {
                float4 bb = *reinterpret_cast<const float4*>(&bias[n]);
                v[0] += bb.x; v[1] += bb.y; v[2] += bb.z; v[3] += bb.w;
            }
            if (Cres) {
                float4 rr = *reinterpret_cast<const float4*>(&Cres[rowo + n]);
                v[0] += rr.x; v[1] += rr.y; v[2] += rr.z; v[3] += rr.w;
            }
            if (act) {
                #pragma unroll
                for (int u = 0; u < 4; u++) v[u] = tanhf(v[u]);
            }
            float4 o = make_float4(v[0], v[1], v[2], v[3]);
            *reinterpret_cast<float4*>(&C[rowo + n]) = o;
        }
    }
}

// ------------------------- softmax over rows of 512 -------------------------
__global__ void softmax_k(float* __restrict__ att)
{
    long long row = blockIdx.x;
    float* p = att + row * Lsz;
    int t = threadIdx.x;                     // 256 threads, 2 elems each
    float v0 = p[t], v1 = p[t + 256];

    __shared__ float red[8];
    unsigned lane = t & 31, w = t >> 5;

    float m = fmaxf(v0, v1);
    #pragma unroll
    for (int o = 16; o > 0; o >>= 1) m = fmaxf(m, __shfl_xor_sync(0xffffffffu, m, o));
    if (lane == 0) red[w] = m;
    __syncthreads();
    if (t == 0) {
        float mm = red[0];
        #pragma unroll
        for (int i = 1; i < 8; i++) mm = fmaxf(mm, red[i]);
        red[0] = mm;
    }
    __syncthreads();
    m = red[0];
    __syncthreads();

    float e0 = expf(v0 - m), e1 = expf(v1 - m);
    float s = e0 + e1;
    #pragma unroll
    for (int o = 16; o > 0; o >>= 1) s += __shfl_xor_sync(0xffffffffu, s, o);
    if (lane == 0) red[w] = s;
    __syncthreads();
    if (t == 0) {
        float ss = 0.f;
        #pragma unroll
        for (int i = 0; i < 8; i++) ss += red[i];
        red[0] = ss;
    }
    __syncthreads();
    float inv = 1.0f / red[0];
    p[t] = e0 * inv;
    p[t + 256] = e1 * inv;
}

// ------------------------- elementwise tanh -------------------------
__global__ void tanh_k(const float* __restrict__ in, float* __restrict__ out, int n)
{
    int i = blockIdx.x * blockDim.x + threadIdx.x;
    if (i < n) out[i] = tanhf(in[i]);
}

// ------------------------- bin smoothing + aggregate -------------------------
__global__ void smooth_k(const float* __restrict__ raw, const float* __restrict__ sm,
                         const float* __restrict__ agg, float* __restrict__ cm_out,
                         float* __restrict__ cm1)
{
    long long idx = (long long)blockIdx.x * blockDim.x + threadIdx.x;
    const long long tot = (long long)Bsz * Lsz * Lsz;
    if (idx >= tot) return;
    int b   = (int)(idx / ((long long)Lsz*Lsz));
    int rem = (int)(idx % ((long long)Lsz*Lsz));

    const float* p = raw + (long long)b * NBINS * Lsz * Lsz + rem;
    float rv[NBINS];
    #pragma unroll
    for (int n = 0; n < NBINS; n++) rv[n] = p[(long long)n * Lsz * Lsz];

    float sw[5];
    #pragma unroll
    for (int k = 0; k < 5; k++) sw[k] = sm[k];

    float* q = cm_out + (long long)b * NBINS * Lsz * Lsz + rem;
    float acc = 0.f;
    #pragma unroll
    for (int n = 0; n < NBINS; n++) {
        float v = 0.f;
        #pragma unroll
        for (int k = 0; k < 5; k++) {
            int m = n + k - 2;
            if (m >= 0 && m < NBINS) v += sw[k] * rv[m];
        }
        q[(long long)n * Lsz * Lsz] = v;
        acc += v * agg[n];
    }
    cm1[idx] = tanhf(acc);
}

// ------------------------- integral image -------------------------
__global__ void zero_k(float* __restrict__ p, int n)
{
    int i = blockIdx.x * blockDim.x + threadIdx.x;
    if (i < n) p[i] = 0.f;
}

__global__ void colsum_k(const float* __restrict__ cm1, float* __restrict__ cs)
{
    int t = blockIdx.x * blockDim.x + threadIdx.x;
    if (t >= Bsz * Lsz) return;
    int b = t / Lsz, j = t % Lsz;
    const float* src = cm1 + (long long)b * Lsz * Lsz + j;
    float* dst       = cs  + (long long)b * Lsz * Lsz + j;
    float acc = 0.f;
    for (int i = 0; i < Lsz; i++) {
        acc += src[(long long)i * Lsz];
        dst[(long long)i * Lsz] = acc;
    }
}

__global__ void rowsum_k(const float* __restrict__ cs, float* __restrict__ I)
{
    int t = blockIdx.x * blockDim.x + threadIdx.x;
    if (t >= Bsz * Lsz) return;
    int b = t / Lsz, i = t % Lsz;
    const float* src = cs + (long long)b * Lsz * Lsz + (long long)i * Lsz;
    float* row = I + (long long)b * ISZ * ISZ + (long long)(i + 1) * ISZ;
    float acc = 0.f;
    row[0] = 0.f;
    for (int j = 0; j < Lsz; j++) { acc += src[j]; row[j + 1] = acc; }
    if (i == 0) {
        float* r0 = I + (long long)b * ISZ * ISZ;
        for (int c = 0; c < ISZ; c++) r0[c] = 0.f;
    }
}

// ------------------------- box sums + sigmoid head -------------------------
__global__ void finalize_k(const float* __restrict__ I, const float* __restrict__ Lmat,
                           const float* __restrict__ biasp, float* __restrict__ pp)
{
    int b = blockIdx.x;
    __shared__ float terms[128];
    int t = threadIdx.x;
    float val = 0.f;
    if (t < PWc * PWc) {
        int p = t / PWc, q = t % PWc;
        const float* Ib = I + (long long)b * ISZ * ISZ;
        const int Hp = Lsz - PWc + 1;   // 503
        float w = Ib[(Hp + p) * ISZ + (Hp + q)] - Ib[(Hp + p) * ISZ + q]
                - Ib[p * ISZ + (Hp + q)]       + Ib[p * ISZ + q];
        val = tanhf(w) * Lmat[t];
    }
    terms[t] = val;
    __syncthreads();
    if (t == 0) {
        float s = 0.f;
        for (int i = 0; i < PWc * PWc; i++) s += terms[i];
        pp[b] = 1.0f / (1.0f + expf(-(s + biasp[0])));
    }
}

// ------------------------- host-side launch helpers -------------------------
static void gemm(bool tb, const float* A, const float* B, float* C,
                 int M, int N, int K, int lda, int ldb, int ldc,
                 long long sA1, long long sA2, long long sB1, long long sB2,
                 long long sC1, long long sC2, int batch1, int batch2,
                 const float* bias, float alpha, int act, const float* Cres)
{
    if (N % 128 == 0) {
        dim3 grid(N / 128, M / 128, batch1 * batch2);
        if (tb) gemm_k<true , 128, 128, 8, 8><<<grid, 256>>>(A, B, C, M, N, K, lda, ldb, ldc,
                     sA1, sA2, sB1, sB2, sC1, sC2, batch2, bias, alpha, act, Cres);
        else    gemm_k<false, 128, 128, 8, 8><<<grid, 256>>>(A, B, C, M, N, K, lda, ldb, ldc,
                     sA1, sA2, sB1, sB2, sC1, sC2, batch2, bias, alpha, act, Cres);
    } else {
        dim3 grid(N / 64, M / 128, batch1 * batch2);
        if (tb) gemm_k<true , 128, 64, 8, 4><<<grid, 256>>>(A, B, C, M, N, K, lda, ldb, ldc,
                     sA1, sA2, sB1, sB2, sC1, sC2, batch2, bias, alpha, act, Cres);
        else    gemm_k<false, 128, 64, 8, 4><<<grid, 256>>>(A, B, C, M, N, K, lda, ldb, ldc,
                     sA1, sA2, sB1, sB2, sC1, sC2, batch2, bias, alpha, act, Cres);
    }
}

static void run_mha(const float* xq, const float* xkv,
                    const float* in_w, const float* in_b,
                    const float* out_w, const float* out_b,
                    float* target, float* q, float* kv,
                    float* att, float* o)
{
    const int M = Bsz * Lsz;
    // q projection (N=512), fused k+v projection (N=1024)
    gemm(true, xq,  in_w,          q,  M, Dm,   Dm, Dm, Dm, Dm,    0,0,0,0,0,0, 1,1, in_b,      1.f, 0, nullptr);
    gemm(true, xkv, in_w + Dm*Dm,  kv, M, 2*Dm, Dm, Dm, Dm, 2*Dm,  0,0,0,0,0,0, 1,1, in_b + Dm, 1.f, 0, nullptr);
    // scores: (b,h) batched, S = Q K^T / 8;  K rows live in kv with stride 2*Dm
    gemm(true, q, kv, att, Lsz, Lsz, DH, Dm, 2*Dm, Lsz,
         (long long)Lsz*Dm, DH, (long long)Lsz*2*Dm, DH,
         (long long)Hh*Lsz*Lsz, (long long)Lsz*Lsz, Bsz, Hh,
         nullptr, 0.125f, 0, nullptr);
    softmax_k<<<Bsz*Hh*Lsz, 256>>>(att);
    // O = att @ V  (V part of kv at column offset Dm)
    gemm(false, att, kv + Dm, o, Lsz, DH, Lsz, Lsz, 2*Dm, Dm,
         (long long)Hh*Lsz*Lsz, (long long)Lsz*Lsz,
         (long long)Lsz*2*Dm, DH, (long long)Lsz*Dm, DH, Bsz, Hh,
         nullptr, 1.f, 0, nullptr);
    // output projection + residual into target
    gemm(true, o, out_w, target, M, Dm, Dm, Dm, Dm, Dm, 0,0,0,0,0,0, 1,1,
         out_b, 1.f, 0, target);
}

extern "C" void kernel_launch(void* const* d_in, const int* in_sizes, int n_in,
                              void* d_out, int out_size)
{
    const float* x1i     = (const float*)d_in[0];
    const float* x2i     = (const float*)d_in[1];
    const float* proj_w  = (const float*)d_in[2];
    const float* proj_b  = (const float*)d_in[3];
    const float* mha_in_w  = (const float*)d_in[4];
    const float* mha_in_b  = (const float*)d_in[5];
    const float* mha_out_w = (const float*)d_in[6];
    const float* mha_out_b = (const float*)d_in[7];
    const float* ca_in_w   = (const float*)d_in[8];
    const float* ca_in_b   = (const float*)d_in[9];
    const float* ca_out_w  = (const float*)d_in[10];
    const float* ca_out_b  = (const float*)d_in[11];
    const float* Wbins   = (const float*)d_in[12];
    const float* agg     = (const float*)d_in[13];
    const float* Lmat    = (const float*)d_in[14];
    const float* biasp   = (const float*)d_in[15];
    const float* smooth  = (const float*)d_in[16];

    float *x1b, *x2b, *t1b, *t2b, *qb, *kvb, *ob, *attb, *h1b, *h2b, *cmraw, *cm1b, *csb, *Ib;
    cudaGetSymbolAddress((void**)&x1b, g_x1);
    cudaGetSymbolAddress((void**)&x2b, g_x2);
    cudaGetSymbolAddress((void**)&t1b, g_t1);
    cudaGetSymbolAddress((void**)&t2b, g_t2);
    cudaGetSymbolAddress((void**)&qb,  g_q);
    cudaGetSymbolAddress((void**)&kvb, g_kv);
    cudaGetSymbolAddress((void**)&ob,  g_o);
    cudaGetSymbolAddress((void**)&attb, g_att);
    cudaGetSymbolAddress((void**)&h1b, g_h1);
    cudaGetSymbolAddress((void**)&h2b, g_h2);
    cudaGetSymbolAddress((void**)&cmraw, g_cmraw);
    cudaGetSymbolAddress((void**)&cm1b, g_cm1);
    cudaGetSymbolAddress((void**)&csb,  g_cs);
    cudaGetSymbolAddress((void**)&Ib,   g_I);

    float* out = (float*)d_out;
    float* pp_out = out + (out_size - Bsz);   // cm first, pp_prob last 8

    const int M = Bsz * Lsz;  // 4096
    const int NXD = M * Dm;   // elementwise sizes

    // 1. input projections
    gemm(true, x1i, proj_w, x1b, M, Dm, IDIM, IDIM, IDIM, Dm, 0,0,0,0,0,0, 1,1, proj_b, 1.f, 0, nullptr);
    gemm(true, x2i, proj_w, x2b, M, Dm, IDIM, IDIM, IDIM, Dm, 0,0,0,0,0,0, 1,1, proj_b, 1.f, 0, nullptr);

    // 2. self-attention (+residual)
    run_mha(x1b, x1b, mha_in_w, mha_in_b, mha_out_w, mha_out_b, x1b, qb, kvb, attb, ob);
    run_mha(x2b, x2b, mha_in_w, mha_in_b, mha_out_w, mha_out_b, x2b, qb, kvb, attb, ob);

    // 3. tanh copies for cross-attn inputs
    tanh_k<<<(NXD + 255) / 256, 256>>>(x1b, t1b, NXD);
    tanh_k<<<(NXD + 255) / 256, 256>>>(x2b, t2b, NXD);

    // 4. cross-attention (+residual into x)
    run_mha(t1b, t2b, ca_in_w, ca_in_b, ca_out_w, ca_out_b, x1b, qb, kvb, attb, ob);
    run_mha(t2b, t1b, ca_in_w, ca_in_b, ca_out_w, ca_out_b, x2b, qb, kvb, attb, ob);

    // 5. tanh in place
    tanh_k<<<(NXD + 255) / 256, 256>>>(x1b, x1b, NXD);
    tanh_k<<<(NXD + 255) / 256, 256>>>(x2b, x2b, NXD);

    // 6. h1/h2 = tanh(einsum('bld,ndk->bnlk'))  — batched over (b, n)
    gemm(false, x1b, Wbins, h1b, Lsz, HALFc, Dm, Dm, HALFc, HALFc,
         (long long)Lsz*Dm, 0, 0, (long long)Dm*HALFc,
         (long long)NBINS*Lsz*HALFc, (long long)Lsz*HALFc, Bsz, NBINS,
         nullptr, 1.f, 1, nullptr);
    gemm(false, x2b, Wbins, h2b, Lsz, HALFc, Dm, Dm, HALFc, HALFc,
         (long long)Lsz*Dm, 0, 0, (long long)Dm*HALFc,
         (long long)NBINS*Lsz*HALFc, (long long)Lsz*HALFc, Bsz, NBINS,
         nullptr, 1.f, 1, nullptr);

    // 7. cm_raw = h1 h2^T — batched over b*n = 200
    gemm(true, h1b, h2b, cmraw, Lsz, Lsz, HALFc, HALFc, HALFc, Lsz,
         (long long)Lsz*HALFc, 0, (long long)Lsz*HALFc, 0,
         (long long)Lsz*Lsz, 0, Bsz*NBINS, 1,
         nullptr, 1.f, 0, nullptr);

    // 8. bin smoothing -> cm (output) + cm1
    {
        long long tot = (long long)Bsz * Lsz * Lsz;
        smooth_k<<<(unsigned)((tot + 255) / 256), 256>>>(cmraw, smooth, agg, out, cm1b);
    }

    // 9. integral image
    zero_k<<<(Bsz*ISZ*ISZ + 255) / 256, 256>>>(Ib, Bsz*ISZ*ISZ);
    colsum_k<<<(Bsz*Lsz + 255) / 256, 256>>>(cm1b, csb);
    rowsum_k<<<(Bsz*Lsz + 255) / 256, 256>>>(csb, Ib);

    // 10. box sums + linear head + sigmoid
    finalize_k<<<Bsz, 128>>>(Ib, Lmat, biasp, pp_out);
}

// round 3
// speedup vs baseline: 1.1978x; 1.0017x over previous
#include <cuda_runtime.h>
#include <math.h>

#define Bsz 8
#define Lsz 512
#define IDIM 1024
#define Dm 512
#define Hh 8
#define DH 64
#define NBINS 25
#define PWc 10
#define HALFc 256
#define ISZ 513

// ------------------------- scratch (static device mem) -------------------------
__device__ float g_x1[Bsz*Lsz*Dm];
__device__ float g_x2[Bsz*Lsz*Dm];
__device__ float g_t1[Bsz*Lsz*Dm];
__device__ float g_t2[Bsz*Lsz*Dm];
__device__ float g_q [Bsz*Lsz*Dm];
__device__ float g_kv[Bsz*Lsz*2*Dm];
__device__ float g_o [Bsz*Lsz*Dm];
__device__ float g_att[Bsz*Hh*Lsz*Lsz];
__device__ float g_h1[(size_t)Bsz*NBINS*Lsz*HALFc];
__device__ float g_h2[(size_t)Bsz*NBINS*Lsz*HALFc];
__device__ float g_cmraw[(size_t)Bsz*NBINS*Lsz*Lsz];
__device__ float g_cm1[Bsz*Lsz*Lsz];
__device__ float g_cs [Bsz*Lsz*Lsz];
__device__ float g_I  [Bsz*ISZ*ISZ];

// packed dual-fp32 FMA (sm_100+): d = a*b + c elementwise on 2 lanes
__device__ __forceinline__ float2 ffma2(float2 a, float2 b, float2 c)
{
    unsigned long long ua = *reinterpret_cast<unsigned long long*>(&a);
    unsigned long long ub = *reinterpret_cast<unsigned long long*>(&b);
    unsigned long long uc = *reinterpret_cast<unsigned long long*>(&c);
    unsigned long long ud;
    asm("fma.rn.f32x2 %0, %1, %2, %3;" : "=l"(ud) : "l"(ua), "l"(ub), "l"(uc));
    return *reinterpret_cast<float2*>(&ud);
}

// ------------------------- tiled GEMM -------------------------
// C = act( alpha * A x op(B) + bias + Cres )
// TB=true : B is (N,K) row-major (C = A * B^T); TB=false: B is (K,N) row-major.
// two-level batching: z = z1*batch2 + z2.
// Requires: M%BM==0, N%BN==0, K%16==0, all row strides %4==0.
template<bool TB, int BM, int BN, int TM, int TN>
__global__ void __launch_bounds__(256)
gemm_k(const float* __restrict__ A, const float* __restrict__ B,
       float* __restrict__ C,
       int M, int N, int K, int lda, int ldb, int ldc,
       long long sA1, long long sA2, long long sB1, long long sB2,
       long long sC1, long long sC2, int batch2,
       const float* __restrict__ bias,
       float alpha, int act, const float* __restrict__ Cres)
{
    constexpr int BK = 16;
    int z  = blockIdx.z;
    int z1 = z / batch2, z2 = z % batch2;
    A += z1*sA1 + z2*sA2;
    B += z1*sB1 + z2*sB2;
    C += z1*sC1 + z2*sC2;
    if (Cres) Cres += z1*sC1 + z2*sC2;

    __shared__ float As[BK][BM+4];
    __shared__ float Bs[BK][BN+4];

    const int m0 = blockIdx.y * BM;
    const int n0 = blockIdx.x * BN;
    const int tid = threadIdx.x;          // 0..255
    const int tr = tid >> 4;              // 0..15
    const int tc = tid & 15;              // 0..15

    float2 acc[TM][TN/2];
    #pragma unroll
    for (int i = 0; i < TM; i++)
        #pragma unroll
        for (int j = 0; j < TN/2; j++) acc[i][j] = make_float2(0.f, 0.f);

    for (int k0 = 0; k0 < K; k0 += BK) {
        // ---- A tile: As[k][m], float4 loads along k ----
        #pragma unroll
        for (int i = 0; i < (BM*BK/4)/256; i++) {
            int idx = tid + i*256;
            int m = idx >> 2, c4 = (idx & 3) * 4;
            float4 t = *reinterpret_cast<const float4*>(
                &A[(long long)(m0+m)*lda + k0 + c4]);
            As[c4+0][m] = t.x; As[c4+1][m] = t.y;
            As[c4+2][m] = t.z; As[c4+3][m] = t.w;
        }
        // ---- B tile: Bs[k][n] ----
        if (TB) {
            #pragma unroll
            for (int i = 0; i < (BN*BK/4)/256; i++) {
                int idx = tid + i*256;
                int n = idx >> 2, c4 = (idx & 3) * 4;
                float4 t = *reinterpret_cast<const float4*>(
                    &B[(long long)(n0+n)*ldb + k0 + c4]);
                Bs[c4+0][n] = t.x; Bs[c4+1][n] = t.y;
                Bs[c4+2][n] = t.z; Bs[c4+3][n] = t.w;
            }
        } else {
            constexpr int NW = BN/4;
            #pragma unroll
            for (int i = 0; i < (BK*BN/4)/256; i++) {
                int idx = tid + i*256;
                int kk = idx / NW, n4 = (idx % NW) * 4;
                float4 t = *reinterpret_cast<const float4*>(
                    &B[(long long)(k0+kk)*ldb + n0 + n4]);
                *reinterpret_cast<float4*>(&Bs[kk][n4]) = t;
            }
        }
        __syncthreads();
        #pragma unroll
        for (int kk = 0; kk < BK; kk++) {
            float av[TM];
            #pragma unroll
            for (int i = 0; i < TM; i += 4) {
                float4 t = *reinterpret_cast<const float4*>(&As[kk][tr*TM + i]);
                av[i+0] = t.x; av[i+1] = t.y; av[i+2] = t.z; av[i+3] = t.w;
            }
            float2 bv[TN/2];
            #pragma unroll
            for (int j = 0; j < TN; j += 4) {
                float4 t = *reinterpret_cast<const float4*>(&Bs[kk][tc*TN + j]);
                bv[j/2+0] = make_float2(t.x, t.y);
                bv[j/2+1] = make_float2(t.z, t.w);
            }
            #pragma unroll
            for (int i = 0; i < TM; i++) {
                float2 a2 = make_float2(av[i], av[i]);
                #pragma unroll
                for (int j = 0; j < TN/2; j++)
                    acc[i][j] = ffma2(a2, bv[j], acc[i][j]);
            }
        }
        __syncthreads();
    }

    // ---- epilogue ----
    #pragma unroll
    for (int i = 0; i < TM; i++) {
        int m = m0 + tr*TM + i;
        long long rowo = (long long)m * ldc;
        #pragma unroll
        for (int j4 = 0; j4 < TN/4; j4++) {
            int n = n0 + tc*TN + j4*4;
            float v[4] = { acc[i][j4*2].x,   acc[i][j4*2].y,
                           acc[i][j4*2+1].x, acc[i][j4*2+1].y };
            #pragma unroll
            for (int u = 0; u < 4; u++) v[u] *= alpha;
            if (bias) {
                float4 bb = *reinterpret_cast<const float4*>(&bias[n]);
                v[0] += bb.x; v[1] += bb.y; v[2] += bb.z; v[3] += bb.w;
            }
            if (Cres) {
                float4 rr = *reinterpret_cast<const float4*>(&Cres[rowo + n]);
                v[0] += rr.x; v[1] += rr.y; v[2] += rr.z; v[3] += rr.w;
            }
            if (act) {
                #pragma unroll
                for (int u = 0; u < 4; u++) v[u] = tanhf(v[u]);
            }
            float4 o = make_float4(v[0], v[1], v[2], v[3]);
            *reinterpret_cast<float4*>(&C[rowo + n]) = o;
        }
    }
}

// ------------------------- softmax over rows of 512 -------------------------
__global__ void softmax_k(float* __restrict__ att)
{
    long long row = blockIdx.x;
    float* p = att + row * Lsz;
    int t = threadIdx.x;                     // 256 threads, 2 elems each
    float v0 = p[t], v1 = p[t + 256];

    __shared__ float red[8];
    unsigned lane = t & 31, w = t >> 5;

    float m = fmaxf(v0, v1);
    #pragma unroll
    for (int o = 16; o > 0; o >>= 1) m = fmaxf(m, __shfl_xor_sync(0xffffffffu, m, o));
    if (lane == 0) red[w] = m;
    __syncthreads();
    if (t == 0) {
        float mm = red[0];
        #pragma unroll
        for (int i = 1; i < 8; i++) mm = fmaxf(mm, red[i]);
        red[0] = mm;
    }
    __syncthreads();
    m = red[0];
    __syncthreads();

    float e0 = expf(v0 - m), e1 = expf(v1 - m);
    float s = e0 + e1;
    #pragma unroll
    for (int o = 16; o > 0; o >>= 1) s += __shfl_xor_sync(0xffffffffu, s, o);
    if (lane == 0) red[w] = s;
    __syncthreads();
    if (t == 0) {
        float ss = 0.f;
        #pragma unroll
        for (int i = 0; i < 8; i++) ss += red[i];
        red[0] = ss;
    }
    __syncthreads();
    float inv = 1.0f / red[0];
    p[t] = e0 * inv;
    p[t + 256] = e1 * inv;
}

// ------------------------- elementwise tanh -------------------------
__global__ void tanh_k(const float* __restrict__ in, float* __restrict__ out, int n)
{
    int i = blockIdx.x * blockDim.x + threadIdx.x;
    if (i < n) out[i] = tanhf(in[i]);
}

// ------------------------- bin smoothing + aggregate -------------------------
__global__ void smooth_k(const float* __restrict__ raw, const float* __restrict__ sm,
                         const float* __restrict__ agg, float* __restrict__ cm_out,
                         float* __restrict__ cm1)
{
    long long idx = (long long)blockIdx.x * blockDim.x + threadIdx.x;
    const long long tot = (long long)Bsz * Lsz * Lsz;
    if (idx >= tot) return;
    int b   = (int)(idx / ((long long)Lsz*Lsz));
    int rem = (int)(idx % ((long long)Lsz*Lsz));

    const float* p = raw + (long long)b * NBINS * Lsz * Lsz + rem;
    float rv[NBINS];
    #pragma unroll
    for (int n = 0; n < NBINS; n++) rv[n] = p[(long long)n * Lsz * Lsz];

    float sw[5];
    #pragma unroll
    for (int k = 0; k < 5; k++) sw[k] = sm[k];

    float* q = cm_out + (long long)b * NBINS * Lsz * Lsz + rem;
    float acc = 0.f;
    #pragma unroll
    for (int n = 0; n < NBINS; n++) {
        float v = 0.f;
        #pragma unroll
        for (int k = 0; k < 5; k++) {
            int m = n + k - 2;
            if (m >= 0 && m < NBINS) v += sw[k] * rv[m];
        }
        q[(long long)n * Lsz * Lsz] = v;
        acc += v * agg[n];
    }
    cm1[idx] = tanhf(acc);
}

// ------------------------- integral image -------------------------
__global__ void zero_k(float* __restrict__ p, int n)
{
    int i = blockIdx.x * blockDim.x + threadIdx.x;
    if (i < n) p[i] = 0.f;
}

__global__ void colsum_k(const float* __restrict__ cm1, float* __restrict__ cs)
{
    int t = blockIdx.x * blockDim.x + threadIdx.x;
    if (t >= Bsz * Lsz) return;
    int b = t / Lsz, j = t % Lsz;
    const float* src = cm1 + (long long)b * Lsz * Lsz + j;
    float* dst       = cs  + (long long)b * Lsz * Lsz + j;
    float acc = 0.f;
    for (int i = 0; i < Lsz; i++) {
        acc += src[(long long)i * Lsz];
        dst[(long long)i * Lsz] = acc;
    }
}

__global__ void rowsum_k(const float* __restrict__ cs, float* __restrict__ I)
{
    int t = blockIdx.x * blockDim.x + threadIdx.x;
    if (t >= Bsz * Lsz) return;
    int b = t / Lsz, i = t % Lsz;
    const float* src = cs + (long long)b * Lsz * Lsz + (long long)i * Lsz;
    float* row = I + (long long)b * ISZ * ISZ + (long long)(i + 1) * ISZ;
    float acc = 0.f;
    row[0] = 0.f;
    for (int j = 0; j < Lsz; j++) { acc += src[j]; row[j + 1] = acc; }
    if (i == 0) {
        float* r0 = I + (long long)b * ISZ * ISZ;
        for (int c = 0; c < ISZ; c++) r0[c] = 0.f;
    }
}

// ------------------------- box sums + sigmoid head -------------------------
__global__ void finalize_k(const float* __restrict__ I, const float* __restrict__ Lmat,
                           const float* __restrict__ biasp, float* __restrict__ pp)
{
    int b = blockIdx.x;
    __shared__ float terms[128];
    int t = threadIdx.x;
    float val = 0.f;
    if (t < PWc * PWc) {
        int p = t / PWc, q = t % PWc;
        const float* Ib = I + (long long)b * ISZ * ISZ;
        const int Hp = Lsz - PWc + 1;   // 503
        float w = Ib[(Hp + p) * ISZ + (Hp + q)] - Ib[(Hp + p) * ISZ + q]
                - Ib[p * ISZ + (Hp + q)]       + Ib[p * ISZ + q];
        val = tanhf(w) * Lmat[t];
    }
    terms[t] = val;
    __syncthreads();
    if (t == 0) {
        float s = 0.f;
        for (int i = 0; i < PWc * PWc; i++) s += terms[i];
        pp[b] = 1.0f / (1.0f + expf(-(s + biasp[0])));
    }
}

// ------------------------- host-side launch helpers -------------------------
static void gemm(bool tb, const float* A, const float* B, float* C,
                 int M, int N, int K, int lda, int ldb, int ldc,
                 long long sA1, long long sA2, long long sB1, long long sB2,
                 long long sC1, long long sC2, int batch1, int batch2,
                 const float* bias, float alpha, int act, const float* Cres)
{
    if (N % 128 == 0) {
        dim3 grid(N / 128, M / 128, batch1 * batch2);
        if (tb) gemm_k<true , 128, 128, 8, 8><<<grid, 256>>>(A, B, C, M, N, K, lda, ldb, ldc,
                     sA1, sA2, sB1, sB2, sC1, sC2, batch2, bias, alpha, act, Cres);
        else    gemm_k<false, 128, 128, 8, 8><<<grid, 256>>>(A, B, C, M, N, K, lda, ldb, ldc,
                     sA1, sA2, sB1, sB2, sC1, sC2, batch2, bias, alpha, act, Cres);
    } else {
        dim3 grid(N / 64, M / 128, batch1 * batch2);
        if (tb) gemm_k<true , 128, 64, 8, 4><<<grid, 256>>>(A, B, C, M, N, K, lda, ldb, ldc,
                     sA1, sA2, sB1, sB2, sC1, sC2, batch2, bias, alpha, act, Cres);
        else    gemm_k<false, 128, 64, 8, 4><<<grid, 256>>>(A, B, C, M, N, K, lda, ldb, ldc,
                     sA1, sA2, sB1, sB2, sC1, sC2, batch2, bias, alpha, act, Cres);
    }
}

static void run_mha(const float* xq, const float* xkv,
                    const float* in_w, const float* in_b,
                    const float* out_w, const float* out_b,
                    float* target, float* q, float* kv,
                    float* att, float* o)
{
    const int M = Bsz * Lsz;
    // q projection (N=512), fused k+v projection (N=1024)
    gemm(true, xq,  in_w,          q,  M, Dm,   Dm, Dm, Dm, Dm,    0,0,0,0,0,0, 1,1, in_b,      1.f, 0, nullptr);
    gemm(true, xkv, in_w + Dm*Dm,  kv, M, 2*Dm, Dm, Dm, Dm, 2*Dm,  0,0,0,0,0,0, 1,1, in_b + Dm, 1.f, 0, nullptr);
    // scores: (b,h) batched, S = Q K^T / 8;  K rows live in kv with stride 2*Dm
    gemm(true, q, kv, att, Lsz, Lsz, DH, Dm, 2*Dm, Lsz,
         (long long)Lsz*Dm, DH, (long long)Lsz*2*Dm, DH,
         (long long)Hh*Lsz*Lsz, (long long)Lsz*Lsz, Bsz, Hh,
         nullptr, 0.125f, 0, nullptr);
    softmax_k<<<Bsz*Hh*Lsz, 256>>>(att);
    // O = att @ V  (V part of kv at column offset Dm)
    gemm(false, att, kv + Dm, o, Lsz, DH, Lsz, Lsz, 2*Dm, Dm,
         (long long)Hh*Lsz*Lsz, (long long)Lsz*Lsz,
         (long long)Lsz*2*Dm, DH, (long long)Lsz*Dm, DH, Bsz, Hh,
         nullptr, 1.f, 0, nullptr);
    // output projection + residual into target
    gemm(true, o, out_w, target, M, Dm, Dm, Dm, Dm, Dm, 0,0,0,0,0,0, 1,1,
         out_b, 1.f, 0, target);
}

extern "C" void kernel_launch(void* const* d_in, const int* in_sizes, int n_in,
                              void* d_out, int out_size)
{
    const float* x1i     = (const float*)d_in[0];
    const float* x2i     = (const float*)d_in[1];
    const float* proj_w  = (const float*)d_in[2];
    const float* proj_b  = (const float*)d_in[3];
    const float* mha_in_w  = (const float*)d_in[4];
    const float* mha_in_b  = (const float*)d_in[5];
    const float* mha_out_w = (const float*)d_in[6];
    const float* mha_out_b = (const float*)d_in[7];
    const float* ca_in_w   = (const float*)d_in[8];
    const float* ca_in_b   = (const float*)d_in[9];
    const float* ca_out_w  = (const float*)d_in[10];
    const float* ca_out_b  = (const float*)d_in[11];
    const float* Wbins   = (const float*)d_in[12];
    const float* agg     = (const float*)d_in[13];
    const float* Lmat    = (const float*)d_in[14];
    const float* biasp   = (const float*)d_in[15];
    const float* smooth  = (const float*)d_in[16];

    float *x1b, *x2b, *t1b, *t2b, *qb, *kvb, *ob, *attb, *h1b, *h2b, *cmraw, *cm1b, *csb, *Ib;
    cudaGetSymbolAddress((void**)&x1b, g_x1);
    cudaGetSymbolAddress((void**)&x2b, g_x2);
    cudaGetSymbolAddress((void**)&t1b, g_t1);
    cudaGetSymbolAddress((void**)&t2b, g_t2);
    cudaGetSymbolAddress((void**)&qb,  g_q);
    cudaGetSymbolAddress((void**)&kvb, g_kv);
    cudaGetSymbolAddress((void**)&ob,  g_o);
    cudaGetSymbolAddress((void**)&attb, g_att);
    cudaGetSymbolAddress((void**)&h1b, g_h1);
    cudaGetSymbolAddress((void**)&h2b, g_h2);
    cudaGetSymbolAddress((void**)&cmraw, g_cmraw);
    cudaGetSymbolAddress((void**)&cm1b, g_cm1);
    cudaGetSymbolAddress((void**)&csb,  g_cs);
    cudaGetSymbolAddress((void**)&Ib,   g_I);

    float* out = (float*)d_out;
    float* pp_out = out + (out_size - Bsz);   // cm first, pp_prob last 8

    const int M = Bsz * Lsz;  // 4096
    const int NXD = M * Dm;   // elementwise sizes

    // 1. input projections
    gemm(true, x1i, proj_w, x1b, M, Dm, IDIM, IDIM, IDIM, Dm, 0,0,0,0,0,0, 1,1, proj_b, 1.f, 0, nullptr);
    gemm(true, x2i, proj_w, x2b, M, Dm, IDIM, IDIM, IDIM, Dm, 0,0,0,0,0,0, 1,1, proj_b, 1.f, 0, nullptr);

    // 2. self-attention (+residual)
    run_mha(x1b, x1b, mha_in_w, mha_in_b, mha_out_w, mha_out_b, x1b, qb, kvb, attb, ob);
    run_mha(x2b, x2b, mha_in_w, mha_in_b, mha_out_w, mha_out_b, x2b, qb, kvb, attb, ob);

    // 3. tanh copies for cross-attn inputs
    tanh_k<<<(NXD + 255) / 256, 256>>>(x1b, t1b, NXD);
    tanh_k<<<(NXD + 255) / 256, 256>>>(x2b, t2b, NXD);

    // 4. cross-attention (+residual into x)
    run_mha(t1b, t2b, ca_in_w, ca_in_b, ca_out_w, ca_out_b, x1b, qb, kvb, attb, ob);
    run_mha(t2b, t1b, ca_in_w, ca_in_b, ca_out_w, ca_out_b, x2b, qb, kvb, attb, ob);

    // 5. tanh in place
    tanh_k<<<(NXD + 255) / 256, 256>>>(x1b, x1b, NXD);
    tanh_k<<<(NXD + 255) / 256, 256>>>(x2b, x2b, NXD);

    // 6. h1/h2 = tanh(einsum('bld,ndk->bnlk'))  — batched over (b, n)
    gemm(false, x1b, Wbins, h1b, Lsz, HALFc, Dm, Dm, HALFc, HALFc,
         (long long)Lsz*Dm, 0, 0, (long long)Dm*HALFc,
         (long long)NBINS*Lsz*HALFc, (long long)Lsz*HALFc, Bsz, NBINS,
         nullptr, 1.f, 1, nullptr);
    gemm(false, x2b, Wbins, h2b, Lsz, HALFc, Dm, Dm, HALFc, HALFc,
         (long long)Lsz*Dm, 0, 0, (long long)Dm*HALFc,
         (long long)NBINS*Lsz*HALFc, (long long)Lsz*HALFc, Bsz, NBINS,
         nullptr, 1.f, 1, nullptr);

    // 7. cm_raw = h1 h2^T — batched over b*n = 200
    gemm(true, h1b, h2b, cmraw, Lsz, Lsz, HALFc, HALFc, HALFc, Lsz,
         (long long)Lsz*HALFc, 0, (long long)Lsz*HALFc, 0,
         (long long)Lsz*Lsz, 0, Bsz*NBINS, 1,
         nullptr, 1.f, 0, nullptr);

    // 8. bin smoothing -> cm (output) + cm1
    {
        long long tot = (long long)Bsz * Lsz * Lsz;
        smooth_k<<<(unsigned)((tot + 255) / 256), 256>>>(cmraw, smooth, agg, out, cm1b);
    }

    // 9. integral image
    zero_k<<<(Bsz*ISZ*ISZ + 255) / 256, 256>>>(Ib, Bsz*ISZ*ISZ);
    colsum_k<<<(Bsz*Lsz + 255) / 256, 256>>>(cm1b, csb);
    rowsum_k<<<(Bsz*Lsz + 255) / 256, 256>>>(csb, Ib);

    // 10. box sums + linear head + sigmoid
    finalize_k<<<Bsz, 128>>>(Ib, Lmat, biasp, pp_out);
}

// round 5
// speedup vs baseline: 2.4085x; 2.0108x over previous
#include <cuda_runtime.h>
#include <cuda_bf16.h>
#include <math.h>
#include <stdint.h>

#define Bsz 8
#define Lsz 512
#define IDIM 1024
#define Dm 512
#define Hh 8
#define DH 64
#define NBINS 25
#define PWc 10
#define HALFc 256
#define ISZ 513

typedef __nv_bfloat16 bf16;

// ------------------------- fp32 scratch -------------------------
__device__ float g_x1b[Bsz*Lsz*Dm];
__device__ float g_x2b[Bsz*Lsz*Dm];
__device__ float g_att[(size_t)Bsz*Hh*Lsz*Lsz];
__device__ float g_cmraw[(size_t)Bsz*NBINS*Lsz*Lsz];
__device__ float g_cm1[Bsz*Lsz*Lsz];
__device__ float g_cs [Bsz*Lsz*Lsz];
__device__ float g_I  [Bsz*ISZ*ISZ];

// ------------------------- bf16 hi/lo planes -------------------------
__device__ bf16 g_x1ih[Bsz*Lsz*IDIM], g_x1il[Bsz*Lsz*IDIM];
__device__ bf16 g_x2ih[Bsz*Lsz*IDIM], g_x2il[Bsz*Lsz*IDIM];
__device__ bf16 g_wph[Dm*IDIM],  g_wpl[Dm*IDIM];
__device__ bf16 g_miwh[3*Dm*Dm], g_miwl[3*Dm*Dm];
__device__ bf16 g_mowh[Dm*Dm],   g_mowl[Dm*Dm];
__device__ bf16 g_ciwh[3*Dm*Dm], g_ciwl[3*Dm*Dm];
__device__ bf16 g_cowh[Dm*Dm],   g_cowl[Dm*Dm];
__device__ bf16 g_x1h[Bsz*Lsz*Dm], g_x1l[Bsz*Lsz*Dm];
__device__ bf16 g_x2h[Bsz*Lsz*Dm], g_x2l[Bsz*Lsz*Dm];
__device__ bf16 g_t1h[Bsz*Lsz*Dm], g_t1l[Bsz*Lsz*Dm];
__device__ bf16 g_t2h[Bsz*Lsz*Dm], g_t2l[Bsz*Lsz*Dm];
__device__ bf16 g_qh [Bsz*Lsz*Dm], g_ql [Bsz*Lsz*Dm];
__device__ bf16 g_kh [Bsz*Lsz*Dm], g_kl [Bsz*Lsz*Dm];
__device__ bf16 g_vth[Dm*Bsz*Lsz], g_vtl[Dm*Bsz*Lsz];
__device__ bf16 g_oh [Bsz*Lsz*Dm], g_ol [Bsz*Lsz*Dm];
__device__ bf16 g_atth[(size_t)Bsz*Hh*Lsz*Lsz], g_attl[(size_t)Bsz*Hh*Lsz*Lsz];
__device__ bf16 g_wbth[NBINS*HALFc*Dm], g_wbtl[NBINS*HALFc*Dm];
__device__ bf16 g_h1h[(size_t)Bsz*NBINS*Lsz*HALFc], g_h1l[(size_t)Bsz*NBINS*Lsz*HALFc];
__device__ bf16 g_h2h[(size_t)Bsz*NBINS*Lsz*HALFc], g_h2l[(size_t)Bsz*NBINS*Lsz*HALFc];

// ------------------------- helpers -------------------------
__device__ __forceinline__ uint32_t smem_u32(const void* p){
    uint32_t a;
    asm("{ .reg .u64 t; cvta.to.shared.u64 t, %1; cvt.u32.u64 %0, t; }" : "=r"(a) : "l"(p));
    return a;
}
__device__ __forceinline__ void cp16(uint32_t dst, const void* src){
    asm volatile("cp.async.cg.shared.global [%0], [%1], 16;" :: "r"(dst), "l"(src));
}
#define CP_COMMIT() asm volatile("cp.async.commit_group;" ::: "memory")
#define CP_WAIT(n)  asm volatile("cp.async.wait_group %0;" :: "n"(n) : "memory")

__device__ __forceinline__ uint4 ldm4(uint32_t addr){
    uint4 r;
    asm volatile("ldmatrix.sync.aligned.m8n8.x4.shared.b16 {%0,%1,%2,%3}, [%4];"
        : "=r"(r.x), "=r"(r.y), "=r"(r.z), "=r"(r.w) : "r"(addr));
    return r;
}
__device__ __forceinline__ void mma_bf16(float c[4], uint4 a, uint32_t b0, uint32_t b1){
    asm volatile("mma.sync.aligned.m16n8k16.row.col.f32.bf16.bf16.f32 "
        "{%0,%1,%2,%3}, {%4,%5,%6,%7}, {%8,%9}, {%0,%1,%2,%3};"
        : "+f"(c[0]), "+f"(c[1]), "+f"(c[2]), "+f"(c[3])
        : "r"(a.x), "r"(a.y), "r"(a.z), "r"(a.w), "r"(b0), "r"(b1));
}

// fp32 -> bf16 hi (truncate) / lo (rn of remainder)
__device__ __forceinline__ void cvt_hilo(float4 v, uint2& hi, uint2& lo){
    uint32_t ux = __float_as_uint(v.x), uy = __float_as_uint(v.y),
             uz = __float_as_uint(v.z), uw = __float_as_uint(v.w);
    float hx = __uint_as_float(ux & 0xffff0000u);
    float hy = __uint_as_float(uy & 0xffff0000u);
    float hz = __uint_as_float(uz & 0xffff0000u);
    float hw = __uint_as_float(uw & 0xffff0000u);
    asm("prmt.b32 %0, %1, %2, 0x7632;" : "=r"(hi.x) : "r"(ux), "r"(uy));
    asm("prmt.b32 %0, %1, %2, 0x7632;" : "=r"(hi.y) : "r"(uz), "r"(uw));
    float lx = v.x - hx, ly = v.y - hy, lz = v.z - hz, lw = v.w - hw;
    asm("cvt.rn.bf16x2.f32 %0, %1, %2;" : "=r"(lo.x) : "f"(ly), "f"(lx));
    asm("cvt.rn.bf16x2.f32 %0, %1, %2;" : "=r"(lo.y) : "f"(lw), "f"(lz));
}
__device__ __forceinline__ void cvt_hilo2(float v0, float v1, uint32_t& h, uint32_t& l){
    uint32_t u0 = __float_as_uint(v0), u1 = __float_as_uint(v1);
    asm("prmt.b32 %0, %1, %2, 0x7632;" : "=r"(h) : "r"(u0), "r"(u1));
    float h0 = __uint_as_float(u0 & 0xffff0000u);
    float h1 = __uint_as_float(u1 & 0xffff0000u);
    asm("cvt.rn.bf16x2.f32 %0, %1, %2;" : "=r"(l) : "f"(v1-h1), "f"(v0-h0));
}
__device__ __forceinline__ void split1(float x, bf16* h, bf16* l){
    uint32_t ux = __float_as_uint(x);
    __nv_bfloat16_raw r; r.x = (unsigned short)(ux >> 16);
    *h = r;
    float hf = __uint_as_float(ux & 0xffff0000u);
    *l = __float2bfloat16(x - hf);
}

// ------------------------- mma.sync GEMM -------------------------
// C = act(alpha * A.B^T + bias + Cres); A:(M,K), B:(N,K) bf16 hi/lo planes.
// 2xBF16 emulation: 3 products per k-step. outMode bit0: fp32 C; bit1: planes Ch/Cl.
// biasMode: 0 none, 1 bias[n], 2 bias[m].
// BM=128, BK=32; 8 warps: 4(m) x 2(n), warp tile 32 x (BN/2).
template<int BN>
__global__ void __launch_bounds__(256)
gemm_mma(const bf16* __restrict__ Ah, const bf16* __restrict__ Al,
         const bf16* __restrict__ Bh, const bf16* __restrict__ Bl,
         float* __restrict__ C, bf16* __restrict__ Ch, bf16* __restrict__ Cl,
         int K, int lda, int ldb, int ldc,
         long long sA1, long long sA2, long long sB1, long long sB2,
         long long sC1, long long sC2, int batch2,
         const float* __restrict__ bias, int biasMode, float alpha, int act,
         const float* __restrict__ Cres, int outMode)
{
    constexpr int BM = 128, BK = 32;
    constexpr int ROWB = 80;                 // 64B data + 16B pad
    constexpr int APL = BM * ROWB;           // bytes per A plane
    constexpr int BPL = BN * ROWB;
    constexpr int STAGE = 2*APL + 2*BPL;
    constexpr int WN = BN / 2;               // warp tile n
    constexpr int NB = WN / 8;               // n8 blocks per warp
    constexpr int NCHUNK = (2*BM + 2*BN) * 4;

    extern __shared__ __align__(128) char smem[];
    const uint32_t sb = smem_u32(smem);

    const int z = blockIdx.z, z1 = z / batch2, z2 = z % batch2;
    const long long aoff = z1*sA1 + z2*sA2;
    const long long boff = z1*sB1 + z2*sB2;
    const long long coff = z1*sC1 + z2*sC2;
    Ah += aoff; Al += aoff;
    Bh += boff; Bl += boff;

    const int m0 = blockIdx.y * BM;
    const int n0 = blockIdx.x * BN;
    const int tid = threadIdx.x;
    const int wid = tid >> 5, lane = tid & 31;
    const int wm = wid >> 1, wn = wid & 1;
    const int mbase = wm * 32;
    const int nbase = wn * WN;

    float acc[2][NB][4];
    #pragma unroll
    for (int i = 0; i < 2; i++)
        #pragma unroll
        for (int j = 0; j < NB; j++)
            #pragma unroll
            for (int u = 0; u < 4; u++) acc[i][j][u] = 0.f;

    const int NC = K / BK;

    // ---- stage copy via cp.async ----
    auto stage_copy = [&](int c, int s){
        const uint32_t st = sb + (uint32_t)s * STAGE;
        #pragma unroll
        for (int i = 0; i < NCHUNK/256; i++) {
            int idx = tid + i*256;
            const bf16* src; uint32_t dst;
            if (idx < 2*BM*4) {
                int p = idx / (BM*4); int rem = idx - p*BM*4;
                int r = rem >> 2, cc = rem & 3;
                src = (p ? Al : Ah) + (long long)(m0+r)*lda + c*BK + cc*8;
                dst = st + p*APL + r*ROWB + cc*16;
            } else {
                int j = idx - 2*BM*4;
                int p = j / (BN*4); int rem = j - p*BN*4;
                int r = rem >> 2, cc = rem & 3;
                src = (p ? Bl : Bh) + (long long)(n0+r)*ldb + c*BK + cc*8;
                dst = st + 2*APL + p*BPL + r*ROWB + cc*16;
            }
            cp16(dst, src);
        }
    };

    // ---- compute one staged chunk ----
    auto compute = [&](int s){
        const uint32_t st = sb + (uint32_t)s * STAGE;
        const uint32_t ab = st;
        const uint32_t bb = st + 2*APL;
        const int arow = mbase + (lane & 15);
        const int akoff = ((lane >> 4) & 1) * 16;     // bytes (8 bf16)
        const int brow0 = nbase + (lane & 7) + ((lane >> 4) & 1) * 8;
        const int bkoff = ((lane >> 3) & 1) * 16;
        #pragma unroll
        for (int ks = 0; ks < 2; ks++) {
            const int kb = ks * 32;                   // byte offset of k16 step
            uint4 a[2][2];
            #pragma unroll
            for (int p = 0; p < 2; p++)
                #pragma unroll
                for (int mb = 0; mb < 2; mb++)
                    a[p][mb] = ldm4(ab + p*APL + (arow + mb*16)*ROWB + kb + akoff);
            uint4 b[2][NB/2];
            #pragma unroll
            for (int p = 0; p < 2; p++)
                #pragma unroll
                for (int nb2 = 0; nb2 < NB/2; nb2++)
                    b[p][nb2] = ldm4(bb + p*BPL + (brow0 + nb2*16)*ROWB + kb + bkoff);
            #pragma unroll
            for (int mb = 0; mb < 2; mb++)
                #pragma unroll
                for (int nb2 = 0; nb2 < NB/2; nb2++) {
                    float* c0 = acc[mb][2*nb2];
                    float* c1 = acc[mb][2*nb2+1];
                    mma_bf16(c0, a[0][mb], b[0][nb2].x, b[0][nb2].y);   // hh
                    mma_bf16(c1, a[0][mb], b[0][nb2].z, b[0][nb2].w);
                    mma_bf16(c0, a[0][mb], b[1][nb2].x, b[1][nb2].y);   // hl
                    mma_bf16(c1, a[0][mb], b[1][nb2].z, b[1][nb2].w);
                    mma_bf16(c0, a[1][mb], b[0][nb2].x, b[0][nb2].y);   // lh
                    mma_bf16(c1, a[1][mb], b[0][nb2].z, b[0][nb2].w);
                }
        }
    };

    // ---- pipelined mainloop ----
    stage_copy(0, 0);
    CP_COMMIT();
    for (int c = 0; c < NC; c++) {
        if (c + 1 < NC) {
            stage_copy(c + 1, (c + 1) & 1);
            CP_COMMIT();
            CP_WAIT(1);
        } else {
            CP_WAIT(0);
        }
        __syncthreads();
        compute(c & 1);
        __syncthreads();
    }

    // ---- epilogue ----
    const int g = lane >> 2, t = lane & 3;
    #pragma unroll
    for (int mb = 0; mb < 2; mb++) {
        #pragma unroll
        for (int half = 0; half < 2; half++) {
            const int row = m0 + mbase + mb*16 + g + half*8;
            const long long rowo = coff + (long long)row * ldc;
            float brow = (biasMode == 2) ? bias[row] : 0.f;
            #pragma unroll
            for (int nb = 0; nb < NB; nb++) {
                const int col = n0 + nbase + nb*8 + 2*t;
                float v0 = acc[mb][nb][half*2+0] * alpha;
                float v1 = acc[mb][nb][half*2+1] * alpha;
                if (biasMode == 1) {
                    float2 bb = *reinterpret_cast<const float2*>(&bias[col]);
                    v0 += bb.x; v1 += bb.y;
                } else if (biasMode == 2) {
                    v0 += brow; v1 += brow;
                }
                if (Cres) {
                    float2 rr = *reinterpret_cast<const float2*>(&Cres[rowo + col]);
                    v0 += rr.x; v1 += rr.y;
                }
                if (act) { v0 = tanhf(v0); v1 = tanhf(v1); }
                if (outMode & 1)
                    *reinterpret_cast<float2*>(&C[rowo + col]) = make_float2(v0, v1);
                if (outMode & 2) {
                    uint32_t h, l;
                    cvt_hilo2(v0, v1, h, l);
                    *reinterpret_cast<uint32_t*>(&Ch[rowo + col]) = h;
                    *reinterpret_cast<uint32_t*>(&Cl[rowo + col]) = l;
                }
            }
        }
    }
}

// ------------------------- converts -------------------------
__global__ void split_k(const float* __restrict__ in, bf16* __restrict__ oh,
                        bf16* __restrict__ ol, int n4)
{
    int i = blockIdx.x * blockDim.x + threadIdx.x;
    if (i >= n4) return;
    float4 v = reinterpret_cast<const float4*>(in)[i];
    uint2 h, l; cvt_hilo(v, h, l);
    reinterpret_cast<uint2*>(oh)[i] = h;
    reinterpret_cast<uint2*>(ol)[i] = l;
}
__global__ void tanh_split_k(const float* __restrict__ in, bf16* __restrict__ oh,
                             bf16* __restrict__ ol, int n4)
{
    int i = blockIdx.x * blockDim.x + threadIdx.x;
    if (i >= n4) return;
    float4 v = reinterpret_cast<const float4*>(in)[i];
    v.x = tanhf(v.x); v.y = tanhf(v.y); v.z = tanhf(v.z); v.w = tanhf(v.w);
    uint2 h, l; cvt_hilo(v, h, l);
    reinterpret_cast<uint2*>(oh)[i] = h;
    reinterpret_cast<uint2*>(ol)[i] = l;
}
// Wbins (n, d=512, k=256) -> planes (n, k=256, d=512)
__global__ void transpose_split_k(const float* __restrict__ in,
                                  bf16* __restrict__ oh, bf16* __restrict__ ol)
{
    __shared__ float tile[32][33];
    int n = blockIdx.z;
    int k0 = blockIdx.x * 32, d0 = blockIdx.y * 32;
    in += (size_t)n * Dm * HALFc;
    oh += (size_t)n * HALFc * Dm;
    ol += (size_t)n * HALFc * Dm;
    int tx = threadIdx.x, ty = threadIdx.y;
    #pragma unroll
    for (int i = ty; i < 32; i += 8)
        tile[i][tx] = in[(d0 + i) * HALFc + k0 + tx];
    __syncthreads();
    #pragma unroll
    for (int i = ty; i < 32; i += 8) {
        bf16 h, l; split1(tile[tx][i], &h, &l);
        oh[(k0 + i) * Dm + d0 + tx] = h;
        ol[(k0 + i) * Dm + d0 + tx] = l;
    }
}

// ------------------------- softmax (rows of 512) -> bf16 planes -------------------------
__global__ void softmax_k(const float* __restrict__ att,
                          bf16* __restrict__ oh, bf16* __restrict__ ol)
{
    long long row = blockIdx.x;
    const float* p = att + row * Lsz;
    int t = threadIdx.x;
    float v0 = p[t], v1 = p[t + 256];

    __shared__ float red[8];
    unsigned lane = t & 31, w = t >> 5;

    float m = fmaxf(v0, v1);
    #pragma unroll
    for (int o = 16; o > 0; o >>= 1) m = fmaxf(m, __shfl_xor_sync(0xffffffffu, m, o));
    if (lane == 0) red[w] = m;
    __syncthreads();
    if (t == 0) {
        float mm = red[0];
        #pragma unroll
        for (int i = 1; i < 8; i++) mm = fmaxf(mm, red[i]);
        red[0] = mm;
    }
    __syncthreads();
    m = red[0];
    __syncthreads();

    float e0 = expf(v0 - m), e1 = expf(v1 - m);
    float s = e0 + e1;
    #pragma unroll
    for (int o = 16; o > 0; o >>= 1) s += __shfl_xor_sync(0xffffffffu, s, o);
    if (lane == 0) red[w] = s;
    __syncthreads();
    if (t == 0) {
        float ss = 0.f;
        #pragma unroll
        for (int i = 0; i < 8; i++) ss += red[i];
        red[0] = ss;
    }
    __syncthreads();
    float inv = 1.0f / red[0];
    bf16 h, l;
    split1(e0 * inv, &h, &l); oh[row*Lsz + t] = h;       ol[row*Lsz + t] = l;
    split1(e1 * inv, &h, &l); oh[row*Lsz + t + 256] = h; ol[row*Lsz + t + 256] = l;
}

// ------------------------- bin smoothing + aggregate -------------------------
__global__ void smooth_k(const float* __restrict__ raw, const float* __restrict__ sm,
                         const float* __restrict__ agg, float* __restrict__ cm_out,
                         float* __restrict__ cm1)
{
    long long idx = (long long)blockIdx.x * blockDim.x + threadIdx.x;
    const long long tot = (long long)Bsz * Lsz * Lsz;
    if (idx >= tot) return;
    int b   = (int)(idx / ((long long)Lsz*Lsz));
    int rem = (int)(idx % ((long long)Lsz*Lsz));

    const float* p = raw + (long long)b * NBINS * Lsz * Lsz + rem;
    float rv[NBINS];
    #pragma unroll
    for (int n = 0; n < NBINS; n++) rv[n] = p[(long long)n * Lsz * Lsz];

    float sw[5];
    #pragma unroll
    for (int k = 0; k < 5; k++) sw[k] = sm[k];

    float* q = cm_out + (long long)b * NBINS * Lsz * Lsz + rem;
    float acc = 0.f;
    #pragma unroll
    for (int n = 0; n < NBINS; n++) {
        float v = 0.f;
        #pragma unroll
        for (int k = 0; k < 5; k++) {
            int m = n + k - 2;
            if (m >= 0 && m < NBINS) v += sw[k] * rv[m];
        }
        q[(long long)n * Lsz * Lsz] = v;
        acc += v * agg[n];
    }
    cm1[idx] = tanhf(acc);
}

// ------------------------- integral image + head -------------------------
__global__ void zero_k(float* __restrict__ p, int n)
{
    int i = blockIdx.x * blockDim.x + threadIdx.x;
    if (i < n) p[i] = 0.f;
}
__global__ void colsum_k(const float* __restrict__ cm1, float* __restrict__ cs)
{
    int t = blockIdx.x * blockDim.x + threadIdx.x;
    if (t >= Bsz * Lsz) return;
    int b = t / Lsz, j = t % Lsz;
    const float* src = cm1 + (long long)b * Lsz * Lsz + j;
    float* dst       = cs  + (long long)b * Lsz * Lsz + j;
    float acc = 0.f;
    for (int i = 0; i < Lsz; i++) {
        acc += src[(long long)i * Lsz];
        dst[(long long)i * Lsz] = acc;
    }
}
__global__ void rowsum_k(const float* __restrict__ cs, float* __restrict__ I)
{
    int t = blockIdx.x * blockDim.x + threadIdx.x;
    if (t >= Bsz * Lsz) return;
    int b = t / Lsz, i = t % Lsz;
    const float* src = cs + (long long)b * Lsz * Lsz + (long long)i * Lsz;
    float* row = I + (long long)b * ISZ * ISZ + (long long)(i + 1) * ISZ;
    float acc = 0.f;
    row[0] = 0.f;
    for (int j = 0; j < Lsz; j++) { acc += src[j]; row[j + 1] = acc; }
    if (i == 0) {
        float* r0 = I + (long long)b * ISZ * ISZ;
        for (int c = 0; c < ISZ; c++) r0[c] = 0.f;
    }
}
__global__ void finalize_k(const float* __restrict__ I, const float* __restrict__ Lmat,
                           const float* __restrict__ biasp, float* __restrict__ pp)
{
    int b = blockIdx.x;
    __shared__ float terms[128];
    int t = threadIdx.x;
    float val = 0.f;
    if (t < PWc * PWc) {
        int p = t / PWc, q = t % PWc;
        const float* Ib = I + (long long)b * ISZ * ISZ;
        const int Hp = Lsz - PWc + 1;   // 503
        float w = Ib[(Hp + p) * ISZ + (Hp + q)] - Ib[(Hp + p) * ISZ + q]
                - Ib[p * ISZ + (Hp + q)]       + Ib[p * ISZ + q];
        val = tanhf(w) * Lmat[t];
    }
    terms[t] = val;
    __syncthreads();
    if (t == 0) {
        float s = 0.f;
        for (int i = 0; i < PWc * PWc; i++) s += terms[i];
        pp[b] = 1.0f / (1.0f + expf(-(s + biasp[0])));
    }
}

// ------------------------- host-side -------------------------
static int SMEM_BYTES(int BN) { return 2 * (2*128*80 + 2*BN*80); }   // 81920 / 61440

static void gemm(int BN, const bf16* Ah, const bf16* Al, const bf16* Bh, const bf16* Bl,
                 float* C, bf16* Ch, bf16* Cl,
                 int M, int N, int K, int lda, int ldb, int ldc,
                 long long sA1, long long sA2, long long sB1, long long sB2,
                 long long sC1, long long sC2, int batch1, int batch2,
                 const float* bias, int biasMode, float alpha, int act,
                 const float* Cres, int outMode)
{
    dim3 grid(N / BN, M / 128, batch1 * batch2);
    if (BN == 128)
        gemm_mma<128><<<grid, 256, SMEM_BYTES(128)>>>(Ah, Al, Bh, Bl, C, Ch, Cl,
            K, lda, ldb, ldc, sA1, sA2, sB1, sB2, sC1, sC2, batch2,
            bias, biasMode, alpha, act, Cres, outMode);
    else
        gemm_mma<64><<<grid, 256, SMEM_BYTES(64)>>>(Ah, Al, Bh, Bl, C, Ch, Cl,
            K, lda, ldb, ldc, sA1, sA2, sB1, sB2, sC1, sC2, batch2,
            bias, biasMode, alpha, act, Cres, outMode);
}

struct Ptrs {
    float *x1b, *x2b, *att, *cmraw, *cm1, *cs, *I;
    bf16 *x1ih,*x1il,*x2ih,*x2il,*wph,*wpl,*miwh,*miwl,*mowh,*mowl,*ciwh,*ciwl,*cowh,*cowl;
    bf16 *x1h,*x1l,*x2h,*x2l,*t1h,*t1l,*t2h,*t2l,*qh,*ql,*kh,*kl,*vth,*vtl,*oh,*ol;
    bf16 *atth,*attl,*wbth,*wbtl,*h1h,*h1l,*h2h,*h2l;
};

static void run_mha(const Ptrs& P,
                    const bf16* xqh, const bf16* xql,
                    const bf16* xkh, const bf16* xkl,
                    const bf16* iwh, const bf16* iwl, const float* in_b,
                    const bf16* owh, const bf16* owl, const float* out_b,
                    float* target)
{
    const int M = Bsz * Lsz;
    // Q = xq Wq^T + bq   (planes out)
    gemm(128, xqh, xql, iwh, iwl, nullptr, P.qh, P.ql,
         M, Dm, Dm, Dm, Dm, Dm, 0,0,0,0,0,0, 1,1, in_b, 1, 1.f, 0, nullptr, 2);
    // K = xkv Wk^T + bk
    gemm(128, xkh, xkl, iwh + Dm*Dm, iwl + Dm*Dm, nullptr, P.kh, P.kl,
         M, Dm, Dm, Dm, Dm, Dm, 0,0,0,0,0,0, 1,1, in_b + Dm, 1, 1.f, 0, nullptr, 2);
    // V^T = Wv xkv^T + bv (row bias) : C is (Dm, M)
    gemm(128, iwh + 2*Dm*Dm, iwl + 2*Dm*Dm, xkh, xkl, nullptr, P.vth, P.vtl,
         Dm, M, Dm, Dm, Dm, M, 0,0,0,0,0,0, 1,1, in_b + 2*Dm, 2, 1.f, 0, nullptr, 2);
    // scores = Q K^T / 8 -> fp32
    gemm(128, P.qh, P.ql, P.kh, P.kl, P.att, nullptr, nullptr,
         Lsz, Lsz, DH, Dm, Dm, Lsz,
         (long long)Lsz*Dm, DH, (long long)Lsz*Dm, DH,
         (long long)Hh*Lsz*Lsz, (long long)Lsz*Lsz, Bsz, Hh,
         nullptr, 0, 0.125f, 0, nullptr, 1);
    softmax_k<<<Bsz*Hh*Lsz, 256>>>(P.att, P.atth, P.attl);
    // O = att V = att (V^T)^T  -> planes
    gemm(64, P.atth, P.attl, P.vth, P.vtl, nullptr, P.oh, P.ol,
         Lsz, DH, Lsz, Lsz, M, Dm,
         (long long)Hh*Lsz*Lsz, (long long)Lsz*Lsz,
         (long long)Lsz, (long long)DH*M,
         (long long)Lsz*Dm, (long long)DH, Bsz, Hh,
         nullptr, 0, 1.f, 0, nullptr, 2);
    // out-proj + residual -> fp32 target
    gemm(128, P.oh, P.ol, owh, owl, target, nullptr, nullptr,
         M, Dm, Dm, Dm, Dm, Dm, 0,0,0,0,0,0, 1,1, out_b, 1, 1.f, 0, target, 1);
}

extern "C" void kernel_launch(void* const* d_in, const int* in_sizes, int n_in,
                              void* d_out, int out_size)
{
    const float* x1i     = (const float*)d_in[0];
    const float* x2i     = (const float*)d_in[1];
    const float* proj_w  = (const float*)d_in[2];
    const float* proj_b  = (const float*)d_in[3];
    const float* mha_in_w  = (const float*)d_in[4];
    const float* mha_in_b  = (const float*)d_in[5];
    const float* mha_out_w = (const float*)d_in[6];
    const float* mha_out_b = (const float*)d_in[7];
    const float* ca_in_w   = (const float*)d_in[8];
    const float* ca_in_b   = (const float*)d_in[9];
    const float* ca_out_w  = (const float*)d_in[10];
    const float* ca_out_b  = (const float*)d_in[11];
    const float* Wbins   = (const float*)d_in[12];
    const float* agg     = (const float*)d_in[13];
    const float* Lmat    = (const float*)d_in[14];
    const float* biasp   = (const float*)d_in[15];
    const float* smooth  = (const float*)d_in[16];

    cudaFuncSetAttribute(gemm_mma<128>, cudaFuncAttributeMaxDynamicSharedMemorySize, SMEM_BYTES(128));
    cudaFuncSetAttribute(gemm_mma<64>,  cudaFuncAttributeMaxDynamicSharedMemorySize, SMEM_BYTES(64));

    Ptrs P;
    cudaGetSymbolAddress((void**)&P.x1b, g_x1b);   cudaGetSymbolAddress((void**)&P.x2b, g_x2b);
    cudaGetSymbolAddress((void**)&P.att, g_att);   cudaGetSymbolAddress((void**)&P.cmraw, g_cmraw);
    cudaGetSymbolAddress((void**)&P.cm1, g_cm1);   cudaGetSymbolAddress((void**)&P.cs, g_cs);
    cudaGetSymbolAddress((void**)&P.I, g_I);
    cudaGetSymbolAddress((void**)&P.x1ih, g_x1ih); cudaGetSymbolAddress((void**)&P.x1il, g_x1il);
    cudaGetSymbolAddress((void**)&P.x2ih, g_x2ih); cudaGetSymbolAddress((void**)&P.x2il, g_x2il);
    cudaGetSymbolAddress((void**)&P.wph, g_wph);   cudaGetSymbolAddress((void**)&P.wpl, g_wpl);
    cudaGetSymbolAddress((void**)&P.miwh, g_miwh); cudaGetSymbolAddress((void**)&P.miwl, g_miwl);
    cudaGetSymbolAddress((void**)&P.mowh, g_mowh); cudaGetSymbolAddress((void**)&P.mowl, g_mowl);
    cudaGetSymbolAddress((void**)&P.ciwh, g_ciwh); cudaGetSymbolAddress((void**)&P.ciwl, g_ciwl);
    cudaGetSymbolAddress((void**)&P.cowh, g_cowh); cudaGetSymbolAddress((void**)&P.cowl, g_cowl);
    cudaGetSymbolAddress((void**)&P.x1h, g_x1h);   cudaGetSymbolAddress((void**)&P.x1l, g_x1l);
    cudaGetSymbolAddress((void**)&P.x2h, g_x2h);   cudaGetSymbolAddress((void**)&P.x2l, g_x2l);
    cudaGetSymbolAddress((void**)&P.t1h, g_t1h);   cudaGetSymbolAddress((void**)&P.t1l, g_t1l);
    cudaGetSymbolAddress((void**)&P.t2h, g_t2h);   cudaGetSymbolAddress((void**)&P.t2l, g_t2l);
    cudaGetSymbolAddress((void**)&P.qh, g_qh);     cudaGetSymbolAddress((void**)&P.ql, g_ql);
    cudaGetSymbolAddress((void**)&P.kh, g_kh);     cudaGetSymbolAddress((void**)&P.kl, g_kl);
    cudaGetSymbolAddress((void**)&P.vth, g_vth);   cudaGetSymbolAddress((void**)&P.vtl, g_vtl);
    cudaGetSymbolAddress((void**)&P.oh, g_oh);     cudaGetSymbolAddress((void**)&P.ol, g_ol);
    cudaGetSymbolAddress((void**)&P.atth, g_atth); cudaGetSymbolAddress((void**)&P.attl, g_attl);
    cudaGetSymbolAddress((void**)&P.wbth, g_wbth); cudaGetSymbolAddress((void**)&P.wbtl, g_wbtl);
    cudaGetSymbolAddress((void**)&P.h1h, g_h1h);   cudaGetSymbolAddress((void**)&P.h1l, g_h1l);
    cudaGetSymbolAddress((void**)&P.h2h, g_h2h);   cudaGetSymbolAddress((void**)&P.h2l, g_h2l);

    float* out = (float*)d_out;
    float* pp_out = out + (out_size - Bsz);   // cm first, pp_prob last 8

    const int M = Bsz * Lsz;  // 4096
    const int NXD = M * Dm;

    // 0. one-time splits (weights + inputs)
    split_k<<<(M*IDIM/4 + 255)/256, 256>>>(x1i, P.x1ih, P.x1il, M*IDIM/4);
    split_k<<<(M*IDIM/4 + 255)/256, 256>>>(x2i, P.x2ih, P.x2il, M*IDIM/4);
    split_k<<<(Dm*IDIM/4 + 255)/256, 256>>>(proj_w, P.wph, P.wpl, Dm*IDIM/4);
    split_k<<<(3*Dm*Dm/4 + 255)/256, 256>>>(mha_in_w, P.miwh, P.miwl, 3*Dm*Dm/4);
    split_k<<<(Dm*Dm/4 + 255)/256, 256>>>(mha_out_w, P.mowh, P.mowl, Dm*Dm/4);
    split_k<<<(3*Dm*Dm/4 + 255)/256, 256>>>(ca_in_w, P.ciwh, P.ciwl, 3*Dm*Dm/4);
    split_k<<<(Dm*Dm/4 + 255)/256, 256>>>(ca_out_w, P.cowh, P.cowl, Dm*Dm/4);
    {
        dim3 g(HALFc/32, Dm/32, NBINS);
        transpose_split_k<<<g, dim3(32,8)>>>(Wbins, P.wbth, P.wbtl);
    }

    // 1. input projections: fp32 + planes
    gemm(128, P.x1ih, P.x1il, P.wph, P.wpl, P.x1b, P.x1h, P.x1l,
         M, Dm, IDIM, IDIM, IDIM, Dm, 0,0,0,0,0,0, 1,1, proj_b, 1, 1.f, 0, nullptr, 3);
    gemm(128, P.x2ih, P.x2il, P.wph, P.wpl, P.x2b, P.x2h, P.x2l,
         M, Dm, IDIM, IDIM, IDIM, Dm, 0,0,0,0,0,0, 1,1, proj_b, 1, 1.f, 0, nullptr, 3);

    // 2. self-attention (+residual into fp32 x)
    run_mha(P, P.x1h, P.x1l, P.x1h, P.x1l, P.miwh, P.miwl, mha_in_b,
            P.mowh, P.mowl, mha_out_b, P.x1b);
    run_mha(P, P.x2h, P.x2l, P.x2h, P.x2l, P.miwh, P.miwl, mha_in_b,
            P.mowh, P.mowl, mha_out_b, P.x2b);

    // 3. tanh -> planes for cross-attn inputs
    tanh_split_k<<<(NXD/4 + 255)/256, 256>>>(P.x1b, P.t1h, P.t1l, NXD/4);
    tanh_split_k<<<(NXD/4 + 255)/256, 256>>>(P.x2b, P.t2h, P.t2l, NXD/4);

    // 4. cross-attention (+residual into x)
    run_mha(P, P.t1h, P.t1l, P.t2h, P.t2l, P.ciwh, P.ciwl, ca_in_b,
            P.cowh, P.cowl, ca_out_b, P.x1b);
    run_mha(P, P.t2h, P.t2l, P.t1h, P.t1l, P.ciwh, P.ciwl, ca_in_b,
            P.cowh, P.cowl, ca_out_b, P.x2b);

    // 5. tanh -> planes (reuse t buffers)
    tanh_split_k<<<(NXD/4 + 255)/256, 256>>>(P.x1b, P.t1h, P.t1l, NXD/4);
    tanh_split_k<<<(NXD/4 + 255)/256, 256>>>(P.x2b, P.t2h, P.t2l, NXD/4);

    // 6. h = tanh(x @ Wbins) per bin -> planes only
    gemm(128, P.t1h, P.t1l, P.wbth, P.wbtl, nullptr, P.h1h, P.h1l,
         Lsz, HALFc, Dm, Dm, Dm, HALFc,
         (long long)Lsz*Dm, 0, 0, (long long)HALFc*Dm,
         (long long)NBINS*Lsz*HALFc, (long long)Lsz*HALFc, Bsz, NBINS,
         nullptr, 0, 1.f, 1, nullptr, 2);
    gemm(128, P.t2h, P.t2l, P.wbth, P.wbtl, nullptr, P.h2h, P.h2l,
         Lsz, HALFc, Dm, Dm, Dm, HALFc,
         (long long)Lsz*Dm, 0, 0, (long long)HALFc*Dm,
         (long long)NBINS*Lsz*HALFc, (long long)Lsz*HALFc, Bsz, NBINS,
         nullptr, 0, 1.f, 1, nullptr, 2);

    // 7. cm_raw = h1 h2^T (batch 200) -> fp32
    gemm(128, P.h1h, P.h1l, P.h2h, P.h2l, P.cmraw, nullptr, nullptr,
         Lsz, Lsz, HALFc, HALFc, HALFc, Lsz,
         (long long)Lsz*HALFc, 0, (long long)Lsz*HALFc, 0,
         (long long)Lsz*Lsz, 0, Bsz*NBINS, 1,
         nullptr, 0, 1.f, 0, nullptr, 1);

    // 8. bin smoothing -> cm (output) + cm1
    {
        long long tot = (long long)Bsz * Lsz * Lsz;
        smooth_k<<<(unsigned)((tot + 255) / 256), 256>>>(P.cmraw, smooth, agg, out, P.cm1);
    }

    // 9. integral image
    zero_k<<<(Bsz*ISZ*ISZ + 255) / 256, 256>>>(P.I, Bsz*ISZ*ISZ);
    colsum_k<<<(Bsz*Lsz + 255) / 256, 256>>>(P.cm1, P.cs);
    rowsum_k<<<(Bsz*Lsz + 255) / 256, 256>>>(P.cs, P.I);

    // 10. box sums + linear head + sigmoid
    finalize_k<<<Bsz, 128>>>(P.I, Lmat, biasp, pp_out);
}

// round 6
// speedup vs baseline: 2.6416x; 1.0968x over previous
#include <cuda_runtime.h>
#include <cuda_bf16.h>
#include <math.h>
#include <stdint.h>

#define Bsz 8
#define Lsz 512
#define IDIM 1024
#define Dm 512
#define Hh 8
#define DH 64
#define NBINS 25
#define PWc 10
#define HALFc 256
#define ISZ 513

typedef __nv_bfloat16 bf16;

// ------------------------- fp32 scratch -------------------------
__device__ float g_x1b[Bsz*Lsz*Dm];
__device__ float g_x2b[Bsz*Lsz*Dm];
__device__ float g_att[(size_t)Bsz*Hh*Lsz*Lsz];
__device__ float g_cmraw[(size_t)Bsz*NBINS*Lsz*Lsz];
__device__ float g_cm1[Bsz*Lsz*Lsz];
__device__ float g_cs [Bsz*Lsz*Lsz];
__device__ float g_I  [Bsz*ISZ*ISZ];

// ------------------------- bf16 hi/lo planes -------------------------
__device__ bf16 g_x1ih[Bsz*Lsz*IDIM], g_x1il[Bsz*Lsz*IDIM];
__device__ bf16 g_x2ih[Bsz*Lsz*IDIM], g_x2il[Bsz*Lsz*IDIM];
__device__ bf16 g_wph[Dm*IDIM],  g_wpl[Dm*IDIM];
__device__ bf16 g_miwh[3*Dm*Dm], g_miwl[3*Dm*Dm];
__device__ bf16 g_mowh[Dm*Dm],   g_mowl[Dm*Dm];
__device__ bf16 g_ciwh[3*Dm*Dm], g_ciwl[3*Dm*Dm];
__device__ bf16 g_cowh[Dm*Dm],   g_cowl[Dm*Dm];
__device__ bf16 g_x1h[Bsz*Lsz*Dm], g_x1l[Bsz*Lsz*Dm];
__device__ bf16 g_x2h[Bsz*Lsz*Dm], g_x2l[Bsz*Lsz*Dm];
__device__ bf16 g_t1h[Bsz*Lsz*Dm], g_t1l[Bsz*Lsz*Dm];
__device__ bf16 g_t2h[Bsz*Lsz*Dm], g_t2l[Bsz*Lsz*Dm];
__device__ bf16 g_qh [Bsz*Lsz*Dm], g_ql [Bsz*Lsz*Dm];
__device__ bf16 g_kh [Bsz*Lsz*Dm], g_kl [Bsz*Lsz*Dm];
__device__ bf16 g_vth[Dm*Bsz*Lsz], g_vtl[Dm*Bsz*Lsz];
__device__ bf16 g_oh [Bsz*Lsz*Dm], g_ol [Bsz*Lsz*Dm];
__device__ bf16 g_atth[(size_t)Bsz*Hh*Lsz*Lsz], g_attl[(size_t)Bsz*Hh*Lsz*Lsz];
__device__ bf16 g_wbth[NBINS*HALFc*Dm], g_wbtl[NBINS*HALFc*Dm];
__device__ bf16 g_h1h[(size_t)Bsz*NBINS*Lsz*HALFc], g_h1l[(size_t)Bsz*NBINS*Lsz*HALFc];
__device__ bf16 g_h2h[(size_t)Bsz*NBINS*Lsz*HALFc], g_h2l[(size_t)Bsz*NBINS*Lsz*HALFc];

// ------------------------- helpers -------------------------
__device__ __forceinline__ uint32_t smem_u32(const void* p){
    uint32_t a;
    asm("{ .reg .u64 t; cvta.to.shared.u64 t, %1; cvt.u32.u64 %0, t; }" : "=r"(a) : "l"(p));
    return a;
}
__device__ __forceinline__ void cp16(uint32_t dst, const void* src){
    asm volatile("cp.async.cg.shared.global [%0], [%1], 16;" :: "r"(dst), "l"(src));
}
#define CP_COMMIT() asm volatile("cp.async.commit_group;" ::: "memory")
#define CP_WAIT(n)  asm volatile("cp.async.wait_group %0;" :: "n"(n) : "memory")

__device__ __forceinline__ uint4 ldm4(uint32_t addr){
    uint4 r;
    asm volatile("ldmatrix.sync.aligned.m8n8.x4.shared.b16 {%0,%1,%2,%3}, [%4];"
        : "=r"(r.x), "=r"(r.y), "=r"(r.z), "=r"(r.w) : "r"(addr));
    return r;
}
__device__ __forceinline__ void mma_bf16(float c[4], uint4 a, uint32_t b0, uint32_t b1){
    asm volatile("mma.sync.aligned.m16n8k16.row.col.f32.bf16.bf16.f32 "
        "{%0,%1,%2,%3}, {%4,%5,%6,%7}, {%8,%9}, {%0,%1,%2,%3};"
        : "+f"(c[0]), "+f"(c[1]), "+f"(c[2]), "+f"(c[3])
        : "r"(a.x), "r"(a.y), "r"(a.z), "r"(a.w), "r"(b0), "r"(b1));
}

// fp32 -> bf16 hi (truncate) / lo (rn of remainder)
__device__ __forceinline__ void cvt_hilo(float4 v, uint2& hi, uint2& lo){
    uint32_t ux = __float_as_uint(v.x), uy = __float_as_uint(v.y),
             uz = __float_as_uint(v.z), uw = __float_as_uint(v.w);
    float hx = __uint_as_float(ux & 0xffff0000u);
    float hy = __uint_as_float(uy & 0xffff0000u);
    float hz = __uint_as_float(uz & 0xffff0000u);
    float hw = __uint_as_float(uw & 0xffff0000u);
    asm("prmt.b32 %0, %1, %2, 0x7632;" : "=r"(hi.x) : "r"(ux), "r"(uy));
    asm("prmt.b32 %0, %1, %2, 0x7632;" : "=r"(hi.y) : "r"(uz), "r"(uw));
    float lx = v.x - hx, ly = v.y - hy, lz = v.z - hz, lw = v.w - hw;
    asm("cvt.rn.bf16x2.f32 %0, %1, %2;" : "=r"(lo.x) : "f"(ly), "f"(lx));
    asm("cvt.rn.bf16x2.f32 %0, %1, %2;" : "=r"(lo.y) : "f"(lw), "f"(lz));
}
__device__ __forceinline__ void cvt_hilo2(float v0, float v1, uint32_t& h, uint32_t& l){
    uint32_t u0 = __float_as_uint(v0), u1 = __float_as_uint(v1);
    asm("prmt.b32 %0, %1, %2, 0x7632;" : "=r"(h) : "r"(u0), "r"(u1));
    float h0 = __uint_as_float(u0 & 0xffff0000u);
    float h1 = __uint_as_float(u1 & 0xffff0000u);
    asm("cvt.rn.bf16x2.f32 %0, %1, %2;" : "=r"(l) : "f"(v1-h1), "f"(v0-h0));
}
__device__ __forceinline__ void split1(float x, bf16* h, bf16* l){
    uint32_t ux = __float_as_uint(x);
    __nv_bfloat16_raw r; r.x = (unsigned short)(ux >> 16);
    *h = r;
    float hf = __uint_as_float(ux & 0xffff0000u);
    *l = __float2bfloat16(x - hf);
}

// ------------------------- mma.sync GEMM -------------------------
// C = act(alpha * A.B^T + bias + Cres); A:(M,K), B:(N,K) bf16 hi/lo planes.
// 2xBF16 emulation: 3 products per k-step. outMode bit0: fp32 C; bit1: planes.
// biasMode: 0 none, 1 bias[n], 2 bias[m].
// BM=128; 8 warps: 4(m) x 2(n), warp tile 32 x (BN/2).
// Dynamic smem: STAGE * (K/BK > 1 ? 2 : 1) bytes.
template<int BN, int BK>
__global__ void __launch_bounds__(256)
gemm_mma(const bf16* __restrict__ Ah, const bf16* __restrict__ Al,
         const bf16* __restrict__ Bh, const bf16* __restrict__ Bl,
         float* __restrict__ C, bf16* __restrict__ Ch, bf16* __restrict__ Cl,
         int K, int lda, int ldb, int ldc,
         long long sA1, long long sA2, long long sB1, long long sB2,
         long long sC1, long long sC2, int batch2,
         const float* __restrict__ bias, int biasMode, float alpha, int act,
         const float* __restrict__ Cres, int outMode)
{
    constexpr int BM = 128;
    constexpr int ROWB = BK*2 + 16;          // bytes per smem row (pad keeps banks spread)
    constexpr int APL = BM * ROWB;           // bytes per A plane
    constexpr int BPL = BN * ROWB;
    constexpr int STAGE = 2*APL + 2*BPL;
    constexpr int WN = BN / 2;               // warp tile n
    constexpr int NB = WN / 8;               // n8 blocks per warp
    constexpr int KCH = BK / 8;              // 16B chunks per row per plane
    constexpr int NCHUNK = (2*BM + 2*BN) * KCH;

    extern __shared__ __align__(128) char smem[];
    const uint32_t sb = smem_u32(smem);

    const int z = blockIdx.z, z1 = z / batch2, z2 = z % batch2;
    const long long aoff = z1*sA1 + z2*sA2;
    const long long boff = z1*sB1 + z2*sB2;
    const long long coff = z1*sC1 + z2*sC2;
    Ah += aoff; Al += aoff;
    Bh += boff; Bl += boff;

    const int m0 = blockIdx.y * BM;
    const int n0 = blockIdx.x * BN;
    const int tid = threadIdx.x;
    const int wid = tid >> 5, lane = tid & 31;
    const int wm = wid >> 1, wn = wid & 1;
    const int mbase = wm * 32;
    const int nbase = wn * WN;

    float acc[2][NB][4];
    #pragma unroll
    for (int i = 0; i < 2; i++)
        #pragma unroll
        for (int j = 0; j < NB; j++)
            #pragma unroll
            for (int u = 0; u < 4; u++) acc[i][j][u] = 0.f;

    const int NC = K / BK;

    // ---- stage copy via cp.async ----
    auto stage_copy = [&](int c, int s){
        const uint32_t st = sb + (uint32_t)s * STAGE;
        #pragma unroll
        for (int i = 0; i < NCHUNK/256; i++) {
            int idx = tid + i*256;
            const bf16* src; uint32_t dst;
            if (idx < 2*BM*KCH) {
                int p = idx / (BM*KCH); int rem = idx - p*BM*KCH;
                int r = rem / KCH, cc = rem % KCH;
                src = (p ? Al : Ah) + (long long)(m0+r)*lda + c*BK + cc*8;
                dst = st + p*APL + r*ROWB + cc*16;
            } else {
                int j = idx - 2*BM*KCH;
                int p = j / (BN*KCH); int rem = j - p*BN*KCH;
                int r = rem / KCH, cc = rem % KCH;
                src = (p ? Bl : Bh) + (long long)(n0+r)*ldb + c*BK + cc*8;
                dst = st + 2*APL + p*BPL + r*ROWB + cc*16;
            }
            cp16(dst, src);
        }
    };

    // ---- compute one staged chunk ----
    auto compute = [&](int s){
        const uint32_t st = sb + (uint32_t)s * STAGE;
        const uint32_t ab = st;
        const uint32_t bb = st + 2*APL;
        const int arow = mbase + (lane & 15);
        const int akoff = ((lane >> 4) & 1) * 16;
        const int brow0 = nbase + (lane & 7) + ((lane >> 4) & 1) * 8;
        const int bkoff = ((lane >> 3) & 1) * 16;
        #pragma unroll
        for (int ks = 0; ks < BK/16; ks++) {
            const int kb = ks * 32;
            uint4 a[2][2];
            #pragma unroll
            for (int p = 0; p < 2; p++)
                #pragma unroll
                for (int mb = 0; mb < 2; mb++)
                    a[p][mb] = ldm4(ab + p*APL + (arow + mb*16)*ROWB + kb + akoff);
            uint4 b[2][NB/2];
            #pragma unroll
            for (int p = 0; p < 2; p++)
                #pragma unroll
                for (int nb2 = 0; nb2 < NB/2; nb2++)
                    b[p][nb2] = ldm4(bb + p*BPL + (brow0 + nb2*16)*ROWB + kb + bkoff);
            #pragma unroll
            for (int mb = 0; mb < 2; mb++)
                #pragma unroll
                for (int nb2 = 0; nb2 < NB/2; nb2++) {
                    float* c0 = acc[mb][2*nb2];
                    float* c1 = acc[mb][2*nb2+1];
                    mma_bf16(c0, a[0][mb], b[0][nb2].x, b[0][nb2].y);   // hh
                    mma_bf16(c1, a[0][mb], b[0][nb2].z, b[0][nb2].w);
                    mma_bf16(c0, a[0][mb], b[1][nb2].x, b[1][nb2].y);   // hl
                    mma_bf16(c1, a[0][mb], b[1][nb2].z, b[1][nb2].w);
                    mma_bf16(c0, a[1][mb], b[0][nb2].x, b[0][nb2].y);   // lh
                    mma_bf16(c1, a[1][mb], b[0][nb2].z, b[0][nb2].w);
                }
        }
    };

    // ---- pipelined mainloop: one barrier per chunk ----
    stage_copy(0, 0);
    CP_COMMIT();
    for (int c = 0; c < NC; c++) {
        CP_WAIT(0);
        __syncthreads();                       // stage c ready; prior compute done
        if (c + 1 < NC) { stage_copy(c + 1, (c + 1) & 1); CP_COMMIT(); }
        compute(c & 1);
    }

    // ---- epilogue ----
    const int g = lane >> 2, t = lane & 3;
    #pragma unroll
    for (int mb = 0; mb < 2; mb++) {
        #pragma unroll
        for (int half = 0; half < 2; half++) {
            const int row = m0 + mbase + mb*16 + g + half*8;
            const long long rowo = coff + (long long)row * ldc;
            float brow = (biasMode == 2) ? bias[row] : 0.f;
            #pragma unroll
            for (int nb = 0; nb < NB; nb++) {
                const int col = n0 + nbase + nb*8 + 2*t;
                float v0 = acc[mb][nb][half*2+0] * alpha;
                float v1 = acc[mb][nb][half*2+1] * alpha;
                if (biasMode == 1) {
                    float2 bb = *reinterpret_cast<const float2*>(&bias[col]);
                    v0 += bb.x; v1 += bb.y;
                } else if (biasMode == 2) {
                    v0 += brow; v1 += brow;
                }
                if (Cres) {
                    float2 rr = *reinterpret_cast<const float2*>(&Cres[rowo + col]);
                    v0 += rr.x; v1 += rr.y;
                }
                if (act) { v0 = tanhf(v0); v1 = tanhf(v1); }
                if (outMode & 1)
                    *reinterpret_cast<float2*>(&C[rowo + col]) = make_float2(v0, v1);
                if (outMode & 2) {
                    uint32_t h, l;
                    cvt_hilo2(v0, v1, h, l);
                    *reinterpret_cast<uint32_t*>(&Ch[rowo + col]) = h;
                    *reinterpret_cast<uint32_t*>(&Cl[rowo + col]) = l;
                }
            }
        }
    }
}

// ------------------------- converts -------------------------
__global__ void split_k(const float* __restrict__ in, bf16* __restrict__ oh,
                        bf16* __restrict__ ol, int n4)
{
    int i = blockIdx.x * blockDim.x + threadIdx.x;
    if (i >= n4) return;
    float4 v = reinterpret_cast<const float4*>(in)[i];
    uint2 h, l; cvt_hilo(v, h, l);
    reinterpret_cast<uint2*>(oh)[i] = h;
    reinterpret_cast<uint2*>(ol)[i] = l;
}
__global__ void tanh_split_k(const float* __restrict__ in, bf16* __restrict__ oh,
                             bf16* __restrict__ ol, int n4)
{
    int i = blockIdx.x * blockDim.x + threadIdx.x;
    if (i >= n4) return;
    float4 v = reinterpret_cast<const float4*>(in)[i];
    v.x = tanhf(v.x); v.y = tanhf(v.y); v.z = tanhf(v.z); v.w = tanhf(v.w);
    uint2 h, l; cvt_hilo(v, h, l);
    reinterpret_cast<uint2*>(oh)[i] = h;
    reinterpret_cast<uint2*>(ol)[i] = l;
}
// Wbins (n, d=512, k=256) -> planes (n, k=256, d=512)
__global__ void transpose_split_k(const float* __restrict__ in,
                                  bf16* __restrict__ oh, bf16* __restrict__ ol)
{
    __shared__ float tile[32][33];
    int n = blockIdx.z;
    int k0 = blockIdx.x * 32, d0 = blockIdx.y * 32;
    in += (size_t)n * Dm * HALFc;
    oh += (size_t)n * HALFc * Dm;
    ol += (size_t)n * HALFc * Dm;
    int tx = threadIdx.x, ty = threadIdx.y;
    #pragma unroll
    for (int i = ty; i < 32; i += 8)
        tile[i][tx] = in[(d0 + i) * HALFc + k0 + tx];
    __syncthreads();
    #pragma unroll
    for (int i = ty; i < 32; i += 8) {
        bf16 h, l; split1(tile[tx][i], &h, &l);
        oh[(k0 + i) * Dm + d0 + tx] = h;
        ol[(k0 + i) * Dm + d0 + tx] = l;
    }
}

// ------------------------- softmax (rows of 512) -> bf16 planes -------------------------
__global__ void softmax_k(const float* __restrict__ att,
                          bf16* __restrict__ oh, bf16* __restrict__ ol)
{
    long long row = blockIdx.x;
    const float* p = att + row * Lsz;
    int t = threadIdx.x;
    float v0 = p[t], v1 = p[t + 256];

    __shared__ float red[8];
    unsigned lane = t & 31, w = t >> 5;

    float m = fmaxf(v0, v1);
    #pragma unroll
    for (int o = 16; o > 0; o >>= 1) m = fmaxf(m, __shfl_xor_sync(0xffffffffu, m, o));
    if (lane == 0) red[w] = m;
    __syncthreads();
    if (t == 0) {
        float mm = red[0];
        #pragma unroll
        for (int i = 1; i < 8; i++) mm = fmaxf(mm, red[i]);
        red[0] = mm;
    }
    __syncthreads();
    m = red[0];
    __syncthreads();

    float e0 = expf(v0 - m), e1 = expf(v1 - m);
    float s = e0 + e1;
    #pragma unroll
    for (int o = 16; o > 0; o >>= 1) s += __shfl_xor_sync(0xffffffffu, s, o);
    if (lane == 0) red[w] = s;
    __syncthreads();
    if (t == 0) {
        float ss = 0.f;
        #pragma unroll
        for (int i = 0; i < 8; i++) ss += red[i];
        red[0] = ss;
    }
    __syncthreads();
    float inv = 1.0f / red[0];
    bf16 h, l;
    split1(e0 * inv, &h, &l); oh[row*Lsz + t] = h;       ol[row*Lsz + t] = l;
    split1(e1 * inv, &h, &l); oh[row*Lsz + t + 256] = h; ol[row*Lsz + t + 256] = l;
}

// ------------------------- bin smoothing + aggregate -------------------------
__global__ void smooth_k(const float* __restrict__ raw, const float* __restrict__ sm,
                         const float* __restrict__ agg, float* __restrict__ cm_out,
                         float* __restrict__ cm1)
{
    long long idx = (long long)blockIdx.x * blockDim.x + threadIdx.x;
    const long long tot = (long long)Bsz * Lsz * Lsz;
    if (idx >= tot) return;
    int b   = (int)(idx / ((long long)Lsz*Lsz));
    int rem = (int)(idx % ((long long)Lsz*Lsz));

    const float* p = raw + (long long)b * NBINS * Lsz * Lsz + rem;
    float rv[NBINS];
    #pragma unroll
    for (int n = 0; n < NBINS; n++) rv[n] = p[(long long)n * Lsz * Lsz];

    float sw[5];
    #pragma unroll
    for (int k = 0; k < 5; k++) sw[k] = sm[k];

    float* q = cm_out + (long long)b * NBINS * Lsz * Lsz + rem;
    float acc = 0.f;
    #pragma unroll
    for (int n = 0; n < NBINS; n++) {
        float v = 0.f;
        #pragma unroll
        for (int k = 0; k < 5; k++) {
            int m = n + k - 2;
            if (m >= 0 && m < NBINS) v += sw[k] * rv[m];
        }
        q[(long long)n * Lsz * Lsz] = v;
        acc += v * agg[n];
    }
    cm1[idx] = tanhf(acc);
}

// ------------------------- integral image + head -------------------------
__global__ void colsum_k(const float* __restrict__ cm1, float* __restrict__ cs)
{
    int t = blockIdx.x * blockDim.x + threadIdx.x;
    if (t >= Bsz * Lsz) return;
    int b = t / Lsz, j = t % Lsz;
    const float* src = cm1 + (long long)b * Lsz * Lsz + j;
    float* dst       = cs  + (long long)b * Lsz * Lsz + j;
    float acc = 0.f;
    for (int i = 0; i < Lsz; i++) {
        acc += src[(long long)i * Lsz];
        dst[(long long)i * Lsz] = acc;
    }
}
__global__ void rowsum_k(const float* __restrict__ cs, float* __restrict__ I)
{
    int t = blockIdx.x * blockDim.x + threadIdx.x;
    if (t >= Bsz * Lsz) return;
    int b = t / Lsz, i = t % Lsz;
    const float* src = cs + (long long)b * Lsz * Lsz + (long long)i * Lsz;
    float* row = I + (long long)b * ISZ * ISZ + (long long)(i + 1) * ISZ;
    float acc = 0.f;
    row[0] = 0.f;
    for (int j = 0; j < Lsz; j++) { acc += src[j]; row[j + 1] = acc; }
    if (i == 0) {
        float* r0 = I + (long long)b * ISZ * ISZ;
        for (int c = 0; c < ISZ; c++) r0[c] = 0.f;
    }
}
__global__ void finalize_k(const float* __restrict__ I, const float* __restrict__ Lmat,
                           const float* __restrict__ biasp, float* __restrict__ pp)
{
    int b = blockIdx.x;
    __shared__ float terms[128];
    int t = threadIdx.x;
    float val = 0.f;
    if (t < PWc * PWc) {
        int p = t / PWc, q = t % PWc;
        const float* Ib = I + (long long)b * ISZ * ISZ;
        const int Hp = Lsz - PWc + 1;   // 503
        float w = Ib[(Hp + p) * ISZ + (Hp + q)] - Ib[(Hp + p) * ISZ + q]
                - Ib[p * ISZ + (Hp + q)]       + Ib[p * ISZ + q];
        val = tanhf(w) * Lmat[t];
    }
    terms[t] = val;
    __syncthreads();
    if (t == 0) {
        float s = 0.f;
        for (int i = 0; i < PWc * PWc; i++) s += terms[i];
        pp[b] = 1.0f / (1.0f + expf(-(s + biasp[0])));
    }
}

// ------------------------- host-side -------------------------
static int STAGE_BYTES(int BN, int BK) { return (2*128 + 2*BN) * (BK*2 + 16); }

static void gemm(int BN, const bf16* Ah, const bf16* Al, const bf16* Bh, const bf16* Bl,
                 float* C, bf16* Ch, bf16* Cl,
                 int M, int N, int K, int lda, int ldb, int ldc,
                 long long sA1, long long sA2, long long sB1, long long sB2,
                 long long sC1, long long sC2, int batch1, int batch2,
                 const float* bias, int biasMode, float alpha, int act,
                 const float* Cres, int outMode)
{
    dim3 grid(N / BN, M / 128, batch1 * batch2);
    const int stages = (K > 64) ? 2 : 1;
    if (BN == 128) {
        int smem = STAGE_BYTES(128, 64) * stages;
        gemm_mma<128, 64><<<grid, 256, smem>>>(Ah, Al, Bh, Bl, C, Ch, Cl,
            K, lda, ldb, ldc, sA1, sA2, sB1, sB2, sC1, sC2, batch2,
            bias, biasMode, alpha, act, Cres, outMode);
    } else {
        int smem = STAGE_BYTES(64, 64) * stages;
        gemm_mma<64, 64><<<grid, 256, smem>>>(Ah, Al, Bh, Bl, C, Ch, Cl,
            K, lda, ldb, ldc, sA1, sA2, sB1, sB2, sC1, sC2, batch2,
            bias, biasMode, alpha, act, Cres, outMode);
    }
}

struct Ptrs {
    float *x1b, *x2b, *att, *cmraw, *cm1, *cs, *I;
    bf16 *x1ih,*x1il,*x2ih,*x2il,*wph,*wpl,*miwh,*miwl,*mowh,*mowl,*ciwh,*ciwl,*cowh,*cowl;
    bf16 *x1h,*x1l,*x2h,*x2l,*t1h,*t1l,*t2h,*t2l,*qh,*ql,*kh,*kl,*vth,*vtl,*oh,*ol;
    bf16 *atth,*attl,*wbth,*wbtl,*h1h,*h1l,*h2h,*h2l;
};

static void run_mha(const Ptrs& P,
                    const bf16* xqh, const bf16* xql,
                    const bf16* xkh, const bf16* xkl,
                    const bf16* iwh, const bf16* iwl, const float* in_b,
                    const bf16* owh, const bf16* owl, const float* out_b,
                    float* target)
{
    const int M = Bsz * Lsz;
    // Q = xq Wq^T + bq   (planes out)
    gemm(128, xqh, xql, iwh, iwl, nullptr, P.qh, P.ql,
         M, Dm, Dm, Dm, Dm, Dm, 0,0,0,0,0,0, 1,1, in_b, 1, 1.f, 0, nullptr, 2);
    // K = xkv Wk^T + bk
    gemm(128, xkh, xkl, iwh + Dm*Dm, iwl + Dm*Dm, nullptr, P.kh, P.kl,
         M, Dm, Dm, Dm, Dm, Dm, 0,0,0,0,0,0, 1,1, in_b + Dm, 1, 1.f, 0, nullptr, 2);
    // V^T = Wv xkv^T + bv (row bias) : C is (Dm, M)
    gemm(128, iwh + 2*Dm*Dm, iwl + 2*Dm*Dm, xkh, xkl, nullptr, P.vth, P.vtl,
         Dm, M, Dm, Dm, Dm, M, 0,0,0,0,0,0, 1,1, in_b + 2*Dm, 2, 1.f, 0, nullptr, 2);
    // scores = Q K^T / 8 -> fp32  (K=64 -> single stage, 3 CTAs/SM)
    gemm(128, P.qh, P.ql, P.kh, P.kl, P.att, nullptr, nullptr,
         Lsz, Lsz, DH, Dm, Dm, Lsz,
         (long long)Lsz*Dm, DH, (long long)Lsz*Dm, DH,
         (long long)Hh*Lsz*Lsz, (long long)Lsz*Lsz, Bsz, Hh,
         nullptr, 0, 0.125f, 0, nullptr, 1);
    softmax_k<<<Bsz*Hh*Lsz, 256>>>(P.att, P.atth, P.attl);
    // O = att V = att (V^T)^T  -> planes
    gemm(64, P.atth, P.attl, P.vth, P.vtl, nullptr, P.oh, P.ol,
         Lsz, DH, Lsz, Lsz, M, Dm,
         (long long)Hh*Lsz*Lsz, (long long)Lsz*Lsz,
         (long long)Lsz, (long long)DH*M,
         (long long)Lsz*Dm, (long long)DH, Bsz, Hh,
         nullptr, 0, 1.f, 0, nullptr, 2);
    // out-proj + residual -> fp32 target
    gemm(128, P.oh, P.ol, owh, owl, target, nullptr, nullptr,
         M, Dm, Dm, Dm, Dm, Dm, 0,0,0,0,0,0, 1,1, out_b, 1, 1.f, 0, target, 1);
}

extern "C" void kernel_launch(void* const* d_in, const int* in_sizes, int n_in,
                              void* d_out, int out_size)
{
    const float* x1i     = (const float*)d_in[0];
    const float* x2i     = (const float*)d_in[1];
    const float* proj_w  = (const float*)d_in[2];
    const float* proj_b  = (const float*)d_in[3];
    const float* mha_in_w  = (const float*)d_in[4];
    const float* mha_in_b  = (const float*)d_in[5];
    const float* mha_out_w = (const float*)d_in[6];
    const float* mha_out_b = (const float*)d_in[7];
    const float* ca_in_w   = (const float*)d_in[8];
    const float* ca_in_b   = (const float*)d_in[9];
    const float* ca_out_w  = (const float*)d_in[10];
    const float* ca_out_b  = (const float*)d_in[11];
    const float* Wbins   = (const float*)d_in[12];
    const float* agg     = (const float*)d_in[13];
    const float* Lmat    = (const float*)d_in[14];
    const float* biasp   = (const float*)d_in[15];
    const float* smooth  = (const float*)d_in[16];

    cudaFuncSetAttribute(gemm_mma<128,64>, cudaFuncAttributeMaxDynamicSharedMemorySize,
                         STAGE_BYTES(128,64)*2);
    cudaFuncSetAttribute(gemm_mma<64,64>,  cudaFuncAttributeMaxDynamicSharedMemorySize,
                         STAGE_BYTES(64,64)*2);

    Ptrs P;
    cudaGetSymbolAddress((void**)&P.x1b, g_x1b);   cudaGetSymbolAddress((void**)&P.x2b, g_x2b);
    cudaGetSymbolAddress((void**)&P.att, g_att);   cudaGetSymbolAddress((void**)&P.cmraw, g_cmraw);
    cudaGetSymbolAddress((void**)&P.cm1, g_cm1);   cudaGetSymbolAddress((void**)&P.cs, g_cs);
    cudaGetSymbolAddress((void**)&P.I, g_I);
    cudaGetSymbolAddress((void**)&P.x1ih, g_x1ih); cudaGetSymbolAddress((void**)&P.x1il, g_x1il);
    cudaGetSymbolAddress((void**)&P.x2ih, g_x2ih); cudaGetSymbolAddress((void**)&P.x2il, g_x2il);
    cudaGetSymbolAddress((void**)&P.wph, g_wph);   cudaGetSymbolAddress((void**)&P.wpl, g_wpl);
    cudaGetSymbolAddress((void**)&P.miwh, g_miwh); cudaGetSymbolAddress((void**)&P.miwl, g_miwl);
    cudaGetSymbolAddress((void**)&P.mowh, g_mowh); cudaGetSymbolAddress((void**)&P.mowl, g_mowl);
    cudaGetSymbolAddress((void**)&P.ciwh, g_ciwh); cudaGetSymbolAddress((void**)&P.ciwl, g_ciwl);
    cudaGetSymbolAddress((void**)&P.cowh, g_cowh); cudaGetSymbolAddress((void**)&P.cowl, g_cowl);
    cudaGetSymbolAddress((void**)&P.x1h, g_x1h);   cudaGetSymbolAddress((void**)&P.x1l, g_x1l);
    cudaGetSymbolAddress((void**)&P.x2h, g_x2h);   cudaGetSymbolAddress((void**)&P.x2l, g_x2l);
    cudaGetSymbolAddress((void**)&P.t1h, g_t1h);   cudaGetSymbolAddress((void**)&P.t1l, g_t1l);
    cudaGetSymbolAddress((void**)&P.t2h, g_t2h);   cudaGetSymbolAddress((void**)&P.t2l, g_t2l);
    cudaGetSymbolAddress((void**)&P.qh, g_qh);     cudaGetSymbolAddress((void**)&P.ql, g_ql);
    cudaGetSymbolAddress((void**)&P.kh, g_kh);     cudaGetSymbolAddress((void**)&P.kl, g_kl);
    cudaGetSymbolAddress((void**)&P.vth, g_vth);   cudaGetSymbolAddress((void**)&P.vtl, g_vtl);
    cudaGetSymbolAddress((void**)&P.oh, g_oh);     cudaGetSymbolAddress((void**)&P.ol, g_ol);
    cudaGetSymbolAddress((void**)&P.atth, g_atth); cudaGetSymbolAddress((void**)&P.attl, g_attl);
    cudaGetSymbolAddress((void**)&P.wbth, g_wbth); cudaGetSymbolAddress((void**)&P.wbtl, g_wbtl);
    cudaGetSymbolAddress((void**)&P.h1h, g_h1h);   cudaGetSymbolAddress((void**)&P.h1l, g_h1l);
    cudaGetSymbolAddress((void**)&P.h2h, g_h2h);   cudaGetSymbolAddress((void**)&P.h2l, g_h2l);

    float* out = (float*)d_out;
    float* pp_out = out + (out_size - Bsz);   // cm first, pp_prob last 8

    const int M = Bsz * Lsz;  // 4096
    const int NXD = M * Dm;

    // 0. one-time splits (weights + inputs)
    split_k<<<(M*IDIM/4 + 255)/256, 256>>>(x1i, P.x1ih, P.x1il, M*IDIM/4);
    split_k<<<(M*IDIM/4 + 255)/256, 256>>>(x2i, P.x2ih, P.x2il, M*IDIM/4);
    split_k<<<(Dm*IDIM/4 + 255)/256, 256>>>(proj_w, P.wph, P.wpl, Dm*IDIM/4);
    split_k<<<(3*Dm*Dm/4 + 255)/256, 256>>>(mha_in_w, P.miwh, P.miwl, 3*Dm*Dm/4);
    split_k<<<(Dm*Dm/4 + 255)/256, 256>>>(mha_out_w, P.mowh, P.mowl, Dm*Dm/4);
    split_k<<<(3*Dm*Dm/4 + 255)/256, 256>>>(ca_in_w, P.ciwh, P.ciwl, 3*Dm*Dm/4);
    split_k<<<(Dm*Dm/4 + 255)/256, 256>>>(ca_out_w, P.cowh, P.cowl, Dm*Dm/4);
    {
        dim3 g(HALFc/32, Dm/32, NBINS);
        transpose_split_k<<<g, dim3(32,8)>>>(Wbins, P.wbth, P.wbtl);
    }

    // 1. input projections: fp32 + planes
    gemm(128, P.x1ih, P.x1il, P.wph, P.wpl, P.x1b, P.x1h, P.x1l,
         M, Dm, IDIM, IDIM, IDIM, Dm, 0,0,0,0,0,0, 1,1, proj_b, 1, 1.f, 0, nullptr, 3);
    gemm(128, P.x2ih, P.x2il, P.wph, P.wpl, P.x2b, P.x2h, P.x2l,
         M, Dm, IDIM, IDIM, IDIM, Dm, 0,0,0,0,0,0, 1,1, proj_b, 1, 1.f, 0, nullptr, 3);

    // 2. self-attention (+residual into fp32 x)
    run_mha(P, P.x1h, P.x1l, P.x1h, P.x1l, P.miwh, P.miwl, mha_in_b,
            P.mowh, P.mowl, mha_out_b, P.x1b);
    run_mha(P, P.x2h, P.x2l, P.x2h, P.x2l, P.miwh, P.miwl, mha_in_b,
            P.mowh, P.mowl, mha_out_b, P.x2b);

    // 3. tanh -> planes for cross-attn inputs
    tanh_split_k<<<(NXD/4 + 255)/256, 256>>>(P.x1b, P.t1h, P.t1l, NXD/4);
    tanh_split_k<<<(NXD/4 + 255)/256, 256>>>(P.x2b, P.t2h, P.t2l, NXD/4);

    // 4. cross-attention (+residual into x)
    run_mha(P, P.t1h, P.t1l, P.t2h, P.t2l, P.ciwh, P.ciwl, ca_in_b,
            P.cowh, P.cowl, ca_out_b, P.x1b);
    run_mha(P, P.t2h, P.t2l, P.t1h, P.t1l, P.ciwh, P.ciwl, ca_in_b,
            P.cowh, P.cowl, ca_out_b, P.x2b);

    // 5. tanh -> planes (reuse t buffers)
    tanh_split_k<<<(NXD/4 + 255)/256, 256>>>(P.x1b, P.t1h, P.t1l, NXD/4);
    tanh_split_k<<<(NXD/4 + 255)/256, 256>>>(P.x2b, P.t2h, P.t2l, NXD/4);

    // 6. h = tanh(x @ Wbins) per bin -> planes only
    gemm(128, P.t1h, P.t1l, P.wbth, P.wbtl, nullptr, P.h1h, P.h1l,
         Lsz, HALFc, Dm, Dm, Dm, HALFc,
         (long long)Lsz*Dm, 0, 0, (long long)HALFc*Dm,
         (long long)NBINS*Lsz*HALFc, (long long)Lsz*HALFc, Bsz, NBINS,
         nullptr, 0, 1.f, 1, nullptr, 2);
    gemm(128, P.t2h, P.t2l, P.wbth, P.wbtl, nullptr, P.h2h, P.h2l,
         Lsz, HALFc, Dm, Dm, Dm, HALFc,
         (long long)Lsz*Dm, 0, 0, (long long)HALFc*Dm,
         (long long)NBINS*Lsz*HALFc, (long long)Lsz*HALFc, Bsz, NBINS,
         nullptr, 0, 1.f, 1, nullptr, 2);

    // 7. cm_raw = h1 h2^T (batch 200) -> fp32
    gemm(128, P.h1h, P.h1l, P.h2h, P.h2l, P.cmraw, nullptr, nullptr,
         Lsz, Lsz, HALFc, HALFc, HALFc, Lsz,
         (long long)Lsz*HALFc, 0, (long long)Lsz*HALFc, 0,
         (long long)Lsz*Lsz, 0, Bsz*NBINS, 1,
         nullptr, 0, 1.f, 0, nullptr, 1);

    // 8. bin smoothing -> cm (output) + cm1
    {
        long long tot = (long long)Bsz * Lsz * Lsz;
        smooth_k<<<(unsigned)((tot + 255) / 256), 256>>>(P.cmraw, smooth, agg, out, P.cm1);
    }

    // 9. integral image (rowsum fully covers I; no zero pass needed)
    colsum_k<<<(Bsz*Lsz + 255) / 256, 256>>>(P.cm1, P.cs);
    rowsum_k<<<(Bsz*Lsz + 255) / 256, 256>>>(P.cs, P.I);

    // 10. box sums + linear head + sigmoid
    finalize_k<<<Bsz, 128>>>(P.I, Lmat, biasp, pp_out);
}

// round 7
// speedup vs baseline: 2.6763x; 1.0132x over previous
#include <cuda_runtime.h>
#include <cuda_bf16.h>
#include <math.h>
#include <stdint.h>

#define Bsz 8
#define Lsz 512
#define IDIM 1024
#define Dm 512
#define Hh 8
#define DH 64
#define NBINS 25
#define PWc 10
#define HALFc 256
#define ISZ 513

#define Mrows (Bsz*Lsz)          // 4096
#define M2 (2*Mrows)             // 8192 combined

typedef __nv_bfloat16 bf16;

// ------------------------- fp32 scratch -------------------------
__device__ float g_xf [(size_t)M2*Dm];                       // residual stream (x1|x2)
__device__ float g_att[(size_t)2*Bsz*Hh*Lsz*Lsz];
__device__ float g_cmraw[(size_t)Bsz*NBINS*Lsz*Lsz];
__device__ float g_cm1[Bsz*Lsz*Lsz];
__device__ float g_cs [Bsz*Lsz*Lsz];
__device__ float g_I  [Bsz*ISZ*ISZ];

// ------------------------- bf16 hi/lo planes -------------------------
__device__ bf16 g_x1ih[Mrows*IDIM], g_x1il[Mrows*IDIM];
__device__ bf16 g_x2ih[Mrows*IDIM], g_x2il[Mrows*IDIM];
__device__ bf16 g_wph[Dm*IDIM],  g_wpl[Dm*IDIM];
__device__ bf16 g_miwh[3*Dm*Dm], g_miwl[3*Dm*Dm];
__device__ bf16 g_mowh[Dm*Dm],   g_mowl[Dm*Dm];
__device__ bf16 g_ciwh[3*Dm*Dm], g_ciwl[3*Dm*Dm];
__device__ bf16 g_cowh[Dm*Dm],   g_cowl[Dm*Dm];
__device__ bf16 g_xh[(size_t)M2*Dm], g_xl[(size_t)M2*Dm];    // x planes (x1|x2)
__device__ bf16 g_th[(size_t)M2*Dm], g_tl[(size_t)M2*Dm];    // tanh planes
__device__ bf16 g_qh[(size_t)M2*Dm], g_ql[(size_t)M2*Dm];
__device__ bf16 g_kh[(size_t)M2*Dm], g_kl[(size_t)M2*Dm];
__device__ bf16 g_vth[(size_t)Dm*M2], g_vtl[(size_t)Dm*M2]; // V^T (Dm x 2M)
__device__ bf16 g_oh[(size_t)M2*Dm], g_ol[(size_t)M2*Dm];
__device__ bf16 g_atth[(size_t)2*Bsz*Hh*Lsz*Lsz], g_attl[(size_t)2*Bsz*Hh*Lsz*Lsz];
__device__ bf16 g_wbth[NBINS*HALFc*Dm], g_wbtl[NBINS*HALFc*Dm];
__device__ bf16 g_hh[(size_t)2*Bsz*NBINS*Lsz*HALFc];         // h planes hi (h1|h2)
__device__ bf16 g_hl[(size_t)2*Bsz*NBINS*Lsz*HALFc];         // h planes lo

// ------------------------- helpers -------------------------
__device__ __forceinline__ uint32_t smem_u32(const void* p){
    uint32_t a;
    asm("{ .reg .u64 t; cvta.to.shared.u64 t, %1; cvt.u32.u64 %0, t; }" : "=r"(a) : "l"(p));
    return a;
}
__device__ __forceinline__ void cp16(uint32_t dst, const void* src){
    asm volatile("cp.async.cg.shared.global [%0], [%1], 16;" :: "r"(dst), "l"(src));
}
#define CP_COMMIT() asm volatile("cp.async.commit_group;" ::: "memory")
#define CP_WAIT(n)  asm volatile("cp.async.wait_group %0;" :: "n"(n) : "memory")

__device__ __forceinline__ uint4 ldm4(uint32_t addr){
    uint4 r;
    asm volatile("ldmatrix.sync.aligned.m8n8.x4.shared.b16 {%0,%1,%2,%3}, [%4];"
        : "=r"(r.x), "=r"(r.y), "=r"(r.z), "=r"(r.w) : "r"(addr));
    return r;
}
__device__ __forceinline__ void mma_bf16(float c[4], uint4 a, uint32_t b0, uint32_t b1){
    asm volatile("mma.sync.aligned.m16n8k16.row.col.f32.bf16.bf16.f32 "
        "{%0,%1,%2,%3}, {%4,%5,%6,%7}, {%8,%9}, {%0,%1,%2,%3};"
        : "+f"(c[0]), "+f"(c[1]), "+f"(c[2]), "+f"(c[3])
        : "r"(a.x), "r"(a.y), "r"(a.z), "r"(a.w), "r"(b0), "r"(b1));
}

// fp32 -> bf16 hi (truncate) / lo (rn of remainder)
__device__ __forceinline__ void cvt_hilo(float4 v, uint2& hi, uint2& lo){
    uint32_t ux = __float_as_uint(v.x), uy = __float_as_uint(v.y),
             uz = __float_as_uint(v.z), uw = __float_as_uint(v.w);
    float hx = __uint_as_float(ux & 0xffff0000u);
    float hy = __uint_as_float(uy & 0xffff0000u);
    float hz = __uint_as_float(uz & 0xffff0000u);
    float hw = __uint_as_float(uw & 0xffff0000u);
    asm("prmt.b32 %0, %1, %2, 0x7632;" : "=r"(hi.x) : "r"(ux), "r"(uy));
    asm("prmt.b32 %0, %1, %2, 0x7632;" : "=r"(hi.y) : "r"(uz), "r"(uw));
    float lx = v.x - hx, ly = v.y - hy, lz = v.z - hz, lw = v.w - hw;
    asm("cvt.rn.bf16x2.f32 %0, %1, %2;" : "=r"(lo.x) : "f"(ly), "f"(lx));
    asm("cvt.rn.bf16x2.f32 %0, %1, %2;" : "=r"(lo.y) : "f"(lw), "f"(lz));
}
__device__ __forceinline__ void cvt_hilo2(float v0, float v1, uint32_t& h, uint32_t& l){
    uint32_t u0 = __float_as_uint(v0), u1 = __float_as_uint(v1);
    asm("prmt.b32 %0, %1, %2, 0x7632;" : "=r"(h) : "r"(u0), "r"(u1));
    float h0 = __uint_as_float(u0 & 0xffff0000u);
    float h1 = __uint_as_float(u1 & 0xffff0000u);
    asm("cvt.rn.bf16x2.f32 %0, %1, %2;" : "=r"(l) : "f"(v1-h1), "f"(v0-h0));
}
__device__ __forceinline__ void split1(float x, bf16* h, bf16* l){
    uint32_t ux = __float_as_uint(x);
    __nv_bfloat16_raw r; r.x = (unsigned short)(ux >> 16);
    *h = r;
    float hf = __uint_as_float(ux & 0xffff0000u);
    *l = __float2bfloat16(x - hf);
}

// ------------------------- mma.sync GEMM -------------------------
// C = act(alpha * A.B^T + bias + Cres); A:(M,K), B:(N,K) bf16 hi/lo planes.
// 2xBF16 emulation: 3 products per k16-step. outMode bit0 fp32 C; bit1 planes.
// biasMode: 0 none, 1 bias[n], 2 bias[m].
template<int BN, int BK>
__global__ void __launch_bounds__(256)
gemm_mma(const bf16* __restrict__ Ah, const bf16* __restrict__ Al,
         const bf16* __restrict__ Bh, const bf16* __restrict__ Bl,
         float* __restrict__ C, bf16* __restrict__ Ch, bf16* __restrict__ Cl,
         int K, int lda, int ldb, int ldc,
         long long sA1, long long sA2, long long sB1, long long sB2,
         long long sC1, long long sC2, int batch2,
         const float* __restrict__ bias, int biasMode, float alpha, int act,
         const float* __restrict__ Cres, int outMode)
{
    constexpr int BM = 128;
    constexpr int ROWB = BK*2 + 16;
    constexpr int APL = BM * ROWB;
    constexpr int BPL = BN * ROWB;
    constexpr int STAGE = 2*APL + 2*BPL;
    constexpr int WN = BN / 2;
    constexpr int NB = WN / 8;
    constexpr int KCH = BK / 8;
    constexpr int NCHUNK = (2*BM + 2*BN) * KCH;

    extern __shared__ __align__(128) char smem[];
    const uint32_t sb = smem_u32(smem);

    const int z = blockIdx.z, z1 = z / batch2, z2 = z % batch2;
    const long long aoff = z1*sA1 + z2*sA2;
    const long long boff = z1*sB1 + z2*sB2;
    const long long coff = z1*sC1 + z2*sC2;
    Ah += aoff; Al += aoff;
    Bh += boff; Bl += boff;

    const int m0 = blockIdx.y * BM;
    const int n0 = blockIdx.x * BN;
    const int tid = threadIdx.x;
    const int wid = tid >> 5, lane = tid & 31;
    const int wm = wid >> 1, wn = wid & 1;
    const int mbase = wm * 32;
    const int nbase = wn * WN;

    float acc[2][NB][4];
    #pragma unroll
    for (int i = 0; i < 2; i++)
        #pragma unroll
        for (int j = 0; j < NB; j++)
            #pragma unroll
            for (int u = 0; u < 4; u++) acc[i][j][u] = 0.f;

    const int NC = K / BK;

    auto stage_copy = [&](int c, int s){
        const uint32_t st = sb + (uint32_t)s * STAGE;
        #pragma unroll
        for (int i = 0; i < NCHUNK/256; i++) {
            int idx = tid + i*256;
            const bf16* src; uint32_t dst;
            if (idx < 2*BM*KCH) {
                int p = idx / (BM*KCH); int rem = idx - p*BM*KCH;
                int r = rem / KCH, cc = rem % KCH;
                src = (p ? Al : Ah) + (long long)(m0+r)*lda + c*BK + cc*8;
                dst = st + p*APL + r*ROWB + cc*16;
            } else {
                int j = idx - 2*BM*KCH;
                int p = j / (BN*KCH); int rem = j - p*BN*KCH;
                int r = rem / KCH, cc = rem % KCH;
                src = (p ? Bl : Bh) + (long long)(n0+r)*ldb + c*BK + cc*8;
                dst = st + 2*APL + p*BPL + r*ROWB + cc*16;
            }
            cp16(dst, src);
        }
    };

    auto compute = [&](int s){
        const uint32_t st = sb + (uint32_t)s * STAGE;
        const uint32_t ab = st;
        const uint32_t bb = st + 2*APL;
        const int arow = mbase + (lane & 15);
        const int akoff = ((lane >> 4) & 1) * 16;
        const int brow0 = nbase + (lane & 7) + ((lane >> 4) & 1) * 8;
        const int bkoff = ((lane >> 3) & 1) * 16;
        #pragma unroll
        for (int ks = 0; ks < BK/16; ks++) {
            const int kb = ks * 32;
            uint4 a[2][2];
            #pragma unroll
            for (int p = 0; p < 2; p++)
                #pragma unroll
                for (int mb = 0; mb < 2; mb++)
                    a[p][mb] = ldm4(ab + p*APL + (arow + mb*16)*ROWB + kb + akoff);
            uint4 b[2][NB/2];
            #pragma unroll
            for (int p = 0; p < 2; p++)
                #pragma unroll
                for (int nb2 = 0; nb2 < NB/2; nb2++)
                    b[p][nb2] = ldm4(bb + p*BPL + (brow0 + nb2*16)*ROWB + kb + bkoff);
            #pragma unroll
            for (int mb = 0; mb < 2; mb++)
                #pragma unroll
                for (int nb2 = 0; nb2 < NB/2; nb2++) {
                    float* c0 = acc[mb][2*nb2];
                    float* c1 = acc[mb][2*nb2+1];
                    mma_bf16(c0, a[0][mb], b[0][nb2].x, b[0][nb2].y);
                    mma_bf16(c1, a[0][mb], b[0][nb2].z, b[0][nb2].w);
                    mma_bf16(c0, a[0][mb], b[1][nb2].x, b[1][nb2].y);
                    mma_bf16(c1, a[0][mb], b[1][nb2].z, b[1][nb2].w);
                    mma_bf16(c0, a[1][mb], b[0][nb2].x, b[0][nb2].y);
                    mma_bf16(c1, a[1][mb], b[0][nb2].z, b[0][nb2].w);
                }
        }
    };

    stage_copy(0, 0);
    CP_COMMIT();
    for (int c = 0; c < NC; c++) {
        CP_WAIT(0);
        __syncthreads();
        if (c + 1 < NC) { stage_copy(c + 1, (c + 1) & 1); CP_COMMIT(); }
        compute(c & 1);
    }

    const int g = lane >> 2, t = lane & 3;
    #pragma unroll
    for (int mb = 0; mb < 2; mb++) {
        #pragma unroll
        for (int half = 0; half < 2; half++) {
            const int row = m0 + mbase + mb*16 + g + half*8;
            const long long rowo = coff + (long long)row * ldc;
            float brow = (biasMode == 2) ? bias[row] : 0.f;
            #pragma unroll
            for (int nb = 0; nb < NB; nb++) {
                const int col = n0 + nbase + nb*8 + 2*t;
                float v0 = acc[mb][nb][half*2+0] * alpha;
                float v1 = acc[mb][nb][half*2+1] * alpha;
                if (biasMode == 1) {
                    float2 bb = *reinterpret_cast<const float2*>(&bias[col]);
                    v0 += bb.x; v1 += bb.y;
                } else if (biasMode == 2) {
                    v0 += brow; v1 += brow;
                }
                if (Cres) {
                    float2 rr = *reinterpret_cast<const float2*>(&Cres[rowo + col]);
                    v0 += rr.x; v1 += rr.y;
                }
                if (act) { v0 = tanhf(v0); v1 = tanhf(v1); }
                if (outMode & 1)
                    *reinterpret_cast<float2*>(&C[rowo + col]) = make_float2(v0, v1);
                if (outMode & 2) {
                    uint32_t h, l;
                    cvt_hilo2(v0, v1, h, l);
                    *reinterpret_cast<uint32_t*>(&Ch[rowo + col]) = h;
                    *reinterpret_cast<uint32_t*>(&Cl[rowo + col]) = l;
                }
            }
        }
    }
}

// ------------------------- converts -------------------------
__global__ void split_k(const float* __restrict__ in, bf16* __restrict__ oh,
                        bf16* __restrict__ ol, int n4)
{
    int i = blockIdx.x * blockDim.x + threadIdx.x;
    if (i >= n4) return;
    float4 v = reinterpret_cast<const float4*>(in)[i];
    uint2 h, l; cvt_hilo(v, h, l);
    reinterpret_cast<uint2*>(oh)[i] = h;
    reinterpret_cast<uint2*>(ol)[i] = l;
}
__global__ void tanh_split_k(const float* __restrict__ in, bf16* __restrict__ oh,
                             bf16* __restrict__ ol, int n4)
{
    int i = blockIdx.x * blockDim.x + threadIdx.x;
    if (i >= n4) return;
    float4 v = reinterpret_cast<const float4*>(in)[i];
    v.x = tanhf(v.x); v.y = tanhf(v.y); v.z = tanhf(v.z); v.w = tanhf(v.w);
    uint2 h, l; cvt_hilo(v, h, l);
    reinterpret_cast<uint2*>(oh)[i] = h;
    reinterpret_cast<uint2*>(ol)[i] = l;
}
// Wbins (n, d=512, k=256) -> planes (n, k=256, d=512)
__global__ void transpose_split_k(const float* __restrict__ in,
                                  bf16* __restrict__ oh, bf16* __restrict__ ol)
{
    __shared__ float tile[32][33];
    int n = blockIdx.z;
    int k0 = blockIdx.x * 32, d0 = blockIdx.y * 32;
    in += (size_t)n * Dm * HALFc;
    oh += (size_t)n * HALFc * Dm;
    ol += (size_t)n * HALFc * Dm;
    int tx = threadIdx.x, ty = threadIdx.y;
    #pragma unroll
    for (int i = ty; i < 32; i += 8)
        tile[i][tx] = in[(d0 + i) * HALFc + k0 + tx];
    __syncthreads();
    #pragma unroll
    for (int i = ty; i < 32; i += 8) {
        bf16 h, l; split1(tile[tx][i], &h, &l);
        oh[(k0 + i) * Dm + d0 + tx] = h;
        ol[(k0 + i) * Dm + d0 + tx] = l;
    }
}

// ------------------------- softmax (rows of 512) -> bf16 planes -------------------------
__global__ void softmax_k(const float* __restrict__ att,
                          bf16* __restrict__ oh, bf16* __restrict__ ol)
{
    long long row = blockIdx.x;
    const float* p = att + row * Lsz;
    int t = threadIdx.x;
    float v0 = p[t], v1 = p[t + 256];

    __shared__ float red[8];
    unsigned lane = t & 31, w = t >> 5;

    float m = fmaxf(v0, v1);
    #pragma unroll
    for (int o = 16; o > 0; o >>= 1) m = fmaxf(m, __shfl_xor_sync(0xffffffffu, m, o));
    if (lane == 0) red[w] = m;
    __syncthreads();
    if (t == 0) {
        float mm = red[0];
        #pragma unroll
        for (int i = 1; i < 8; i++) mm = fmaxf(mm, red[i]);
        red[0] = mm;
    }
    __syncthreads();
    m = red[0];
    __syncthreads();

    float e0 = expf(v0 - m), e1 = expf(v1 - m);
    float s = e0 + e1;
    #pragma unroll
    for (int o = 16; o > 0; o >>= 1) s += __shfl_xor_sync(0xffffffffu, s, o);
    if (lane == 0) red[w] = s;
    __syncthreads();
    if (t == 0) {
        float ss = 0.f;
        #pragma unroll
        for (int i = 0; i < 8; i++) ss += red[i];
        red[0] = ss;
    }
    __syncthreads();
    float inv = 1.0f / red[0];
    bf16 h, l;
    split1(e0 * inv, &h, &l); oh[row*Lsz + t] = h;       ol[row*Lsz + t] = l;
    split1(e1 * inv, &h, &l); oh[row*Lsz + t + 256] = h; ol[row*Lsz + t + 256] = l;
}

// ------------------------- bin smoothing + aggregate -------------------------
__global__ void smooth_k(const float* __restrict__ raw, const float* __restrict__ sm,
                         const float* __restrict__ agg, float* __restrict__ cm_out,
                         float* __restrict__ cm1)
{
    long long idx = (long long)blockIdx.x * blockDim.x + threadIdx.x;
    const long long tot = (long long)Bsz * Lsz * Lsz;
    if (idx >= tot) return;
    int b   = (int)(idx / ((long long)Lsz*Lsz));
    int rem = (int)(idx % ((long long)Lsz*Lsz));

    const float* p = raw + (long long)b * NBINS * Lsz * Lsz + rem;
    float rv[NBINS];
    #pragma unroll
    for (int n = 0; n < NBINS; n++) rv[n] = p[(long long)n * Lsz * Lsz];

    float sw[5];
    #pragma unroll
    for (int k = 0; k < 5; k++) sw[k] = sm[k];

    float* q = cm_out + (long long)b * NBINS * Lsz * Lsz + rem;
    float acc = 0.f;
    #pragma unroll
    for (int n = 0; n < NBINS; n++) {
        float v = 0.f;
        #pragma unroll
        for (int k = 0; k < 5; k++) {
            int m = n + k - 2;
            if (m >= 0 && m < NBINS) v += sw[k] * rv[m];
        }
        q[(long long)n * Lsz * Lsz] = v;
        acc += v * agg[n];
    }
    cm1[idx] = tanhf(acc);
}

// ------------------------- integral image + head -------------------------
__global__ void colsum_k(const float* __restrict__ cm1, float* __restrict__ cs)
{
    int t = blockIdx.x * blockDim.x + threadIdx.x;
    if (t >= Bsz * Lsz) return;
    int b = t / Lsz, j = t % Lsz;
    const float* src = cm1 + (long long)b * Lsz * Lsz + j;
    float* dst       = cs  + (long long)b * Lsz * Lsz + j;
    float acc = 0.f;
    for (int i = 0; i < Lsz; i++) {
        acc += src[(long long)i * Lsz];
        dst[(long long)i * Lsz] = acc;
    }
}
__global__ void rowsum_k(const float* __restrict__ cs, float* __restrict__ I)
{
    int t = blockIdx.x * blockDim.x + threadIdx.x;
    if (t >= Bsz * Lsz) return;
    int b = t / Lsz, i = t % Lsz;
    const float* src = cs + (long long)b * Lsz * Lsz + (long long)i * Lsz;
    float* row = I + (long long)b * ISZ * ISZ + (long long)(i + 1) * ISZ;
    float acc = 0.f;
    row[0] = 0.f;
    for (int j = 0; j < Lsz; j++) { acc += src[j]; row[j + 1] = acc; }
    if (i == 0) {
        float* r0 = I + (long long)b * ISZ * ISZ;
        for (int c = 0; c < ISZ; c++) r0[c] = 0.f;
    }
}
__global__ void finalize_k(const float* __restrict__ I, const float* __restrict__ Lmat,
                           const float* __restrict__ biasp, float* __restrict__ pp)
{
    int b = blockIdx.x;
    __shared__ float terms[128];
    int t = threadIdx.x;
    float val = 0.f;
    if (t < PWc * PWc) {
        int p = t / PWc, q = t % PWc;
        const float* Ib = I + (long long)b * ISZ * ISZ;
        const int Hp = Lsz - PWc + 1;   // 503
        float w = Ib[(Hp + p) * ISZ + (Hp + q)] - Ib[(Hp + p) * ISZ + q]
                - Ib[p * ISZ + (Hp + q)]       + Ib[p * ISZ + q];
        val = tanhf(w) * Lmat[t];
    }
    terms[t] = val;
    __syncthreads();
    if (t == 0) {
        float s = 0.f;
        for (int i = 0; i < PWc * PWc; i++) s += terms[i];
        pp[b] = 1.0f / (1.0f + expf(-(s + biasp[0])));
    }
}

// ------------------------- host-side -------------------------
static int STAGE_BYTES(int BN, int BK) { return (2*128 + 2*BN) * (BK*2 + 16); }

static void gemm(int BN, const bf16* Ah, const bf16* Al, const bf16* Bh, const bf16* Bl,
                 float* C, bf16* Ch, bf16* Cl,
                 int M, int N, int K, int lda, int ldb, int ldc,
                 long long sA1, long long sA2, long long sB1, long long sB2,
                 long long sC1, long long sC2, int batch1, int batch2,
                 const float* bias, int biasMode, float alpha, int act,
                 const float* Cres, int outMode)
{
    dim3 grid(N / BN, M / 128, batch1 * batch2);
    const int stages = (K > 64) ? 2 : 1;
    if (BN == 128) {
        int smem = STAGE_BYTES(128, 64) * stages;
        gemm_mma<128, 64><<<grid, 256, smem>>>(Ah, Al, Bh, Bl, C, Ch, Cl,
            K, lda, ldb, ldc, sA1, sA2, sB1, sB2, sC1, sC2, batch2,
            bias, biasMode, alpha, act, Cres, outMode);
    } else {
        int smem = STAGE_BYTES(64, 64) * stages;
        gemm_mma<64, 64><<<grid, 256, smem>>>(Ah, Al, Bh, Bl, C, Ch, Cl,
            K, lda, ldb, ldc, sA1, sA2, sB1, sB2, sC1, sC2, batch2,
            bias, biasMode, alpha, act, Cres, outMode);
    }
}

struct Ptrs {
    float *xf, *att, *cmraw, *cm1, *cs, *I;
    bf16 *x1ih,*x1il,*x2ih,*x2il,*wph,*wpl,*miwh,*miwl,*mowh,*mowl,*ciwh,*ciwl,*cowh,*cowl;
    bf16 *xh,*xl,*th,*tl,*qh,*ql,*kh,*kl,*vth,*vtl,*oh,*ol;
    bf16 *atth,*attl,*wbth,*wbtl,*hh,*hl;
};

// Combined MHA over both sides (x1 rows [0,M), x2 rows [M,2M)).
// qsrc: query planes (combined). kvsrc: key/value source planes (combined).
// swapKV: cross-attention (side s attends to other side's kv).
static void run_mha(const Ptrs& P,
                    const bf16* qsh, const bf16* qsl,
                    const bf16* kvh, const bf16* kvl,
                    const bf16* iwh, const bf16* iwl, const float* in_b,
                    const bf16* owh, const bf16* owl, const float* out_b,
                    float* target, bool swapKV)
{
    const long long MD = (long long)Mrows * Dm;
    // Q = qsrc Wq^T + bq  (combined, M=8192)
    gemm(128, qsh, qsl, iwh, iwl, nullptr, P.qh, P.ql,
         M2, Dm, Dm, Dm, Dm, Dm, 0,0,0,0,0,0, 1,1, in_b, 1, 1.f, 0, nullptr, 2);
    if (!swapKV) {
        // K combined, V^T combined
        gemm(128, kvh, kvl, iwh + Dm*Dm, iwl + Dm*Dm, nullptr, P.kh, P.kl,
             M2, Dm, Dm, Dm, Dm, Dm, 0,0,0,0,0,0, 1,1, in_b + Dm, 1, 1.f, 0, nullptr, 2);
        gemm(128, iwh + 2*Dm*Dm, iwl + 2*Dm*Dm, kvh, kvl, nullptr, P.vth, P.vtl,
             Dm, M2, Dm, Dm, Dm, M2, 0,0,0,0,0,0, 1,1, in_b + 2*Dm, 2, 1.f, 0, nullptr, 2);
    } else {
        // swapped: K rows for side s come from other side's kv source.
        // batch z1 in {0,1}: A = kv + z1*MD ; C = (k + MD) + z1*(-MD)
        gemm(128, kvh, kvl, iwh + Dm*Dm, iwl + Dm*Dm, nullptr, P.kh + MD, P.kl + MD,
             Mrows, Dm, Dm, Dm, Dm, Dm,
             MD, 0, 0, 0, -MD, 0, 2, 1, in_b + Dm, 1, 1.f, 0, nullptr, 2);
        // V^T swapped: B = kv + z1*MD ; C col offset M - z1*M
        gemm(128, iwh + 2*Dm*Dm, iwl + 2*Dm*Dm, kvh, kvl, nullptr, P.vth + Mrows, P.vtl + Mrows,
             Dm, Mrows, Dm, Dm, Dm, M2,
             0, 0, MD, 0, -(long long)Mrows, 0, 2, 1, in_b + 2*Dm, 2, 1.f, 0, nullptr, 2);
    }
    // scores = Q K^T / 8 -> fp32 ; batch1 = 16 (s,b), batch2 = 8 (h)
    gemm(128, P.qh, P.ql, P.kh, P.kl, P.att, nullptr, nullptr,
         Lsz, Lsz, DH, Dm, Dm, Lsz,
         (long long)Lsz*Dm, DH, (long long)Lsz*Dm, DH,
         (long long)Hh*Lsz*Lsz, (long long)Lsz*Lsz, 2*Bsz, Hh,
         nullptr, 0, 0.125f, 0, nullptr, 1);
    softmax_k<<<2*Bsz*Hh*Lsz, 256>>>(P.att, P.atth, P.attl);
    // O = att (V^T)^T ; B ldb = 2M, col offset (8s+b)*Lsz = z1*Lsz, row offset h*DH
    gemm(64, P.atth, P.attl, P.vth, P.vtl, nullptr, P.oh, P.ol,
         Lsz, DH, Lsz, Lsz, M2, Dm,
         (long long)Hh*Lsz*Lsz, (long long)Lsz*Lsz,
         (long long)Lsz, (long long)DH*M2,
         (long long)Lsz*Dm, (long long)DH, 2*Bsz, Hh,
         nullptr, 0, 1.f, 0, nullptr, 2);
    // out-proj + residual -> fp32 target (combined)
    gemm(128, P.oh, P.ol, owh, owl, target, nullptr, nullptr,
         M2, Dm, Dm, Dm, Dm, Dm, 0,0,0,0,0,0, 1,1, out_b, 1, 1.f, 0, target, 1);
}

extern "C" void kernel_launch(void* const* d_in, const int* in_sizes, int n_in,
                              void* d_out, int out_size)
{
    const float* x1i     = (const float*)d_in[0];
    const float* x2i     = (const float*)d_in[1];
    const float* proj_w  = (const float*)d_in[2];
    const float* proj_b  = (const float*)d_in[3];
    const float* mha_in_w  = (const float*)d_in[4];
    const float* mha_in_b  = (const float*)d_in[5];
    const float* mha_out_w = (const float*)d_in[6];
    const float* mha_out_b = (const float*)d_in[7];
    const float* ca_in_w   = (const float*)d_in[8];
    const float* ca_in_b   = (const float*)d_in[9];
    const float* ca_out_w  = (const float*)d_in[10];
    const float* ca_out_b  = (const float*)d_in[11];
    const float* Wbins   = (const float*)d_in[12];
    const float* agg     = (const float*)d_in[13];
    const float* Lmat    = (const float*)d_in[14];
    const float* biasp   = (const float*)d_in[15];
    const float* smooth  = (const float*)d_in[16];

    cudaFuncSetAttribute(gemm_mma<128,64>, cudaFuncAttributeMaxDynamicSharedMemorySize,
                         STAGE_BYTES(128,64)*2);
    cudaFuncSetAttribute(gemm_mma<64,64>,  cudaFuncAttributeMaxDynamicSharedMemorySize,
                         STAGE_BYTES(64,64)*2);

    Ptrs P;
    cudaGetSymbolAddress((void**)&P.xf, g_xf);
    cudaGetSymbolAddress((void**)&P.att, g_att);   cudaGetSymbolAddress((void**)&P.cmraw, g_cmraw);
    cudaGetSymbolAddress((void**)&P.cm1, g_cm1);   cudaGetSymbolAddress((void**)&P.cs, g_cs);
    cudaGetSymbolAddress((void**)&P.I, g_I);
    cudaGetSymbolAddress((void**)&P.x1ih, g_x1ih); cudaGetSymbolAddress((void**)&P.x1il, g_x1il);
    cudaGetSymbolAddress((void**)&P.x2ih, g_x2ih); cudaGetSymbolAddress((void**)&P.x2il, g_x2il);
    cudaGetSymbolAddress((void**)&P.wph, g_wph);   cudaGetSymbolAddress((void**)&P.wpl, g_wpl);
    cudaGetSymbolAddress((void**)&P.miwh, g_miwh); cudaGetSymbolAddress((void**)&P.miwl, g_miwl);
    cudaGetSymbolAddress((void**)&P.mowh, g_mowh); cudaGetSymbolAddress((void**)&P.mowl, g_mowl);
    cudaGetSymbolAddress((void**)&P.ciwh, g_ciwh); cudaGetSymbolAddress((void**)&P.ciwl, g_ciwl);
    cudaGetSymbolAddress((void**)&P.cowh, g_cowh); cudaGetSymbolAddress((void**)&P.cowl, g_cowl);
    cudaGetSymbolAddress((void**)&P.xh, g_xh);     cudaGetSymbolAddress((void**)&P.xl, g_xl);
    cudaGetSymbolAddress((void**)&P.th, g_th);     cudaGetSymbolAddress((void**)&P.tl, g_tl);
    cudaGetSymbolAddress((void**)&P.qh, g_qh);     cudaGetSymbolAddress((void**)&P.ql, g_ql);
    cudaGetSymbolAddress((void**)&P.kh, g_kh);     cudaGetSymbolAddress((void**)&P.kl, g_kl);
    cudaGetSymbolAddress((void**)&P.vth, g_vth);   cudaGetSymbolAddress((void**)&P.vtl, g_vtl);
    cudaGetSymbolAddress((void**)&P.oh, g_oh);     cudaGetSymbolAddress((void**)&P.ol, g_ol);
    cudaGetSymbolAddress((void**)&P.atth, g_atth); cudaGetSymbolAddress((void**)&P.attl, g_attl);
    cudaGetSymbolAddress((void**)&P.wbth, g_wbth); cudaGetSymbolAddress((void**)&P.wbtl, g_wbtl);
    cudaGetSymbolAddress((void**)&P.hh, g_hh);     cudaGetSymbolAddress((void**)&P.hl, g_hl);

    float* out = (float*)d_out;
    float* pp_out = out + (out_size - Bsz);   // cm first, pp_prob last 8

    const long long MD = (long long)Mrows * Dm;
    const int NXD2 = M2 * Dm;

    // 0. one-time splits
    split_k<<<(Mrows*IDIM/4 + 255)/256, 256>>>(x1i, P.x1ih, P.x1il, Mrows*IDIM/4);
    split_k<<<(Mrows*IDIM/4 + 255)/256, 256>>>(x2i, P.x2ih, P.x2il, Mrows*IDIM/4);
    split_k<<<(Dm*IDIM/4 + 255)/256, 256>>>(proj_w, P.wph, P.wpl, Dm*IDIM/4);
    split_k<<<(3*Dm*Dm/4 + 255)/256, 256>>>(mha_in_w, P.miwh, P.miwl, 3*Dm*Dm/4);
    split_k<<<(Dm*Dm/4 + 255)/256, 256>>>(mha_out_w, P.mowh, P.mowl, Dm*Dm/4);
    split_k<<<(3*Dm*Dm/4 + 255)/256, 256>>>(ca_in_w, P.ciwh, P.ciwl, 3*Dm*Dm/4);
    split_k<<<(Dm*Dm/4 + 255)/256, 256>>>(ca_out_w, P.cowh, P.cowl, Dm*Dm/4);
    {
        dim3 g(HALFc/32, Dm/32, NBINS);
        transpose_split_k<<<g, dim3(32,8)>>>(Wbins, P.wbth, P.wbtl);
    }

    // 1. input projections into combined halves: fp32 + planes
    gemm(128, P.x1ih, P.x1il, P.wph, P.wpl, P.xf, P.xh, P.xl,
         Mrows, Dm, IDIM, IDIM, IDIM, Dm, 0,0,0,0,0,0, 1,1, proj_b, 1, 1.f, 0, nullptr, 3);
    gemm(128, P.x2ih, P.x2il, P.wph, P.wpl, P.xf + MD, P.xh + MD, P.xl + MD,
         Mrows, Dm, IDIM, IDIM, IDIM, Dm, 0,0,0,0,0,0, 1,1, proj_b, 1, 1.f, 0, nullptr, 3);

    // 2. self-attention (+residual), both sides in one pass
    run_mha(P, P.xh, P.xl, P.xh, P.xl, P.miwh, P.miwl, mha_in_b,
            P.mowh, P.mowl, mha_out_b, P.xf, false);

    // 3. tanh -> planes for cross-attn inputs (combined)
    tanh_split_k<<<(NXD2/4 + 255)/256, 256>>>(P.xf, P.th, P.tl, NXD2/4);

    // 4. cross-attention (+residual), swapped KV
    run_mha(P, P.th, P.tl, P.th, P.tl, P.ciwh, P.ciwl, ca_in_b,
            P.cowh, P.cowl, ca_out_b, P.xf, true);

    // 5. tanh -> planes (combined)
    tanh_split_k<<<(NXD2/4 + 255)/256, 256>>>(P.xf, P.th, P.tl, NXD2/4);

    // 6. h = tanh(x @ Wbins) per (side,b,bin): batch1=16, batch2=25
    gemm(128, P.th, P.tl, P.wbth, P.wbtl, nullptr, P.hh, P.hl,
         Lsz, HALFc, Dm, Dm, Dm, HALFc,
         (long long)Lsz*Dm, 0, 0, (long long)HALFc*Dm,
         (long long)NBINS*Lsz*HALFc, (long long)Lsz*HALFc, 2*Bsz, NBINS,
         nullptr, 0, 1.f, 1, nullptr, 2);

    // 7. cm_raw = h1 h2^T (batch 200): h1 = first 8 b's, h2 = last 8
    {
        const long long hhalf = (long long)Bsz*NBINS*Lsz*HALFc;
        gemm(128, P.hh, P.hl, P.hh + hhalf, P.hl + hhalf, P.cmraw, nullptr, nullptr,
             Lsz, Lsz, HALFc, HALFc, HALFc, Lsz,
             (long long)Lsz*HALFc, 0, (long long)Lsz*HALFc, 0,
             (long long)Lsz*Lsz, 0, Bsz*NBINS, 1,
             nullptr, 0, 1.f, 0, nullptr, 1);
    }

    // 8. bin smoothing -> cm (output) + cm1
    {
        long long tot = (long long)Bsz * Lsz * Lsz;
        smooth_k<<<(unsigned)((tot + 255) / 256), 256>>>(P.cmraw, smooth, agg, out, P.cm1);
    }

    // 9. integral image
    colsum_k<<<(Bsz*Lsz + 255) / 256, 256>>>(P.cm1, P.cs);
    rowsum_k<<<(Bsz*Lsz + 255) / 256, 256>>>(P.cs, P.I);

    // 10. box sums + linear head + sigmoid
    finalize_k<<<Bsz, 128>>>(P.I, Lmat, biasp, pp_out);
}

// round 8
// speedup vs baseline: 2.7774x; 1.0378x over previous
#include <cuda_runtime.h>
#include <cuda_bf16.h>
#include <math.h>
#include <stdint.h>

#define Bsz 8
#define Lsz 512
#define IDIM 1024
#define Dm 512
#define Hh 8
#define DH 64
#define NBINS 25
#define PWc 10
#define HALFc 256
#define ISZ 513

#define Mrows (Bsz*Lsz)          // 4096
#define M2 (2*Mrows)             // 8192 combined

typedef __nv_bfloat16 bf16;

// ------------------------- fp32 scratch -------------------------
__device__ float g_xf [(size_t)M2*Dm];                       // residual stream (x1|x2)
__device__ float g_att[(size_t)2*Bsz*Hh*Lsz*Lsz];
__device__ float g_cmraw[(size_t)Bsz*NBINS*Lsz*Lsz];
__device__ float g_cm1[Bsz*Lsz*Lsz];
__device__ float g_cs [Bsz*Lsz*Lsz];
__device__ float g_I  [Bsz*ISZ*ISZ];

// ------------------------- bf16 hi/lo planes -------------------------
__device__ bf16 g_x1ih[Mrows*IDIM], g_x1il[Mrows*IDIM];
__device__ bf16 g_x2ih[Mrows*IDIM], g_x2il[Mrows*IDIM];
__device__ bf16 g_wph[Dm*IDIM],  g_wpl[Dm*IDIM];
__device__ bf16 g_miwh[3*Dm*Dm], g_miwl[3*Dm*Dm];
__device__ bf16 g_mowh[Dm*Dm],   g_mowl[Dm*Dm];
__device__ bf16 g_ciwh[3*Dm*Dm], g_ciwl[3*Dm*Dm];
__device__ bf16 g_cowh[Dm*Dm],   g_cowl[Dm*Dm];
__device__ bf16 g_xh[(size_t)M2*Dm], g_xl[(size_t)M2*Dm];
__device__ bf16 g_th[(size_t)M2*Dm], g_tl[(size_t)M2*Dm];
__device__ bf16 g_qh[(size_t)M2*Dm], g_ql[(size_t)M2*Dm];
__device__ bf16 g_kh[(size_t)M2*Dm], g_kl[(size_t)M2*Dm];
__device__ bf16 g_vth[(size_t)Dm*M2], g_vtl[(size_t)Dm*M2];
__device__ bf16 g_oh[(size_t)M2*Dm], g_ol[(size_t)M2*Dm];
__device__ bf16 g_atth[(size_t)2*Bsz*Hh*Lsz*Lsz], g_attl[(size_t)2*Bsz*Hh*Lsz*Lsz];
__device__ bf16 g_wbth[NBINS*HALFc*Dm], g_wbtl[NBINS*HALFc*Dm];
__device__ bf16 g_hh[(size_t)2*Bsz*NBINS*Lsz*HALFc];
__device__ bf16 g_hl[(size_t)2*Bsz*NBINS*Lsz*HALFc];

// ------------------------- helpers -------------------------
__device__ __forceinline__ uint32_t smem_u32(const void* p){
    uint32_t a;
    asm("{ .reg .u64 t; cvta.to.shared.u64 t, %1; cvt.u32.u64 %0, t; }" : "=r"(a) : "l"(p));
    return a;
}
__device__ __forceinline__ void cp16(uint32_t dst, const void* src){
    asm volatile("cp.async.cg.shared.global [%0], [%1], 16;" :: "r"(dst), "l"(src));
}
#define CP_COMMIT() asm volatile("cp.async.commit_group;" ::: "memory")
#define CP_WAIT(n)  asm volatile("cp.async.wait_group %0;" :: "n"(n) : "memory")

__device__ __forceinline__ uint4 ldm4(uint32_t addr){
    uint4 r;
    asm volatile("ldmatrix.sync.aligned.m8n8.x4.shared.b16 {%0,%1,%2,%3}, [%4];"
        : "=r"(r.x), "=r"(r.y), "=r"(r.z), "=r"(r.w) : "r"(addr));
    return r;
}
__device__ __forceinline__ void mma_bf16(float c[4], uint4 a, uint32_t b0, uint32_t b1){
    asm volatile("mma.sync.aligned.m16n8k16.row.col.f32.bf16.bf16.f32 "
        "{%0,%1,%2,%3}, {%4,%5,%6,%7}, {%8,%9}, {%0,%1,%2,%3};"
        : "+f"(c[0]), "+f"(c[1]), "+f"(c[2]), "+f"(c[3])
        : "r"(a.x), "r"(a.y), "r"(a.z), "r"(a.w), "r"(b0), "r"(b1));
}

// fp32 -> bf16 hi (truncate) / lo (rn of remainder)
__device__ __forceinline__ void cvt_hilo(float4 v, uint2& hi, uint2& lo){
    uint32_t ux = __float_as_uint(v.x), uy = __float_as_uint(v.y),
             uz = __float_as_uint(v.z), uw = __float_as_uint(v.w);
    float hx = __uint_as_float(ux & 0xffff0000u);
    float hy = __uint_as_float(uy & 0xffff0000u);
    float hz = __uint_as_float(uz & 0xffff0000u);
    float hw = __uint_as_float(uw & 0xffff0000u);
    asm("prmt.b32 %0, %1, %2, 0x7632;" : "=r"(hi.x) : "r"(ux), "r"(uy));
    asm("prmt.b32 %0, %1, %2, 0x7632;" : "=r"(hi.y) : "r"(uz), "r"(uw));
    float lx = v.x - hx, ly = v.y - hy, lz = v.z - hz, lw = v.w - hw;
    asm("cvt.rn.bf16x2.f32 %0, %1, %2;" : "=r"(lo.x) : "f"(ly), "f"(lx));
    asm("cvt.rn.bf16x2.f32 %0, %1, %2;" : "=r"(lo.y) : "f"(lw), "f"(lz));
}
__device__ __forceinline__ void cvt_hilo2(float v0, float v1, uint32_t& h, uint32_t& l){
    uint32_t u0 = __float_as_uint(v0), u1 = __float_as_uint(v1);
    asm("prmt.b32 %0, %1, %2, 0x7632;" : "=r"(h) : "r"(u0), "r"(u1));
    float h0 = __uint_as_float(u0 & 0xffff0000u);
    float h1 = __uint_as_float(u1 & 0xffff0000u);
    asm("cvt.rn.bf16x2.f32 %0, %1, %2;" : "=r"(l) : "f"(v1-h1), "f"(v0-h0));
}
__device__ __forceinline__ void split1(float x, bf16* h, bf16* l){
    uint32_t ux = __float_as_uint(x);
    __nv_bfloat16_raw r; r.x = (unsigned short)(ux >> 16);
    *h = r;
    float hf = __uint_as_float(ux & 0xffff0000u);
    *l = __float2bfloat16(x - hf);
}

// ------------------------- mma.sync GEMM -------------------------
// C = act(alpha * A.B^T + bias + Cres); A:(M,K), B:(N,K) bf16 hi/lo planes.
// 2xBF16 emulation: hh + hl + lh. outMode bit0 fp32 C; bit1 planes.
// biasMode: 0 none, 1 bias[n], 2 bias[m].
// BM=128, BK=32, 2 stages, 2 CTAs/SM; 8 warps: 4(m) x 2(n), warp tile 32 x BN/2.
template<int BN>
__global__ void __launch_bounds__(256, 2)
gemm_mma(const bf16* __restrict__ Ah, const bf16* __restrict__ Al,
         const bf16* __restrict__ Bh, const bf16* __restrict__ Bl,
         float* __restrict__ C, bf16* __restrict__ Ch, bf16* __restrict__ Cl,
         int K, int lda, int ldb, int ldc,
         long long sA1, long long sA2, long long sB1, long long sB2,
         long long sC1, long long sC2, int batch2,
         const float* __restrict__ bias, int biasMode, float alpha, int act,
         const float* __restrict__ Cres, int outMode)
{
    constexpr int BM = 128, BK = 32;
    constexpr int ROWB = BK*2 + 16;          // 80 bytes/row, conflict-free
    constexpr int APL = BM * ROWB;
    constexpr int BPL = BN * ROWB;
    constexpr int STAGE = 2*APL + 2*BPL;
    constexpr int WN = BN / 2;
    constexpr int NB = WN / 8;
    constexpr int KCH = BK / 8;              // 4
    constexpr int NCHUNK = (2*BM + 2*BN) * KCH;

    extern __shared__ __align__(128) char smem[];
    const uint32_t sb = smem_u32(smem);

    const int z = blockIdx.z, z1 = z / batch2, z2 = z % batch2;
    const long long aoff = z1*sA1 + z2*sA2;
    const long long boff = z1*sB1 + z2*sB2;
    const long long coff = z1*sC1 + z2*sC2;
    Ah += aoff; Al += aoff;
    Bh += boff; Bl += boff;

    const int m0 = blockIdx.y * BM;
    const int n0 = blockIdx.x * BN;
    const int tid = threadIdx.x;
    const int wid = tid >> 5, lane = tid & 31;
    const int wm = wid >> 1, wn = wid & 1;
    const int mbase = wm * 32;
    const int nbase = wn * WN;

    float acc[2][NB][4];
    #pragma unroll
    for (int i = 0; i < 2; i++)
        #pragma unroll
        for (int j = 0; j < NB; j++)
            #pragma unroll
            for (int u = 0; u < 4; u++) acc[i][j][u] = 0.f;

    const int NC = K / BK;

    auto stage_copy = [&](int c, int s){
        const uint32_t st = sb + (uint32_t)s * STAGE;
        #pragma unroll
        for (int i = 0; i < NCHUNK/256; i++) {
            int idx = tid + i*256;
            const bf16* src; uint32_t dst;
            if (idx < 2*BM*KCH) {
                int p = idx / (BM*KCH); int rem = idx - p*BM*KCH;
                int r = rem >> 2, cc = rem & 3;
                src = (p ? Al : Ah) + (long long)(m0+r)*lda + c*BK + cc*8;
                dst = st + p*APL + r*ROWB + cc*16;
            } else {
                int j = idx - 2*BM*KCH;
                int p = j / (BN*KCH); int rem = j - p*BN*KCH;
                int r = rem >> 2, cc = rem & 3;
                src = (p ? Bl : Bh) + (long long)(n0+r)*ldb + c*BK + cc*8;
                dst = st + 2*APL + p*BPL + r*ROWB + cc*16;
            }
            cp16(dst, src);
        }
    };

    auto compute = [&](int s){
        const uint32_t st = sb + (uint32_t)s * STAGE;
        const uint32_t ab = st;
        const uint32_t bb = st + 2*APL;
        const int arow = mbase + (lane & 15);
        const int akoff = ((lane >> 4) & 1) * 16;
        const int brow0 = nbase + (lane & 7) + ((lane >> 4) & 1) * 8;
        const int bkoff = ((lane >> 3) & 1) * 16;
        #pragma unroll
        for (int ks = 0; ks < BK/16; ks++) {
            const int kb = ks * 32;
            uint4 a[2][2];
            #pragma unroll
            for (int p = 0; p < 2; p++)
                #pragma unroll
                for (int mb = 0; mb < 2; mb++)
                    a[p][mb] = ldm4(ab + p*APL + (arow + mb*16)*ROWB + kb + akoff);
            // per n-pair: load b (both planes), apply 6 MMAs — limits live regs
            #pragma unroll
            for (int nb2 = 0; nb2 < NB/2; nb2++) {
                uint4 b0 = ldm4(bb + (brow0 + nb2*16)*ROWB + kb + bkoff);
                uint4 b1 = ldm4(bb + BPL + (brow0 + nb2*16)*ROWB + kb + bkoff);
                #pragma unroll
                for (int mb = 0; mb < 2; mb++) {
                    float* c0 = acc[mb][2*nb2];
                    float* c1 = acc[mb][2*nb2+1];
                    mma_bf16(c0, a[0][mb], b0.x, b0.y);
                    mma_bf16(c1, a[0][mb], b0.z, b0.w);
                    mma_bf16(c0, a[0][mb], b1.x, b1.y);
                    mma_bf16(c1, a[0][mb], b1.z, b1.w);
                    mma_bf16(c0, a[1][mb], b0.x, b0.y);
                    mma_bf16(c1, a[1][mb], b0.z, b0.w);
                }
            }
        }
    };

    stage_copy(0, 0);
    CP_COMMIT();
    for (int c = 0; c < NC; c++) {
        CP_WAIT(0);
        __syncthreads();
        if (c + 1 < NC) { stage_copy(c + 1, (c + 1) & 1); CP_COMMIT(); }
        compute(c & 1);
    }

    const int g = lane >> 2, t = lane & 3;
    #pragma unroll
    for (int mb = 0; mb < 2; mb++) {
        #pragma unroll
        for (int half = 0; half < 2; half++) {
            const int row = m0 + mbase + mb*16 + g + half*8;
            const long long rowo = coff + (long long)row * ldc;
            float brow = (biasMode == 2) ? bias[row] : 0.f;
            #pragma unroll
            for (int nb = 0; nb < NB; nb++) {
                const int col = n0 + nbase + nb*8 + 2*t;
                float v0 = acc[mb][nb][half*2+0] * alpha;
                float v1 = acc[mb][nb][half*2+1] * alpha;
                if (biasMode == 1) {
                    float2 bb = *reinterpret_cast<const float2*>(&bias[col]);
                    v0 += bb.x; v1 += bb.y;
                } else if (biasMode == 2) {
                    v0 += brow; v1 += brow;
                }
                if (Cres) {
                    float2 rr = *reinterpret_cast<const float2*>(&Cres[rowo + col]);
                    v0 += rr.x; v1 += rr.y;
                }
                if (act) { v0 = tanhf(v0); v1 = tanhf(v1); }
                if (outMode & 1)
                    *reinterpret_cast<float2*>(&C[rowo + col]) = make_float2(v0, v1);
                if (outMode & 2) {
                    uint32_t h, l;
                    cvt_hilo2(v0, v1, h, l);
                    *reinterpret_cast<uint32_t*>(&Ch[rowo + col]) = h;
                    *reinterpret_cast<uint32_t*>(&Cl[rowo + col]) = l;
                }
            }
        }
    }
}

// ------------------------- converts -------------------------
__global__ void split_k(const float* __restrict__ in, bf16* __restrict__ oh,
                        bf16* __restrict__ ol, int n4)
{
    int i = blockIdx.x * blockDim.x + threadIdx.x;
    if (i >= n4) return;
    float4 v = reinterpret_cast<const float4*>(in)[i];
    uint2 h, l; cvt_hilo(v, h, l);
    reinterpret_cast<uint2*>(oh)[i] = h;
    reinterpret_cast<uint2*>(ol)[i] = l;
}
__global__ void tanh_split_k(const float* __restrict__ in, bf16* __restrict__ oh,
                             bf16* __restrict__ ol, int n4)
{
    int i = blockIdx.x * blockDim.x + threadIdx.x;
    if (i >= n4) return;
    float4 v = reinterpret_cast<const float4*>(in)[i];
    v.x = tanhf(v.x); v.y = tanhf(v.y); v.z = tanhf(v.z); v.w = tanhf(v.w);
    uint2 h, l; cvt_hilo(v, h, l);
    reinterpret_cast<uint2*>(oh)[i] = h;
    reinterpret_cast<uint2*>(ol)[i] = l;
}
// Wbins (n, d=512, k=256) -> planes (n, k=256, d=512)
__global__ void transpose_split_k(const float* __restrict__ in,
                                  bf16* __restrict__ oh, bf16* __restrict__ ol)
{
    __shared__ float tile[32][33];
    int n = blockIdx.z;
    int k0 = blockIdx.x * 32, d0 = blockIdx.y * 32;
    in += (size_t)n * Dm * HALFc;
    oh += (size_t)n * HALFc * Dm;
    ol += (size_t)n * HALFc * Dm;
    int tx = threadIdx.x, ty = threadIdx.y;
    #pragma unroll
    for (int i = ty; i < 32; i += 8)
        tile[i][tx] = in[(d0 + i) * HALFc + k0 + tx];
    __syncthreads();
    #pragma unroll
    for (int i = ty; i < 32; i += 8) {
        bf16 h, l; split1(tile[tx][i], &h, &l);
        oh[(k0 + i) * Dm + d0 + tx] = h;
        ol[(k0 + i) * Dm + d0 + tx] = l;
    }
}

// ------------------------- softmax (rows of 512) -> bf16 planes -------------------------
__global__ void softmax_k(const float* __restrict__ att,
                          bf16* __restrict__ oh, bf16* __restrict__ ol)
{
    long long row = blockIdx.x;
    const float* p = att + row * Lsz;
    int t = threadIdx.x;
    float v0 = p[t], v1 = p[t + 256];

    __shared__ float red[8];
    unsigned lane = t & 31, w = t >> 5;

    float m = fmaxf(v0, v1);
    #pragma unroll
    for (int o = 16; o > 0; o >>= 1) m = fmaxf(m, __shfl_xor_sync(0xffffffffu, m, o));
    if (lane == 0) red[w] = m;
    __syncthreads();
    if (t == 0) {
        float mm = red[0];
        #pragma unroll
        for (int i = 1; i < 8; i++) mm = fmaxf(mm, red[i]);
        red[0] = mm;
    }
    __syncthreads();
    m = red[0];
    __syncthreads();

    float e0 = expf(v0 - m), e1 = expf(v1 - m);
    float s = e0 + e1;
    #pragma unroll
    for (int o = 16; o > 0; o >>= 1) s += __shfl_xor_sync(0xffffffffu, s, o);
    if (lane == 0) red[w] = s;
    __syncthreads();
    if (t == 0) {
        float ss = 0.f;
        #pragma unroll
        for (int i = 0; i < 8; i++) ss += red[i];
        red[0] = ss;
    }
    __syncthreads();
    float inv = 1.0f / red[0];
    bf16 h, l;
    split1(e0 * inv, &h, &l); oh[row*Lsz + t] = h;       ol[row*Lsz + t] = l;
    split1(e1 * inv, &h, &l); oh[row*Lsz + t + 256] = h; ol[row*Lsz + t + 256] = l;
}

// ------------------------- bin smoothing + aggregate -------------------------
__global__ void smooth_k(const float* __restrict__ raw, const float* __restrict__ sm,
                         const float* __restrict__ agg, float* __restrict__ cm_out,
                         float* __restrict__ cm1)
{
    long long idx = (long long)blockIdx.x * blockDim.x + threadIdx.x;
    const long long tot = (long long)Bsz * Lsz * Lsz;
    if (idx >= tot) return;
    int b   = (int)(idx / ((long long)Lsz*Lsz));
    int rem = (int)(idx % ((long long)Lsz*Lsz));

    const float* p = raw + (long long)b * NBINS * Lsz * Lsz + rem;
    float rv[NBINS];
    #pragma unroll
    for (int n = 0; n < NBINS; n++) rv[n] = p[(long long)n * Lsz * Lsz];

    float sw[5];
    #pragma unroll
    for (int k = 0; k < 5; k++) sw[k] = sm[k];

    float* q = cm_out + (long long)b * NBINS * Lsz * Lsz + rem;
    float acc = 0.f;
    #pragma unroll
    for (int n = 0; n < NBINS; n++) {
        float v = 0.f;
        #pragma unroll
        for (int k = 0; k < 5; k++) {
            int m = n + k - 2;
            if (m >= 0 && m < NBINS) v += sw[k] * rv[m];
        }
        q[(long long)n * Lsz * Lsz] = v;
        acc += v * agg[n];
    }
    cm1[idx] = tanhf(acc);
}

// ------------------------- integral image + head -------------------------
__global__ void colsum_k(const float* __restrict__ cm1, float* __restrict__ cs)
{
    int t = blockIdx.x * blockDim.x + threadIdx.x;
    if (t >= Bsz * Lsz) return;
    int b = t / Lsz, j = t % Lsz;
    const float* src = cm1 + (long long)b * Lsz * Lsz + j;
    float* dst       = cs  + (long long)b * Lsz * Lsz + j;
    float acc = 0.f;
    for (int i = 0; i < Lsz; i++) {
        acc += src[(long long)i * Lsz];
        dst[(long long)i * Lsz] = acc;
    }
}
__global__ void rowsum_k(const float* __restrict__ cs, float* __restrict__ I)
{
    int t = blockIdx.x * blockDim.x + threadIdx.x;
    if (t >= Bsz * Lsz) return;
    int b = t / Lsz, i = t % Lsz;
    const float* src = cs + (long long)b * Lsz * Lsz + (long long)i * Lsz;
    float* row = I + (long long)b * ISZ * ISZ + (long long)(i + 1) * ISZ;
    float acc = 0.f;
    row[0] = 0.f;
    for (int j = 0; j < Lsz; j++) { acc += src[j]; row[j + 1] = acc; }
    if (i == 0) {
        float* r0 = I + (long long)b * ISZ * ISZ;
        for (int c = 0; c < ISZ; c++) r0[c] = 0.f;
    }
}
__global__ void finalize_k(const float* __restrict__ I, const float* __restrict__ Lmat,
                           const float* __restrict__ biasp, float* __restrict__ pp)
{
    int b = blockIdx.x;
    __shared__ float terms[128];
    int t = threadIdx.x;
    float val = 0.f;
    if (t < PWc * PWc) {
        int p = t / PWc, q = t % PWc;
        const float* Ib = I + (long long)b * ISZ * ISZ;
        const int Hp = Lsz - PWc + 1;   // 503
        float w = Ib[(Hp + p) * ISZ + (Hp + q)] - Ib[(Hp + p) * ISZ + q]
                - Ib[p * ISZ + (Hp + q)]       + Ib[p * ISZ + q];
        val = tanhf(w) * Lmat[t];
    }
    terms[t] = val;
    __syncthreads();
    if (t == 0) {
        float s = 0.f;
        for (int i = 0; i < PWc * PWc; i++) s += terms[i];
        pp[b] = 1.0f / (1.0f + expf(-(s + biasp[0])));
    }
}

// ------------------------- host-side -------------------------
static int SMEM_TOTAL_BYTES(int BN) { return 2 * (2*128 + 2*BN) * (32*2 + 16); } // 2 stages, BK=32

static void gemm(int BN, const bf16* Ah, const bf16* Al, const bf16* Bh, const bf16* Bl,
                 float* C, bf16* Ch, bf16* Cl,
                 int M, int N, int K, int lda, int ldb, int ldc,
                 long long sA1, long long sA2, long long sB1, long long sB2,
                 long long sC1, long long sC2, int batch1, int batch2,
                 const float* bias, int biasMode, float alpha, int act,
                 const float* Cres, int outMode)
{
    dim3 grid(N / BN, M / 128, batch1 * batch2);
    if (BN == 128)
        gemm_mma<128><<<grid, 256, SMEM_TOTAL_BYTES(128)>>>(Ah, Al, Bh, Bl, C, Ch, Cl,
            K, lda, ldb, ldc, sA1, sA2, sB1, sB2, sC1, sC2, batch2,
            bias, biasMode, alpha, act, Cres, outMode);
    else
        gemm_mma<64><<<grid, 256, SMEM_TOTAL_BYTES(64)>>>(Ah, Al, Bh, Bl, C, Ch, Cl,
            K, lda, ldb, ldc, sA1, sA2, sB1, sB2, sC1, sC2, batch2,
            bias, biasMode, alpha, act, Cres, outMode);
}

struct Ptrs {
    float *xf, *att, *cmraw, *cm1, *cs, *I;
    bf16 *x1ih,*x1il,*x2ih,*x2il,*wph,*wpl,*miwh,*miwl,*mowh,*mowl,*ciwh,*ciwl,*cowh,*cowl;
    bf16 *xh,*xl,*th,*tl,*qh,*ql,*kh,*kl,*vth,*vtl,*oh,*ol;
    bf16 *atth,*attl,*wbth,*wbtl,*hh,*hl;
};

static void run_mha(const Ptrs& P,
                    const bf16* qsh, const bf16* qsl,
                    const bf16* kvh, const bf16* kvl,
                    const bf16* iwh, const bf16* iwl, const float* in_b,
                    const bf16* owh, const bf16* owl, const float* out_b,
                    float* target, bool swapKV)
{
    const long long MD = (long long)Mrows * Dm;
    gemm(128, qsh, qsl, iwh, iwl, nullptr, P.qh, P.ql,
         M2, Dm, Dm, Dm, Dm, Dm, 0,0,0,0,0,0, 1,1, in_b, 1, 1.f, 0, nullptr, 2);
    if (!swapKV) {
        gemm(128, kvh, kvl, iwh + Dm*Dm, iwl + Dm*Dm, nullptr, P.kh, P.kl,
             M2, Dm, Dm, Dm, Dm, Dm, 0,0,0,0,0,0, 1,1, in_b + Dm, 1, 1.f, 0, nullptr, 2);
        gemm(128, iwh + 2*Dm*Dm, iwl + 2*Dm*Dm, kvh, kvl, nullptr, P.vth, P.vtl,
             Dm, M2, Dm, Dm, Dm, M2, 0,0,0,0,0,0, 1,1, in_b + 2*Dm, 2, 1.f, 0, nullptr, 2);
    } else {
        gemm(128, kvh, kvl, iwh + Dm*Dm, iwl + Dm*Dm, nullptr, P.kh + MD, P.kl + MD,
             Mrows, Dm, Dm, Dm, Dm, Dm,
             MD, 0, 0, 0, -MD, 0, 2, 1, in_b + Dm, 1, 1.f, 0, nullptr, 2);
        gemm(128, iwh + 2*Dm*Dm, iwl + 2*Dm*Dm, kvh, kvl, nullptr, P.vth + Mrows, P.vtl + Mrows,
             Dm, Mrows, Dm, Dm, Dm, M2,
             0, 0, MD, 0, -(long long)Mrows, 0, 2, 1, in_b + 2*Dm, 2, 1.f, 0, nullptr, 2);
    }
    gemm(128, P.qh, P.ql, P.kh, P.kl, P.att, nullptr, nullptr,
         Lsz, Lsz, DH, Dm, Dm, Lsz,
         (long long)Lsz*Dm, DH, (long long)Lsz*Dm, DH,
         (long long)Hh*Lsz*Lsz, (long long)Lsz*Lsz, 2*Bsz, Hh,
         nullptr, 0, 0.125f, 0, nullptr, 1);
    softmax_k<<<2*Bsz*Hh*Lsz, 256>>>(P.att, P.atth, P.attl);
    gemm(64, P.atth, P.attl, P.vth, P.vtl, nullptr, P.oh, P.ol,
         Lsz, DH, Lsz, Lsz, M2, Dm,
         (long long)Hh*Lsz*Lsz, (long long)Lsz*Lsz,
         (long long)Lsz, (long long)DH*M2,
         (long long)Lsz*Dm, (long long)DH, 2*Bsz, Hh,
         nullptr, 0, 1.f, 0, nullptr, 2);
    gemm(128, P.oh, P.ol, owh, owl, target, nullptr, nullptr,
         M2, Dm, Dm, Dm, Dm, Dm, 0,0,0,0,0,0, 1,1, out_b, 1, 1.f, 0, target, 1);
}

extern "C" void kernel_launch(void* const* d_in, const int* in_sizes, int n_in,
                              void* d_out, int out_size)
{
    const float* x1i     = (const float*)d_in[0];
    const float* x2i     = (const float*)d_in[1];
    const float* proj_w  = (const float*)d_in[2];
    const float* proj_b  = (const float*)d_in[3];
    const float* mha_in_w  = (const float*)d_in[4];
    const float* mha_in_b  = (const float*)d_in[5];
    const float* mha_out_w = (const float*)d_in[6];
    const float* mha_out_b = (const float*)d_in[7];
    const float* ca_in_w   = (const float*)d_in[8];
    const float* ca_in_b   = (const float*)d_in[9];
    const float* ca_out_w  = (const float*)d_in[10];
    const float* ca_out_b  = (const float*)d_in[11];
    const float* Wbins   = (const float*)d_in[12];
    const float* agg     = (const float*)d_in[13];
    const float* Lmat    = (const float*)d_in[14];
    const float* biasp   = (const float*)d_in[15];
    const float* smooth  = (const float*)d_in[16];

    cudaFuncSetAttribute(gemm_mma<128>, cudaFuncAttributeMaxDynamicSharedMemorySize,
                         SMEM_TOTAL_BYTES(128));
    cudaFuncSetAttribute(gemm_mma<64>,  cudaFuncAttributeMaxDynamicSharedMemorySize,
                         SMEM_TOTAL_BYTES(64));

    Ptrs P;
    cudaGetSymbolAddress((void**)&P.xf, g_xf);
    cudaGetSymbolAddress((void**)&P.att, g_att);   cudaGetSymbolAddress((void**)&P.cmraw, g_cmraw);
    cudaGetSymbolAddress((void**)&P.cm1, g_cm1);   cudaGetSymbolAddress((void**)&P.cs, g_cs);
    cudaGetSymbolAddress((void**)&P.I, g_I);
    cudaGetSymbolAddress((void**)&P.x1ih, g_x1ih); cudaGetSymbolAddress((void**)&P.x1il, g_x1il);
    cudaGetSymbolAddress((void**)&P.x2ih, g_x2ih); cudaGetSymbolAddress((void**)&P.x2il, g_x2il);
    cudaGetSymbolAddress((void**)&P.wph, g_wph);   cudaGetSymbolAddress((void**)&P.wpl, g_wpl);
    cudaGetSymbolAddress((void**)&P.miwh, g_miwh); cudaGetSymbolAddress((void**)&P.miwl, g_miwl);
    cudaGetSymbolAddress((void**)&P.mowh, g_mowh); cudaGetSymbolAddress((void**)&P.mowl, g_mowl);
    cudaGetSymbolAddress((void**)&P.ciwh, g_ciwh); cudaGetSymbolAddress((void**)&P.ciwl, g_ciwl);
    cudaGetSymbolAddress((void**)&P.cowh, g_cowh); cudaGetSymbolAddress((void**)&P.cowl, g_cowl);
    cudaGetSymbolAddress((void**)&P.xh, g_xh);     cudaGetSymbolAddress((void**)&P.xl, g_xl);
    cudaGetSymbolAddress((void**)&P.th, g_th);     cudaGetSymbolAddress((void**)&P.tl, g_tl);
    cudaGetSymbolAddress((void**)&P.qh, g_qh);     cudaGetSymbolAddress((void**)&P.ql, g_ql);
    cudaGetSymbolAddress((void**)&P.kh, g_kh);     cudaGetSymbolAddress((void**)&P.kl, g_kl);
    cudaGetSymbolAddress((void**)&P.vth, g_vth);   cudaGetSymbolAddress((void**)&P.vtl, g_vtl);
    cudaGetSymbolAddress((void**)&P.oh, g_oh);     cudaGetSymbolAddress((void**)&P.ol, g_ol);
    cudaGetSymbolAddress((void**)&P.atth, g_atth); cudaGetSymbolAddress((void**)&P.attl, g_attl);
    cudaGetSymbolAddress((void**)&P.wbth, g_wbth); cudaGetSymbolAddress((void**)&P.wbtl, g_wbtl);
    cudaGetSymbolAddress((void**)&P.hh, g_hh);     cudaGetSymbolAddress((void**)&P.hl, g_hl);

    float* out = (float*)d_out;
    float* pp_out = out + (out_size - Bsz);   // cm first, pp_prob last 8

    const long long MD = (long long)Mrows * Dm;
    const int NXD2 = M2 * Dm;

    // 0. one-time splits
    split_k<<<(Mrows*IDIM/4 + 255)/256, 256>>>(x1i, P.x1ih, P.x1il, Mrows*IDIM/4);
    split_k<<<(Mrows*IDIM/4 + 255)/256, 256>>>(x2i, P.x2ih, P.x2il, Mrows*IDIM/4);
    split_k<<<(Dm*IDIM/4 + 255)/256, 256>>>(proj_w, P.wph, P.wpl, Dm*IDIM/4);
    split_k<<<(3*Dm*Dm/4 + 255)/256, 256>>>(mha_in_w, P.miwh, P.miwl, 3*Dm*Dm/4);
    split_k<<<(Dm*Dm/4 + 255)/256, 256>>>(mha_out_w, P.mowh, P.mowl, Dm*Dm/4);
    split_k<<<(3*Dm*Dm/4 + 255)/256, 256>>>(ca_in_w, P.ciwh, P.ciwl, 3*Dm*Dm/4);
    split_k<<<(Dm*Dm/4 + 255)/256, 256>>>(ca_out_w, P.cowh, P.cowl, Dm*Dm/4);
    {
        dim3 g(HALFc/32, Dm/32, NBINS);
        transpose_split_k<<<g, dim3(32,8)>>>(Wbins, P.wbth, P.wbtl);
    }

    // 1. input projections into combined halves
    gemm(128, P.x1ih, P.x1il, P.wph, P.wpl, P.xf, P.xh, P.xl,
         Mrows, Dm, IDIM, IDIM, IDIM, Dm, 0,0,0,0,0,0, 1,1, proj_b, 1, 1.f, 0, nullptr, 3);
    gemm(128, P.x2ih, P.x2il, P.wph, P.wpl, P.xf + MD, P.xh + MD, P.xl + MD,
         Mrows, Dm, IDIM, IDIM, IDIM, Dm, 0,0,0,0,0,0, 1,1, proj_b, 1, 1.f, 0, nullptr, 3);

    // 2. self-attention (+residual), both sides in one pass
    run_mha(P, P.xh, P.xl, P.xh, P.xl, P.miwh, P.miwl, mha_in_b,
            P.mowh, P.mowl, mha_out_b, P.xf, false);

    // 3. tanh -> planes for cross-attn inputs (combined)
    tanh_split_k<<<(NXD2/4 + 255)/256, 256>>>(P.xf, P.th, P.tl, NXD2/4);

    // 4. cross-attention (+residual), swapped KV
    run_mha(P, P.th, P.tl, P.th, P.tl, P.ciwh, P.ciwl, ca_in_b,
            P.cowh, P.cowl, ca_out_b, P.xf, true);

    // 5. tanh -> planes
    tanh_split_k<<<(NXD2/4 + 255)/256, 256>>>(P.xf, P.th, P.tl, NXD2/4);

    // 6. h = tanh(x @ Wbins) per (side,b,bin)
    gemm(128, P.th, P.tl, P.wbth, P.wbtl, nullptr, P.hh, P.hl,
         Lsz, HALFc, Dm, Dm, Dm, HALFc,
         (long long)Lsz*Dm, 0, 0, (long long)HALFc*Dm,
         (long long)NBINS*Lsz*HALFc, (long long)Lsz*HALFc, 2*Bsz, NBINS,
         nullptr, 0, 1.f, 1, nullptr, 2);

    // 7. cm_raw = h1 h2^T (batch 200)
    {
        const long long hhalf = (long long)Bsz*NBINS*Lsz*HALFc;
        gemm(128, P.hh, P.hl, P.hh + hhalf, P.hl + hhalf, P.cmraw, nullptr, nullptr,
             Lsz, Lsz, HALFc, HALFc, HALFc, Lsz,
             (long long)Lsz*HALFc, 0, (long long)Lsz*HALFc, 0,
             (long long)Lsz*Lsz, 0, Bsz*NBINS, 1,
             nullptr, 0, 1.f, 0, nullptr, 1);
    }

    // 8. bin smoothing -> cm (output) + cm1
    {
        long long tot = (long long)Bsz * Lsz * Lsz;
        smooth_k<<<(unsigned)((tot + 255) / 256), 256>>>(P.cmraw, smooth, agg, out, P.cm1);
    }

    // 9. integral image
    colsum_k<<<(Bsz*Lsz + 255) / 256, 256>>>(P.cm1, P.cs);
    rowsum_k<<<(Bsz*Lsz + 255) / 256, 256>>>(P.cs, P.I);

    // 10. box sums + linear head + sigmoid
    finalize_k<<<Bsz, 128>>>(P.I, Lmat, biasp, pp_out);
}